// round 2
// baseline (speedup 1.0000x reference)
#include <cuda_runtime.h>

// Problem constants
#define BB 4
#define SS 2048
#define DD 1024
#define MM 4096
#define LL 4
#define ROWS (BB*SS)          // 8192
#define NEG_INF __int_as_float(0xff800000)

// Scratch (device globals — no allocation allowed).
// g_big is shared: first used as attention scores [B*S*S] (64 MB),
// then (after scores are consumed) as the FFN mid buffer [ROWS*MM] (128 MB).
__device__ float g_h[ROWS*DD];                    // 32 MB
__device__ float g_q[ROWS*DD];                    // 32 MB
__device__ float g_k[ROWS*DD];                    // 32 MB
__device__ float g_v[ROWS*DD];                    // 32 MB
__device__ float g_big[(long long)ROWS*MM];       // 128 MB (scores alias mid)
__device__ int   g_is32;

// ---------------------------------------------------------------------------
// Detect whether x is int32 or int64. Reading the first 4096 int64 words is
// in-bounds either way (int32 buffer = 32 KB = exactly 4096 int64 words).
// If the buffer is really int32, pairs of tokens form out-of-range int64
// values -> flag set. Deterministic for a fixed input.
__global__ void detect_kernel(const void* __restrict__ x) {
    const long long* p = (const long long*)x;
    int bad = 0;
    for (int i = threadIdx.x; i < 4096; i += 256) {
        long long v = p[i];
        if (v < 0 || v >= 32000) bad = 1;
    }
    bad = __syncthreads_or(bad);
    if (threadIdx.x == 0) g_is32 = bad;
}

// ---------------------------------------------------------------------------
// h[row] = emb[x[row]] + pos_enc[row % S];  one block per row, float4.
__global__ __launch_bounds__(256) void embed_kernel(
    const void* __restrict__ x, const float* __restrict__ emb,
    const float* __restrict__ pos, float* __restrict__ h)
{
    int row = blockIdx.x;
    int s = row & (SS - 1);
    long long tok;
    if (g_is32) tok = ((const int*)x)[row];
    else        tok = ((const long long*)x)[row];
    const float4* e = (const float4*)(emb + tok * (long long)DD);
    const float4* p = (const float4*)(pos + (long long)s * DD);
    float4*       o = (float4*)(h + (long long)row * DD);
    int t = threadIdx.x;                       // D/4 = 256
    float4 a = e[t], b = p[t];
    o[t] = make_float4(a.x + b.x, a.y + b.y, a.z + b.z, a.w + b.w);
}

// ---------------------------------------------------------------------------
// Register-blocked SGEMM: C = A @ B (+bias) with optional epilogues.
// 128x128 block, BK=8, 256 threads, 8x8 per thread.
// EPI: 0 = bias, 1 = bias(+optional null)+relu, 2 = scale + anti-causal mask
// TRANSB: B stored [N,K] row-major (C = A @ B^T)
// All dims here are multiples of 128 (M,N) / 8 (K).
template<int EPI, bool TRANSB>
__global__ __launch_bounds__(256) void sgemm_kernel(
    const float* __restrict__ A, const float* __restrict__ Bm,
    const float* __restrict__ bias, float* __restrict__ C,
    int M, int N, int K,
    long long sA, long long sB, long long sC, float scale)
{
    A  += (long long)blockIdx.z * sA;
    Bm += (long long)blockIdx.z * sB;
    C  += (long long)blockIdx.z * sC;

    const int row0 = blockIdx.y * 128;
    const int col0 = blockIdx.x * 128;
    const int tid  = threadIdx.x;

    __shared__ __align__(16) float As[8][128];
    __shared__ __align__(16) float Bs[8][128];

    float acc[8][8];
    #pragma unroll
    for (int i = 0; i < 8; i++)
        #pragma unroll
        for (int j = 0; j < 8; j++) acc[i][j] = 0.f;

    const int ar = tid >> 1;            // 0..127 (row within tile)
    const int ac = (tid & 1) * 4;       // 0 or 4 (k within tile)
    const int br = tid >> 5;            // 0..7  (k row, NN path)
    const int bc = (tid & 31) * 4;      // 0..124 (col, NN path)
    const int ty = tid >> 4, tx = tid & 15;

    for (int k0 = 0; k0 < K; k0 += 8) {
        float4 a4 = *(const float4*)(A + (long long)(row0 + ar) * K + (k0 + ac));
        As[ac + 0][ar] = a4.x; As[ac + 1][ar] = a4.y;
        As[ac + 2][ar] = a4.z; As[ac + 3][ar] = a4.w;
        if (TRANSB) {
            float4 b4 = *(const float4*)(Bm + (long long)(col0 + ar) * K + (k0 + ac));
            Bs[ac + 0][ar] = b4.x; Bs[ac + 1][ar] = b4.y;
            Bs[ac + 2][ar] = b4.z; Bs[ac + 3][ar] = b4.w;
        } else {
            float4 b4 = *(const float4*)(Bm + (long long)(k0 + br) * N + (col0 + bc));
            *(float4*)&Bs[br][bc] = b4;
        }
        __syncthreads();
        #pragma unroll
        for (int kk = 0; kk < 8; kk++) {
            float av[8], bv[8];
            *(float4*)&av[0] = *(const float4*)&As[kk][ty * 8];
            *(float4*)&av[4] = *(const float4*)&As[kk][ty * 8 + 4];
            *(float4*)&bv[0] = *(const float4*)&Bs[kk][tx * 8];
            *(float4*)&bv[4] = *(const float4*)&Bs[kk][tx * 8 + 4];
            #pragma unroll
            for (int i = 0; i < 8; i++)
                #pragma unroll
                for (int j = 0; j < 8; j++)
                    acc[i][j] = fmaf(av[i], bv[j], acc[i][j]);
        }
        __syncthreads();
    }

    const bool has_bias = (bias != nullptr);
    #pragma unroll
    for (int i = 0; i < 8; i++) {
        int r = row0 + ty * 8 + i;
        #pragma unroll
        for (int j = 0; j < 8; j++) {
            int c = col0 + tx * 8 + j;
            float vv = acc[i][j];
            if (EPI == 2) {
                vv *= scale;
                if (c < r) vv = NEG_INF;   // keep only keys >= query (triu k=0)
            } else {
                if (has_bias) vv += bias[c];
                if (EPI == 1) vv = fmaxf(vv, 0.f);
            }
            C[(long long)r * N + c] = vv;
        }
    }
}

// ---------------------------------------------------------------------------
// Row softmax over length-2048 rows. One block (256 thr) per row.
__global__ __launch_bounds__(256) void softmax_kernel(float* __restrict__ sc)
{
    float* p = sc + (long long)blockIdx.x * SS;
    const int t = threadIdx.x;
    const int lane = t & 31, warp = t >> 5;
    __shared__ float red[8];

    float v[8];
    float m = NEG_INF;
    #pragma unroll
    for (int i = 0; i < 8; i++) { v[i] = p[t + 256 * i]; m = fmaxf(m, v[i]); }
    #pragma unroll
    for (int o = 16; o > 0; o >>= 1) m = fmaxf(m, __shfl_xor_sync(0xffffffffu, m, o));
    if (lane == 0) red[warp] = m;
    __syncthreads();
    float mb = red[0];
    #pragma unroll
    for (int w = 1; w < 8; w++) mb = fmaxf(mb, red[w]);

    float s = 0.f;
    #pragma unroll
    for (int i = 0; i < 8; i++) { v[i] = __expf(v[i] - mb); s += v[i]; }
    #pragma unroll
    for (int o = 16; o > 0; o >>= 1) s += __shfl_xor_sync(0xffffffffu, s, o);
    __syncthreads();                  // guard red reuse
    if (lane == 0) red[warp] = s;
    __syncthreads();
    float sb = 0.f;
    #pragma unroll
    for (int w = 0; w < 8; w++) sb += red[w];

    float inv = 1.f / sb;
    #pragma unroll
    for (int i = 0; i < 8; i++) p[t + 256 * i] = v[i] * inv;
}

// ---------------------------------------------------------------------------
extern "C" void kernel_launch(void* const* d_in, const int* in_sizes, int n_in,
                              void* d_out, int out_size)
{
    const void*  x    = d_in[0];
    const float* emb  = (const float*)d_in[1];
    const float* pos  = (const float*)d_in[2];
    const float* wq   = (const float*)d_in[3];
    const float* bq   = (const float*)d_in[4];
    const float* wk   = (const float*)d_in[5];
    const float* bk   = (const float*)d_in[6];
    const float* wv   = (const float*)d_in[7];
    const float* bv   = (const float*)d_in[8];
    const float* w1s  = (const float*)d_in[9];
    const float* b1s  = (const float*)d_in[10];
    const float* w2s  = (const float*)d_in[11];
    const float* b2s  = (const float*)d_in[12];
    float* out = (float*)d_out;

    void *ph, *pq, *pk, *pv, *pbig;
    cudaGetSymbolAddress(&ph,   g_h);
    cudaGetSymbolAddress(&pq,   g_q);
    cudaGetSymbolAddress(&pk,   g_k);
    cudaGetSymbolAddress(&pv,   g_v);
    cudaGetSymbolAddress(&pbig, g_big);
    float* h   = (float*)ph;
    float* q   = (float*)pq;
    float* k   = (float*)pk;
    float* v   = (float*)pv;
    float* sc  = (float*)pbig;   // scores phase
    float* mid = (float*)pbig;   // FFN phase (scores dead by then)

    detect_kernel<<<1, 256>>>(x);
    embed_kernel<<<ROWS, 256>>>(x, emb, pos, h);

    // QKV projections: [8192,1024] @ [1024,1024] + bias
    sgemm_kernel<0, false><<<dim3(8, 64, 1), 256>>>(h, wq, bq, q, ROWS, DD, DD, 0, 0, 0, 0.f);
    sgemm_kernel<0, false><<<dim3(8, 64, 1), 256>>>(h, wk, bk, k, ROWS, DD, DD, 0, 0, 0, 0.f);
    sgemm_kernel<0, false><<<dim3(8, 64, 1), 256>>>(h, wv, bv, v, ROWS, DD, DD, 0, 0, 0, 0.f);

    // scores = q @ k^T / sqrt(D), anti-causal mask (keep col >= row)
    sgemm_kernel<2, true><<<dim3(16, 16, BB), 256>>>(
        q, k, nullptr, sc, SS, SS, DD,
        (long long)SS * DD, (long long)SS * DD, (long long)SS * SS, 0.03125f);

    softmax_kernel<<<ROWS, 256>>>(sc);

    // h = relu(attn @ v)
    sgemm_kernel<1, false><<<dim3(8, 16, BB), 256>>>(
        sc, v, nullptr, h, SS, DD, SS,
        (long long)SS * SS, (long long)SS * DD, (long long)SS * DD, 0.f);

    // FFN stack
    for (int l = 0; l < LL; l++) {
        sgemm_kernel<1, false><<<dim3(32, 64, 1), 256>>>(
            h, w1s + (long long)l * DD * MM, b1s + (long long)l * MM, mid,
            ROWS, MM, DD, 0, 0, 0, 0.f);
        float* dst = (l == LL - 1) ? out : h;
        sgemm_kernel<1, false><<<dim3(8, 64, 1), 256>>>(
            mid, w2s + (long long)l * MM * DD, b2s + (long long)l * DD, dst,
            ROWS, DD, MM, 0, 0, 0, 0.f);
    }
}

// round 3
// speedup vs baseline: 1.8336x; 1.8336x over previous
#include <cuda_runtime.h>
#include <cuda_bf16.h>
#include <cstdint>

// Problem constants
#define BB 4
#define SS 2048
#define DD 1024
#define MM 4096
#define LL 4
#define ROWS (BB*SS)          // 8192
#define NEG_INF __int_as_float(0xff800000)

// Scratch (device globals — no allocation allowed).
__device__ float g_h[ROWS*DD];                    // 32 MB
__device__ float g_q[ROWS*DD];                    // 32 MB
__device__ float g_k[ROWS*DD];                    // 32 MB
__device__ float g_v[ROWS*DD];                    // 32 MB
__device__ float g_big[(long long)ROWS*MM];       // 128 MB (scores alias FFN mid)
__device__ int   g_is32;

// ---------------------------------------------------------------------------
__global__ void detect_kernel(const void* __restrict__ x) {
    const long long* p = (const long long*)x;
    int bad = 0;
    for (int i = threadIdx.x; i < 4096; i += 256) {
        long long v = p[i];
        if (v < 0 || v >= 32000) bad = 1;
    }
    bad = __syncthreads_or(bad);
    if (threadIdx.x == 0) g_is32 = bad;
}

__global__ __launch_bounds__(256) void embed_kernel(
    const void* __restrict__ x, const float* __restrict__ emb,
    const float* __restrict__ pos, float* __restrict__ h)
{
    int row = blockIdx.x;
    int s = row & (SS - 1);
    long long tok;
    if (g_is32) tok = ((const int*)x)[row];
    else        tok = ((const long long*)x)[row];
    const float4* e = (const float4*)(emb + tok * (long long)DD);
    const float4* p = (const float4*)(pos + (long long)s * DD);
    float4*       o = (float4*)(h + (long long)row * DD);
    int t = threadIdx.x;                       // D/4 = 256
    float4 a = e[t], b = p[t];
    o[t] = make_float4(a.x + b.x, a.y + b.y, a.z + b.z, a.w + b.w);
}

// ---------------------------------------------------------------------------
// Tensor-core GEMM with bf16 hi/lo split (fp32-grade accuracy).
// C = A @ B (+epilogue). 128x128 tile, BK=32, 256 threads (8 warps, 4x2).
// EPI: 0 = bias, 1 = bias+relu, 2 = scale + anti-causal mask (keep col>=row)
// TRANSB: B stored [N,K] row-major (C = A @ B^T); else B is [K,N].
// All dims are multiples of 128 (M,N) / 32 (K).

__device__ __forceinline__ unsigned cvta_s(const void* p) {
    return (unsigned)__cvta_generic_to_shared(p);
}
__device__ __forceinline__ void ldsm4(unsigned addr, unsigned* r) {
    asm volatile("ldmatrix.sync.aligned.m8n8.x4.shared.b16 {%0,%1,%2,%3},[%4];"
                 : "=r"(r[0]), "=r"(r[1]), "=r"(r[2]), "=r"(r[3]) : "r"(addr));
}
__device__ __forceinline__ void ldsm4t(unsigned addr, unsigned* r) {
    asm volatile("ldmatrix.sync.aligned.m8n8.x4.trans.shared.b16 {%0,%1,%2,%3},[%4];"
                 : "=r"(r[0]), "=r"(r[1]), "=r"(r[2]), "=r"(r[3]) : "r"(addr));
}
__device__ __forceinline__ void mma_bf16(float* c, const unsigned* a,
                                         unsigned b0, unsigned b1) {
    asm volatile(
        "mma.sync.aligned.m16n8k16.row.col.f32.bf16.bf16.f32 "
        "{%0,%1,%2,%3},{%4,%5,%6,%7},{%8,%9},{%0,%1,%2,%3};"
        : "+f"(c[0]), "+f"(c[1]), "+f"(c[2]), "+f"(c[3])
        : "r"(a[0]), "r"(a[1]), "r"(a[2]), "r"(a[3]), "r"(b0), "r"(b1));
}
__device__ __forceinline__ void store_hilo(__nv_bfloat16* ph, __nv_bfloat16* pl,
                                           float4 v) {
    float f[4] = {v.x, v.y, v.z, v.w};
    __nv_bfloat16 h[4], l[4];
    #pragma unroll
    for (int i = 0; i < 4; i++) {
        h[i] = __float2bfloat16(f[i]);
        l[i] = __float2bfloat16(f[i] - __bfloat162float(h[i]));
    }
    *(uint2*)ph = *(uint2*)h;
    *(uint2*)pl = *(uint2*)l;
}

#define SA 40            // A/B-TN smem row stride in bf16 (80 B, conflict-free)
#define SBNN 136         // B-NN smem row stride in bf16 (272 B, conflict-free)

template<int EPI, bool TRANSB>
__global__ __launch_bounds__(256) void mma_gemm(
    const float* __restrict__ A, const float* __restrict__ Bm,
    const float* __restrict__ bias, float* __restrict__ C,
    int M, int N, int K,
    long long sA, long long sB, long long sC, float scale)
{
    A  += (long long)blockIdx.z * sA;
    Bm += (long long)blockIdx.z * sB;
    C  += (long long)blockIdx.z * sC;

    const int row0 = blockIdx.y * 128;
    const int col0 = blockIdx.x * 128;
    const int tid  = threadIdx.x;
    const int lane = tid & 31;
    const int wid  = tid >> 5;
    const int m_off = (wid & 3) * 32;   // warp m offset (4 warps along M)
    const int n_off = (wid >> 2) * 64;  // warp n offset (2 warps along N)

    __shared__ __align__(16) __nv_bfloat16 As_hi[128 * SA];
    __shared__ __align__(16) __nv_bfloat16 As_lo[128 * SA];
    __shared__ __align__(16) __nv_bfloat16 Bs_hi[128 * SA];  // sized for max
    __shared__ __align__(16) __nv_bfloat16 Bs_lo[128 * SA];

    float acc[2][8][4];
    #pragma unroll
    for (int mi = 0; mi < 2; mi++)
        #pragma unroll
        for (int ni = 0; ni < 8; ni++)
            #pragma unroll
            for (int j = 0; j < 4; j++) acc[mi][ni][j] = 0.f;

    for (int k0 = 0; k0 < K; k0 += 32) {
        // ---- load A tile: [128 rows][32 k] fp32 -> hi/lo bf16 ----
        #pragma unroll
        for (int i = 0; i < 4; i++) {
            int idx = tid + 256 * i;
            int r = idx >> 3, g = idx & 7;          // r 0..127, k = 4g
            float4 a4 = *(const float4*)(A + (long long)(row0 + r) * K + k0 + 4 * g);
            store_hilo(&As_hi[r * SA + 4 * g], &As_lo[r * SA + 4 * g], a4);
        }
        // ---- load B tile ----
        if (TRANSB) {  // B [N,K]: same pattern as A, n-major rows
            #pragma unroll
            for (int i = 0; i < 4; i++) {
                int idx = tid + 256 * i;
                int r = idx >> 3, g = idx & 7;
                float4 b4 = *(const float4*)(Bm + (long long)(col0 + r) * K + k0 + 4 * g);
                store_hilo(&Bs_hi[r * SA + 4 * g], &Bs_lo[r * SA + 4 * g], b4);
            }
        } else {       // B [K,N]: store k-major rows [32][128], coalesced
            #pragma unroll
            for (int i = 0; i < 4; i++) {
                int idx = tid + 256 * i;
                int kr = idx >> 5, g = idx & 31;    // kr 0..31, n = 4g
                float4 b4 = *(const float4*)(Bm + (long long)(k0 + kr) * N + col0 + 4 * g);
                store_hilo(&Bs_hi[kr * SBNN + 4 * g], &Bs_lo[kr * SBNN + 4 * g], b4);
            }
        }
        __syncthreads();

        // ---- mma over BK=32 (two k16 steps) ----
        #pragma unroll
        for (int ks = 0; ks < 2; ks++) {
            unsigned ah[2][4], al[2][4];
            #pragma unroll
            for (int mi = 0; mi < 2; mi++) {
                int rrow = m_off + mi * 16 + (lane & 15);
                int kel  = ((lane >> 4) << 3) + ks * 16;
                ldsm4(cvta_s(&As_hi[rrow * SA + kel]), ah[mi]);
                ldsm4(cvta_s(&As_lo[rrow * SA + kel]), al[mi]);
            }
            #pragma unroll
            for (int np = 0; np < 4; np++) {   // pairs of n8 tiles
                unsigned bh[4], bl[4];
                if (TRANSB) {
                    int g = lane >> 3;
                    int nrow = n_off + np * 16 + ((g >> 1) << 3) + (lane & 7);
                    int kel  = ks * 16 + ((g & 1) << 3);
                    ldsm4(cvta_s(&Bs_hi[nrow * SA + kel]), bh);
                    ldsm4(cvta_s(&Bs_lo[nrow * SA + kel]), bl);
                } else {
                    int g = lane >> 3;
                    int krow = ks * 16 + ((g & 1) << 3) + (lane & 7);
                    int ncol = n_off + np * 16 + ((g >> 1) << 3);
                    ldsm4t(cvta_s(&Bs_hi[krow * SBNN + ncol]), bh);
                    ldsm4t(cvta_s(&Bs_lo[krow * SBNN + ncol]), bl);
                }
                #pragma unroll
                for (int half = 0; half < 2; half++) {
                    int ni = np * 2 + half;
                    unsigned b0h = bh[half * 2], b1h = bh[half * 2 + 1];
                    unsigned b0l = bl[half * 2], b1l = bl[half * 2 + 1];
                    #pragma unroll
                    for (int mi = 0; mi < 2; mi++) {
                        mma_bf16(acc[mi][ni], ah[mi], b0h, b1h);  // hi*hi
                        mma_bf16(acc[mi][ni], ah[mi], b0l, b1l);  // hi*lo
                        mma_bf16(acc[mi][ni], al[mi], b0h, b1h);  // lo*hi
                    }
                }
            }
        }
        __syncthreads();
    }

    // ---- epilogue ----
    const bool has_bias = (bias != nullptr);
    #pragma unroll
    for (int mi = 0; mi < 2; mi++) {
        #pragma unroll
        for (int ni = 0; ni < 8; ni++) {
            int r_base = row0 + m_off + mi * 16 + (lane >> 2);
            int c      = col0 + n_off + ni * 8 + 2 * (lane & 3);
            #pragma unroll
            for (int h = 0; h < 2; h++) {
                int r = r_base + h * 8;
                float v0 = acc[mi][ni][2 * h];
                float v1 = acc[mi][ni][2 * h + 1];
                if (EPI == 2) {
                    v0 *= scale; v1 *= scale;
                    if (c < r)     v0 = NEG_INF;
                    if (c + 1 < r) v1 = NEG_INF;
                } else {
                    if (has_bias) { v0 += bias[c]; v1 += bias[c + 1]; }
                    if (EPI == 1) { v0 = fmaxf(v0, 0.f); v1 = fmaxf(v1, 0.f); }
                }
                *(float2*)(C + (long long)r * N + c) = make_float2(v0, v1);
            }
        }
    }
}

// ---------------------------------------------------------------------------
// Row softmax over length-2048 rows. One block (256 thr) per row.
__global__ __launch_bounds__(256) void softmax_kernel(float* __restrict__ sc)
{
    float* p = sc + (long long)blockIdx.x * SS;
    const int t = threadIdx.x;
    const int lane = t & 31, warp = t >> 5;
    __shared__ float red[8];

    float v[8];
    float m = NEG_INF;
    #pragma unroll
    for (int i = 0; i < 8; i++) { v[i] = p[t + 256 * i]; m = fmaxf(m, v[i]); }
    #pragma unroll
    for (int o = 16; o > 0; o >>= 1) m = fmaxf(m, __shfl_xor_sync(0xffffffffu, m, o));
    if (lane == 0) red[warp] = m;
    __syncthreads();
    float mb = red[0];
    #pragma unroll
    for (int w = 1; w < 8; w++) mb = fmaxf(mb, red[w]);

    float s = 0.f;
    #pragma unroll
    for (int i = 0; i < 8; i++) { v[i] = __expf(v[i] - mb); s += v[i]; }
    #pragma unroll
    for (int o = 16; o > 0; o >>= 1) s += __shfl_xor_sync(0xffffffffu, s, o);
    __syncthreads();
    if (lane == 0) red[warp] = s;
    __syncthreads();
    float sb = 0.f;
    #pragma unroll
    for (int w = 0; w < 8; w++) sb += red[w];

    float inv = 1.f / sb;
    #pragma unroll
    for (int i = 0; i < 8; i++) p[t + 256 * i] = v[i] * inv;
}

// ---------------------------------------------------------------------------
extern "C" void kernel_launch(void* const* d_in, const int* in_sizes, int n_in,
                              void* d_out, int out_size)
{
    const void*  x    = d_in[0];
    const float* emb  = (const float*)d_in[1];
    const float* pos  = (const float*)d_in[2];
    const float* wq   = (const float*)d_in[3];
    const float* bq   = (const float*)d_in[4];
    const float* wk   = (const float*)d_in[5];
    const float* bk   = (const float*)d_in[6];
    const float* wv   = (const float*)d_in[7];
    const float* bv   = (const float*)d_in[8];
    const float* w1s  = (const float*)d_in[9];
    const float* b1s  = (const float*)d_in[10];
    const float* w2s  = (const float*)d_in[11];
    const float* b2s  = (const float*)d_in[12];
    float* out = (float*)d_out;

    void *ph, *pq, *pk, *pv, *pbig;
    cudaGetSymbolAddress(&ph,   g_h);
    cudaGetSymbolAddress(&pq,   g_q);
    cudaGetSymbolAddress(&pk,   g_k);
    cudaGetSymbolAddress(&pv,   g_v);
    cudaGetSymbolAddress(&pbig, g_big);
    float* h   = (float*)ph;
    float* q   = (float*)pq;
    float* k   = (float*)pk;
    float* v   = (float*)pv;
    float* sc  = (float*)pbig;   // scores phase
    float* mid = (float*)pbig;   // FFN phase (scores dead by then)

    detect_kernel<<<1, 256>>>(x);
    embed_kernel<<<ROWS, 256>>>(x, emb, pos, h);

    // QKV projections: [8192,1024] @ [1024,1024] + bias
    mma_gemm<0, false><<<dim3(8, 64, 1), 256>>>(h, wq, bq, q, ROWS, DD, DD, 0, 0, 0, 0.f);
    mma_gemm<0, false><<<dim3(8, 64, 1), 256>>>(h, wk, bk, k, ROWS, DD, DD, 0, 0, 0, 0.f);
    mma_gemm<0, false><<<dim3(8, 64, 1), 256>>>(h, wv, bv, v, ROWS, DD, DD, 0, 0, 0, 0.f);

    // scores = q @ k^T / sqrt(D), anti-causal mask (keep col >= row)
    mma_gemm<2, true><<<dim3(16, 16, BB), 256>>>(
        q, k, nullptr, sc, SS, SS, DD,
        (long long)SS * DD, (long long)SS * DD, (long long)SS * SS, 0.03125f);

    softmax_kernel<<<ROWS, 256>>>(sc);

    // h = relu(attn @ v)
    mma_gemm<1, false><<<dim3(8, 16, BB), 256>>>(
        sc, v, nullptr, h, SS, DD, SS,
        (long long)SS * SS, (long long)SS * DD, (long long)SS * DD, 0.f);

    // FFN stack
    for (int l = 0; l < LL; l++) {
        mma_gemm<1, false><<<dim3(32, 64, 1), 256>>>(
            h, w1s + (long long)l * DD * MM, b1s + (long long)l * MM, mid,
            ROWS, MM, DD, 0, 0, 0, 0.f);
        float* dst = (l == LL - 1) ? out : h;
        mma_gemm<1, false><<<dim3(8, 64, 1), 256>>>(
            mid, w2s + (long long)l * MM * DD, b2s + (long long)l * DD, dst,
            ROWS, DD, MM, 0, 0, 0, 0.f);
    }
}

// round 5
// speedup vs baseline: 2.7226x; 1.4848x over previous
#include <cuda_runtime.h>
#include <cuda_bf16.h>
#include <cstdint>

// Problem constants
#define BB 4
#define SS 2048
#define DD 1024
#define MM 4096
#define LL 4
#define ROWS (BB*SS)          // 8192
#define NEG_INF __int_as_float(0xff800000)

// GEMM tiling: 128x128 tile, BK=32, 256 threads (8 warps 4x2), 2-stage cp.async
#define SA 40                 // smem row stride (bf16 elems) = 80B, conflict-free
#define TILEB 10240           // 128*SA*2 bytes per tile
#define STAGE (4*TILEB)       // aHi,aLo,bHi,bLo = 40960
#define SMEM_DYN (2*STAGE)    // 81920

// ---------------- scratch (device globals; no allocation allowed) ----------
__device__ __nv_bfloat16 g_hH[ROWS*DD],  g_hL[ROWS*DD];        // 16MB each
__device__ __nv_bfloat16 g_qH[ROWS*DD],  g_qL[ROWS*DD];
__device__ __nv_bfloat16 g_kH[ROWS*DD],  g_kL[ROWS*DD];
__device__ __nv_bfloat16 g_vTH[ROWS*DD], g_vTL[ROWS*DD];
__device__ __nv_bfloat16 g_scH[BB*SS*SS], g_scL[BB*SS*SS];     // 32MB each
__device__ __nv_bfloat16 g_midH[(long long)ROWS*MM], g_midL[(long long)ROWS*MM]; // 64MB each
__device__ __nv_bfloat16 g_wqH[DD*DD], g_wqL[DD*DD];
__device__ __nv_bfloat16 g_wkH[DD*DD], g_wkL[DD*DD];
__device__ __nv_bfloat16 g_wvH[DD*DD], g_wvL[DD*DD];
__device__ __nv_bfloat16 g_w1H[LL*DD*MM], g_w1L[LL*DD*MM];     // 32MB each
__device__ __nv_bfloat16 g_w2H[LL*DD*MM], g_w2L[LL*DD*MM];
__device__ float g_v[ROWS*DD];                                  // 32MB
__device__ float g_sc[BB*SS*SS];                                // 64MB
__device__ int   g_is32;

// ---------------------------------------------------------------------------
__global__ void detect_kernel(const void* __restrict__ x) {
    const long long* p = (const long long*)x;
    int bad = 0;
    for (int i = threadIdx.x; i < 4096; i += 256) {
        long long v = p[i];
        if (v < 0 || v >= 32000) bad = 1;
    }
    bad = __syncthreads_or(bad);
    if (threadIdx.x == 0) g_is32 = bad;
}

__device__ __forceinline__ void split4(const float* f, __nv_bfloat16* h, __nv_bfloat16* l) {
    #pragma unroll
    for (int i = 0; i < 4; i++) {
        h[i] = __float2bfloat16(f[i]);
        l[i] = __float2bfloat16(f[i] - __bfloat162float(h[i]));
    }
}

// h = emb[x] + pos -> bf16 hi/lo
__global__ __launch_bounds__(256) void embed_kernel(
    const void* __restrict__ x, const float* __restrict__ emb,
    const float* __restrict__ pos,
    __nv_bfloat16* __restrict__ hH, __nv_bfloat16* __restrict__ hL)
{
    int row = blockIdx.x;
    int s = row & (SS - 1);
    long long tok;
    if (g_is32) tok = ((const int*)x)[row];
    else        tok = ((const long long*)x)[row];
    int t = threadIdx.x;
    float4 a = ((const float4*)(emb + tok * (long long)DD))[t];
    float4 b = ((const float4*)(pos + (long long)s * DD))[t];
    float f[4] = {a.x + b.x, a.y + b.y, a.z + b.z, a.w + b.w};
    __nv_bfloat16 hh[4], ll[4];
    split4(f, hh, ll);
    *(uint2*)(hH + (long long)row * DD + 4 * t) = *(uint2*)hh;
    *(uint2*)(hL + (long long)row * DD + 4 * t) = *(uint2*)ll;
}

// ---------------------------------------------------------------------------
// Transpose + split: in fp32 [R,C] row-major -> out bf16 hi/lo [C,R].
// blockDim (32,8), grid (C/32, R/32, Z).
__global__ __launch_bounds__(256) void transcvt_kernel(
    const float* __restrict__ in,
    __nv_bfloat16* __restrict__ oH, __nv_bfloat16* __restrict__ oL,
    int R, int C, long long si, long long so)
{
    __shared__ float t[32][33];
    in += (long long)blockIdx.z * si;
    oH += (long long)blockIdx.z * so;
    oL += (long long)blockIdx.z * so;
    int x  = blockIdx.x * 32 + threadIdx.x;
    int y0 = blockIdx.y * 32 + threadIdx.y;
    #pragma unroll
    for (int j = 0; j < 32; j += 8)
        t[threadIdx.y + j][threadIdx.x] = in[(long long)(y0 + j) * C + x];
    __syncthreads();
    int x2 = blockIdx.y * 32 + threadIdx.x;
    int y2 = blockIdx.x * 32 + threadIdx.y;
    #pragma unroll
    for (int j = 0; j < 32; j += 8) {
        float v = t[threadIdx.x][threadIdx.y + j];
        __nv_bfloat16 h = __float2bfloat16(v);
        __nv_bfloat16 l = __float2bfloat16(v - __bfloat162float(h));
        oH[(long long)(y2 + j) * R + x2] = h;
        oL[(long long)(y2 + j) * R + x2] = l;
    }
}

// ---------------------------------------------------------------------------
__device__ __forceinline__ unsigned cvta_s(const void* p) {
    return (unsigned)__cvta_generic_to_shared(p);
}
__device__ __forceinline__ void cpa16(unsigned s, const void* g) {
    asm volatile("cp.async.cg.shared.global [%0], [%1], 16;" :: "r"(s), "l"(g));
}
__device__ __forceinline__ void ldsm4(unsigned addr, unsigned* r) {
    asm volatile("ldmatrix.sync.aligned.m8n8.x4.shared.b16 {%0,%1,%2,%3},[%4];"
                 : "=r"(r[0]), "=r"(r[1]), "=r"(r[2]), "=r"(r[3]) : "r"(addr));
}
__device__ __forceinline__ void mma_bf16(float* c, const unsigned* a,
                                         unsigned b0, unsigned b1) {
    asm volatile(
        "mma.sync.aligned.m16n8k16.row.col.f32.bf16.bf16.f32 "
        "{%0,%1,%2,%3},{%4,%5,%6,%7},{%8,%9},{%0,%1,%2,%3};"
        : "+f"(c[0]), "+f"(c[1]), "+f"(c[2]), "+f"(c[3])
        : "r"(a[0]), "r"(a[1]), "r"(a[2]), "r"(a[3]), "r"(b0), "r"(b1));
}

// ---------------------------------------------------------------------------
// HMMA GEMM, TN: C[M,N] = A[M,K] @ B[N,K]^T, operands pre-split bf16 hi/lo.
// EPI:  0 = +bias, 1 = +bias(+opt null)+relu, 2 = scale + anti-causal mask
// OUTM: 0 = fp32 C, 1 = bf16 hi/lo (Chi/Clo)
template<int EPI, int OUTM>
__global__ __launch_bounds__(256, 2) void hmma_gemm(
    const __nv_bfloat16* __restrict__ Ahi, const __nv_bfloat16* __restrict__ Alo,
    const __nv_bfloat16* __restrict__ Bhi, const __nv_bfloat16* __restrict__ Blo,
    const float* __restrict__ bias, float* __restrict__ C,
    __nv_bfloat16* __restrict__ Chi, __nv_bfloat16* __restrict__ Clo,
    int M, int N, int K,
    long long sA, long long sB, long long sC, float scale)
{
    extern __shared__ __align__(128) char smem[];

    const long long zA = (long long)blockIdx.z * sA;
    const long long zB = (long long)blockIdx.z * sB;
    const long long zC = (long long)blockIdx.z * sC;

    const int tid  = threadIdx.x;
    const int lane = tid & 31;
    const int wid  = tid >> 5;
    const int row0 = blockIdx.y * 128;
    const int col0 = blockIdx.x * 128;
    const int m_off = (wid & 3) * 32;
    const int n_off = (wid >> 2) * 64;

    const __nv_bfloat16* AtH = Ahi + zA + (long long)row0 * K;
    const __nv_bfloat16* AtL = Alo + zA + (long long)row0 * K;
    const __nv_bfloat16* BtH = Bhi + zB + (long long)col0 * K;
    const __nv_bfloat16* BtL = Blo + zB + (long long)col0 * K;

    const int r_ld = tid >> 2;          // 0..63? no: tid>>2 = 0..63 for 256? 256>>2=64 rows/pass
    const int c_ld = tid & 3;

    float acc[2][8][4];
    #pragma unroll
    for (int mi = 0; mi < 2; mi++)
        #pragma unroll
        for (int ni = 0; ni < 8; ni++)
            #pragma unroll
            for (int j = 0; j < 4; j++) acc[mi][ni][j] = 0.f;

    const int NC = K / 32;

    // stage loader: 128 rows x 4 chunks per tile; 256 thr -> 2 passes/tile
    auto load_stage = [&](int s, int k0) {
        unsigned sb = cvta_s(smem + s * STAGE);
        #pragma unroll
        for (int i = 0; i < 2; i++) {
            int r = r_ld + 64 * i;
            long long go = (long long)r * K + k0 + 8 * c_ld;
            unsigned so = (unsigned)(r * (SA * 2) + c_ld * 16);
            cpa16(sb + so,             AtH + go);
            cpa16(sb + TILEB + so,     AtL + go);
            cpa16(sb + 2 * TILEB + so, BtH + go);
            cpa16(sb + 3 * TILEB + so, BtL + go);
        }
        asm volatile("cp.async.commit_group;");
    };

    load_stage(0, 0);

    for (int ch = 0; ch < NC; ch++) {
        const int s = ch & 1;
        if (ch + 1 < NC) {
            load_stage(s ^ 1, (ch + 1) * 32);
            asm volatile("cp.async.wait_group 1;");
        } else {
            asm volatile("cp.async.wait_group 0;");
        }
        __syncthreads();

        const __nv_bfloat16* As_hi = (const __nv_bfloat16*)(smem + s * STAGE);
        const __nv_bfloat16* As_lo = (const __nv_bfloat16*)(smem + s * STAGE + TILEB);
        const __nv_bfloat16* Bs_hi = (const __nv_bfloat16*)(smem + s * STAGE + 2 * TILEB);
        const __nv_bfloat16* Bs_lo = (const __nv_bfloat16*)(smem + s * STAGE + 3 * TILEB);

        #pragma unroll
        for (int ks = 0; ks < 2; ks++) {
            unsigned ah[2][4], al[2][4];
            #pragma unroll
            for (int mi = 0; mi < 2; mi++) {
                int rrow = m_off + mi * 16 + (lane & 15);
                int kel  = ((lane >> 4) << 3) + ks * 16;
                ldsm4(cvta_s(As_hi + rrow * SA + kel), ah[mi]);
                ldsm4(cvta_s(As_lo + rrow * SA + kel), al[mi]);
            }
            #pragma unroll
            for (int np = 0; np < 4; np++) {
                unsigned bh[4], bl[4];
                int g = lane >> 3;
                int nrow = n_off + np * 16 + ((g >> 1) << 3) + (lane & 7);
                int kel  = ks * 16 + ((g & 1) << 3);
                ldsm4(cvta_s(Bs_hi + nrow * SA + kel), bh);
                ldsm4(cvta_s(Bs_lo + nrow * SA + kel), bl);
                #pragma unroll
                for (int half = 0; half < 2; half++) {
                    int ni = np * 2 + half;
                    #pragma unroll
                    for (int mi = 0; mi < 2; mi++) {
                        mma_bf16(acc[mi][ni], ah[mi], bh[half*2], bh[half*2+1]);
                        mma_bf16(acc[mi][ni], ah[mi], bl[half*2], bl[half*2+1]);
                        mma_bf16(acc[mi][ni], al[mi], bh[half*2], bh[half*2+1]);
                    }
                }
            }
        }
        __syncthreads();
    }

    // epilogue
    const bool has_bias = (bias != nullptr);
    #pragma unroll
    for (int mi = 0; mi < 2; mi++) {
        #pragma unroll
        for (int ni = 0; ni < 8; ni++) {
            int r_base = row0 + m_off + mi * 16 + (lane >> 2);
            int c      = col0 + n_off + ni * 8 + 2 * (lane & 3);
            #pragma unroll
            for (int hh = 0; hh < 2; hh++) {
                int r = r_base + hh * 8;
                float v0 = acc[mi][ni][2 * hh];
                float v1 = acc[mi][ni][2 * hh + 1];
                if (EPI == 2) {
                    v0 *= scale; v1 *= scale;
                    if (c < r)     v0 = NEG_INF;
                    if (c + 1 < r) v1 = NEG_INF;
                } else {
                    if (has_bias) { v0 += bias[c]; v1 += bias[c + 1]; }
                    if (EPI == 1) { v0 = fmaxf(v0, 0.f); v1 = fmaxf(v1, 0.f); }
                }
                long long off = zC + (long long)r * N + c;
                if (OUTM == 0) {
                    *(float2*)(C + off) = make_float2(v0, v1);
                } else {
                    __nv_bfloat16 h2[2], l2[2];
                    h2[0] = __float2bfloat16(v0);
                    h2[1] = __float2bfloat16(v1);
                    l2[0] = __float2bfloat16(v0 - __bfloat162float(h2[0]));
                    l2[1] = __float2bfloat16(v1 - __bfloat162float(h2[1]));
                    *(unsigned*)(Chi + off) = *(unsigned*)h2;
                    *(unsigned*)(Clo + off) = *(unsigned*)l2;
                }
            }
        }
    }
}

// ---------------------------------------------------------------------------
// Row softmax over length-2048 rows; reads fp32, writes bf16 hi/lo.
__global__ __launch_bounds__(256) void softmax_kernel(
    const float* __restrict__ sc,
    __nv_bfloat16* __restrict__ oH, __nv_bfloat16* __restrict__ oL)
{
    const float* p = sc + (long long)blockIdx.x * SS;
    __nv_bfloat16* pH = oH + (long long)blockIdx.x * SS;
    __nv_bfloat16* pL = oL + (long long)blockIdx.x * SS;
    const int t = threadIdx.x;
    const int lane = t & 31, warp = t >> 5;
    __shared__ float red[8];

    float v[8];
    float m = NEG_INF;
    #pragma unroll
    for (int i = 0; i < 8; i++) { v[i] = p[t + 256 * i]; m = fmaxf(m, v[i]); }
    #pragma unroll
    for (int o = 16; o > 0; o >>= 1) m = fmaxf(m, __shfl_xor_sync(0xffffffffu, m, o));
    if (lane == 0) red[warp] = m;
    __syncthreads();
    float mb = red[0];
    #pragma unroll
    for (int w = 1; w < 8; w++) mb = fmaxf(mb, red[w]);

    float s = 0.f;
    #pragma unroll
    for (int i = 0; i < 8; i++) { v[i] = __expf(v[i] - mb); s += v[i]; }
    #pragma unroll
    for (int o = 16; o > 0; o >>= 1) s += __shfl_xor_sync(0xffffffffu, s, o);
    __syncthreads();
    if (lane == 0) red[warp] = s;
    __syncthreads();
    float sb = 0.f;
    #pragma unroll
    for (int w = 0; w < 8; w++) sb += red[w];

    float inv = 1.f / sb;
    #pragma unroll
    for (int i = 0; i < 8; i++) {
        float x = v[i] * inv;
        __nv_bfloat16 h = __float2bfloat16(x);
        __nv_bfloat16 l = __float2bfloat16(x - __bfloat162float(h));
        pH[t + 256 * i] = h;
        pL[t + 256 * i] = l;
    }
}

// ---------------------------------------------------------------------------
extern "C" void kernel_launch(void* const* d_in, const int* in_sizes, int n_in,
                              void* d_out, int out_size)
{
    const void*  x    = d_in[0];
    const float* emb  = (const float*)d_in[1];
    const float* pos  = (const float*)d_in[2];
    const float* wq   = (const float*)d_in[3];
    const float* bq   = (const float*)d_in[4];
    const float* wk   = (const float*)d_in[5];
    const float* bk   = (const float*)d_in[6];
    const float* wv   = (const float*)d_in[7];
    const float* bv   = (const float*)d_in[8];
    const float* w1s  = (const float*)d_in[9];
    const float* b1s  = (const float*)d_in[10];
    const float* w2s  = (const float*)d_in[11];
    const float* b2s  = (const float*)d_in[12];
    float* out = (float*)d_out;

    cudaFuncSetAttribute(hmma_gemm<0,1>, cudaFuncAttributeMaxDynamicSharedMemorySize, SMEM_DYN);
    cudaFuncSetAttribute(hmma_gemm<0,0>, cudaFuncAttributeMaxDynamicSharedMemorySize, SMEM_DYN);
    cudaFuncSetAttribute(hmma_gemm<2,0>, cudaFuncAttributeMaxDynamicSharedMemorySize, SMEM_DYN);
    cudaFuncSetAttribute(hmma_gemm<1,1>, cudaFuncAttributeMaxDynamicSharedMemorySize, SMEM_DYN);
    cudaFuncSetAttribute(hmma_gemm<1,0>, cudaFuncAttributeMaxDynamicSharedMemorySize, SMEM_DYN);

    #define SYM(T, n) T* n; { void* p_; cudaGetSymbolAddress(&p_, g_##n); n = (T*)p_; }
    SYM(__nv_bfloat16, hH)  SYM(__nv_bfloat16, hL)
    SYM(__nv_bfloat16, qH)  SYM(__nv_bfloat16, qL)
    SYM(__nv_bfloat16, kH)  SYM(__nv_bfloat16, kL)
    SYM(__nv_bfloat16, vTH) SYM(__nv_bfloat16, vTL)
    SYM(__nv_bfloat16, scH) SYM(__nv_bfloat16, scL)
    SYM(__nv_bfloat16, midH) SYM(__nv_bfloat16, midL)
    SYM(__nv_bfloat16, wqH) SYM(__nv_bfloat16, wqL)
    SYM(__nv_bfloat16, wkH) SYM(__nv_bfloat16, wkL)
    SYM(__nv_bfloat16, wvH) SYM(__nv_bfloat16, wvL)
    SYM(__nv_bfloat16, w1H) SYM(__nv_bfloat16, w1L)
    SYM(__nv_bfloat16, w2H) SYM(__nv_bfloat16, w2L)
    SYM(float, v)  SYM(float, sc)
    #undef SYM

    detect_kernel<<<1, 256>>>(x);
    embed_kernel<<<ROWS, 256>>>(x, emb, pos, hH, hL);

    // weight transpose+split to [N][K] bf16 hi/lo
    dim3 tb(32, 8);
    transcvt_kernel<<<dim3(32, 32, 1),  tb>>>(wq, wqH, wqL, DD, DD, 0, 0);
    transcvt_kernel<<<dim3(32, 32, 1),  tb>>>(wk, wkH, wkL, DD, DD, 0, 0);
    transcvt_kernel<<<dim3(32, 32, 1),  tb>>>(wv, wvH, wvL, DD, DD, 0, 0);
    transcvt_kernel<<<dim3(128, 32, LL), tb>>>(w1s, w1H, w1L, DD, MM,
        (long long)DD * MM, (long long)DD * MM);
    transcvt_kernel<<<dim3(32, 128, LL), tb>>>(w2s, w2H, w2L, MM, DD,
        (long long)MM * DD, (long long)MM * DD);

    // QKV projections (TN)
    hmma_gemm<0,1><<<dim3(8, 64, 1), 256, SMEM_DYN>>>(hH, hL, wqH, wqL, bq,
        nullptr, qH, qL, ROWS, DD, DD, 0, 0, 0, 0.f);
    hmma_gemm<0,1><<<dim3(8, 64, 1), 256, SMEM_DYN>>>(hH, hL, wkH, wkL, bk,
        nullptr, kH, kL, ROWS, DD, DD, 0, 0, 0, 0.f);
    hmma_gemm<0,0><<<dim3(8, 64, 1), 256, SMEM_DYN>>>(hH, hL, wvH, wvL, bv,
        v, nullptr, nullptr, ROWS, DD, DD, 0, 0, 0, 0.f);

    // scores = q @ k^T / 32, anti-causal mask (keep col >= row) -> fp32
    hmma_gemm<2,0><<<dim3(16, 16, BB), 256, SMEM_DYN>>>(qH, qL, kH, kL, nullptr,
        sc, nullptr, nullptr, SS, SS, DD,
        (long long)SS * DD, (long long)SS * DD, (long long)SS * SS, 0.03125f);

    // vT hi/lo: per-batch transpose of v [S,D] -> [D,S]
    transcvt_kernel<<<dim3(32, 64, BB), tb>>>(v, vTH, vTL, SS, DD,
        (long long)SS * DD, (long long)DD * SS);

    softmax_kernel<<<ROWS, 256>>>(sc, scH, scL);

    // h = relu(attn @ v): A=sc hi/lo, B=vT hi/lo -> h hi/lo
    hmma_gemm<1,1><<<dim3(8, 16, BB), 256, SMEM_DYN>>>(scH, scL, vTH, vTL, nullptr,
        nullptr, hH, hL, SS, DD, SS,
        (long long)SS * SS, (long long)DD * SS, (long long)SS * DD, 0.f);

    // FFN stack
    for (int l = 0; l < LL; l++) {
        hmma_gemm<1,1><<<dim3(32, 64, 1), 256, SMEM_DYN>>>(
            hH, hL, w1H + (long long)l * DD * MM, w1L + (long long)l * DD * MM,
            b1s + (long long)l * MM, nullptr, midH, midL,
            ROWS, MM, DD, 0, 0, 0, 0.f);
        if (l == LL - 1) {
            hmma_gemm<1,0><<<dim3(8, 64, 1), 256, SMEM_DYN>>>(
                midH, midL, w2H + (long long)l * MM * DD, w2L + (long long)l * MM * DD,
                b2s + (long long)l * DD, out, nullptr, nullptr,
                ROWS, DD, MM, 0, 0, 0, 0.f);
        } else {
            hmma_gemm<1,1><<<dim3(8, 64, 1), 256, SMEM_DYN>>>(
                midH, midL, w2H + (long long)l * MM * DD, w2L + (long long)l * MM * DD,
                b2s + (long long)l * DD, nullptr, hH, hL,
                ROWS, DD, MM, 0, 0, 0, 0.f);
        }
    }
}

// round 6
// speedup vs baseline: 2.7616x; 1.0143x over previous
#include <cuda_runtime.h>
#include <cuda_bf16.h>
#include <cstdint>

// Problem constants
#define BB 4
#define SS 2048
#define DD 1024
#define MM 4096
#define LL 4
#define ROWS (BB*SS)          // 8192
#define NEG_INF __int_as_float(0xff800000)

// GEMM tiling: 128x128 tile, BK=32, 256 threads (8 warps 4x2), 2-stage cp.async
#define SA 40                 // smem row stride (bf16 elems) = 80B, conflict-free
#define TILEB 10240           // 128*SA*2 bytes per tile
#define STAGE (4*TILEB)       // aHi,aLo,bHi,bLo = 40960
#define SMEM_DYN (2*STAGE)    // 81920

// ---------------- scratch (device globals; no allocation allowed) ----------
__device__ __nv_bfloat16 g_hH[ROWS*DD],  g_hL[ROWS*DD];
__device__ __nv_bfloat16 g_qH[ROWS*DD],  g_qL[ROWS*DD];
__device__ __nv_bfloat16 g_kH[ROWS*DD],  g_kL[ROWS*DD];
__device__ __nv_bfloat16 g_vTH[ROWS*DD], g_vTL[ROWS*DD];
__device__ __nv_bfloat16 g_scH[BB*SS*SS], g_scL[BB*SS*SS];
__device__ __nv_bfloat16 g_midH[(long long)ROWS*MM], g_midL[(long long)ROWS*MM];
__device__ __nv_bfloat16 g_wqH[DD*DD], g_wqL[DD*DD];
__device__ __nv_bfloat16 g_wkH[DD*DD], g_wkL[DD*DD];
__device__ __nv_bfloat16 g_wvH[DD*DD], g_wvL[DD*DD];
__device__ __nv_bfloat16 g_w1H[LL*DD*MM], g_w1L[LL*DD*MM];
__device__ __nv_bfloat16 g_w2H[LL*DD*MM], g_w2L[LL*DD*MM];
__device__ float g_v[ROWS*DD];
__device__ float g_sc[BB*SS*SS];
__device__ int   g_is32;

// ---------------------------------------------------------------------------
__global__ void detect_kernel(const void* __restrict__ x) {
    const long long* p = (const long long*)x;
    int bad = 0;
    for (int i = threadIdx.x; i < 4096; i += 256) {
        long long v = p[i];
        if (v < 0 || v >= 32000) bad = 1;
    }
    bad = __syncthreads_or(bad);
    if (threadIdx.x == 0) g_is32 = bad;
}

__device__ __forceinline__ void split4(const float* f, __nv_bfloat16* h, __nv_bfloat16* l) {
    #pragma unroll
    for (int i = 0; i < 4; i++) {
        h[i] = __float2bfloat16(f[i]);
        l[i] = __float2bfloat16(f[i] - __bfloat162float(h[i]));
    }
}

__global__ __launch_bounds__(256) void embed_kernel(
    const void* __restrict__ x, const float* __restrict__ emb,
    const float* __restrict__ pos,
    __nv_bfloat16* __restrict__ hH, __nv_bfloat16* __restrict__ hL)
{
    int row = blockIdx.x;
    int s = row & (SS - 1);
    long long tok;
    if (g_is32) tok = ((const int*)x)[row];
    else        tok = ((const long long*)x)[row];
    int t = threadIdx.x;
    float4 a = ((const float4*)(emb + tok * (long long)DD))[t];
    float4 b = ((const float4*)(pos + (long long)s * DD))[t];
    float f[4] = {a.x + b.x, a.y + b.y, a.z + b.z, a.w + b.w};
    __nv_bfloat16 hh[4], ll[4];
    split4(f, hh, ll);
    *(uint2*)(hH + (long long)row * DD + 4 * t) = *(uint2*)hh;
    *(uint2*)(hL + (long long)row * DD + 4 * t) = *(uint2*)ll;
}

// ---------------------------------------------------------------------------
// Transpose + split: in fp32 [R,C] row-major -> out bf16 hi/lo [C,R].
__global__ __launch_bounds__(256) void transcvt_kernel(
    const float* __restrict__ in,
    __nv_bfloat16* __restrict__ oH, __nv_bfloat16* __restrict__ oL,
    int R, int C, long long si, long long so)
{
    __shared__ float t[32][33];
    in += (long long)blockIdx.z * si;
    oH += (long long)blockIdx.z * so;
    oL += (long long)blockIdx.z * so;
    int x  = blockIdx.x * 32 + threadIdx.x;
    int y0 = blockIdx.y * 32 + threadIdx.y;
    #pragma unroll
    for (int j = 0; j < 32; j += 8)
        t[threadIdx.y + j][threadIdx.x] = in[(long long)(y0 + j) * C + x];
    __syncthreads();
    int x2 = blockIdx.y * 32 + threadIdx.x;
    int y2 = blockIdx.x * 32 + threadIdx.y;
    #pragma unroll
    for (int j = 0; j < 32; j += 8) {
        float v = t[threadIdx.x][threadIdx.y + j];
        __nv_bfloat16 h = __float2bfloat16(v);
        __nv_bfloat16 l = __float2bfloat16(v - __bfloat162float(h));
        oH[(long long)(y2 + j) * R + x2] = h;
        oL[(long long)(y2 + j) * R + x2] = l;
    }
}

// ---------------------------------------------------------------------------
__device__ __forceinline__ unsigned cvta_s(const void* p) {
    return (unsigned)__cvta_generic_to_shared(p);
}
__device__ __forceinline__ void cpa16(unsigned s, const void* g) {
    asm volatile("cp.async.cg.shared.global [%0], [%1], 16;" :: "r"(s), "l"(g));
}
__device__ __forceinline__ void ldsm4(unsigned addr, unsigned* r) {
    asm volatile("ldmatrix.sync.aligned.m8n8.x4.shared.b16 {%0,%1,%2,%3},[%4];"
                 : "=r"(r[0]), "=r"(r[1]), "=r"(r[2]), "=r"(r[3]) : "r"(addr));
}
__device__ __forceinline__ void mma_bf16(float* c, const unsigned* a,
                                         unsigned b0, unsigned b1) {
    asm volatile(
        "mma.sync.aligned.m16n8k16.row.col.f32.bf16.bf16.f32 "
        "{%0,%1,%2,%3},{%4,%5,%6,%7},{%8,%9},{%0,%1,%2,%3};"
        : "+f"(c[0]), "+f"(c[1]), "+f"(c[2]), "+f"(c[3])
        : "r"(a[0]), "r"(a[1]), "r"(a[2]), "r"(a[3]), "r"(b0), "r"(b1));
}

// ---------------------------------------------------------------------------
// HMMA GEMM, TN: C[M,N] = A[M,K] @ B[N,K]^T, operands pre-split bf16 hi/lo.
// EPI:  0 = +bias, 1 = +bias(+opt null)+relu, 2 = scale + anti-causal mask
// OUTM: 0 = fp32 C, 1 = bf16 hi/lo (Chi/Clo)
// TRIM: 1 = start K loop at row0 (A rows are exactly zero for k < row0)
template<int EPI, int OUTM, int TRIM>
__global__ __launch_bounds__(256, 2) void hmma_gemm(
    const __nv_bfloat16* __restrict__ Ahi, const __nv_bfloat16* __restrict__ Alo,
    const __nv_bfloat16* __restrict__ Bhi, const __nv_bfloat16* __restrict__ Blo,
    const float* __restrict__ bias, float* __restrict__ C,
    __nv_bfloat16* __restrict__ Chi, __nv_bfloat16* __restrict__ Clo,
    int M, int N, int K,
    long long sA, long long sB, long long sC, float scale)
{
    extern __shared__ __align__(128) char smem[];

    const long long zC = (long long)blockIdx.z * sC;

    const int tid  = threadIdx.x;
    const int lane = tid & 31;
    const int wid  = tid >> 5;
    const int row0 = blockIdx.y * 128;
    const int col0 = blockIdx.x * 128;
    const int m_off = (wid & 3) * 32;
    const int n_off = (wid >> 2) * 64;

    // Fully-masked scores tile: every output col < row -> all NEG_INF. Exact.
    if (EPI == 2 && col0 + 128 <= row0) {
        #pragma unroll
        for (int mi = 0; mi < 2; mi++) {
            #pragma unroll
            for (int ni = 0; ni < 8; ni++) {
                int r_base = row0 + m_off + mi * 16 + (lane >> 2);
                int c      = col0 + n_off + ni * 8 + 2 * (lane & 3);
                #pragma unroll
                for (int hh = 0; hh < 2; hh++) {
                    long long off = zC + (long long)(r_base + hh * 8) * N + c;
                    *(float2*)(C + off) = make_float2(NEG_INF, NEG_INF);
                }
            }
        }
        return;
    }

    const long long zA = (long long)blockIdx.z * sA;
    const long long zB = (long long)blockIdx.z * sB;
    const __nv_bfloat16* AtH = Ahi + zA + (long long)row0 * K;
    const __nv_bfloat16* AtL = Alo + zA + (long long)row0 * K;
    const __nv_bfloat16* BtH = Bhi + zB + (long long)col0 * K;
    const __nv_bfloat16* BtL = Blo + zB + (long long)col0 * K;

    const int r_ld = tid >> 2;
    const int c_ld = tid & 3;

    float acc[2][8][4];
    #pragma unroll
    for (int mi = 0; mi < 2; mi++)
        #pragma unroll
        for (int ni = 0; ni < 8; ni++)
            #pragma unroll
            for (int j = 0; j < 4; j++) acc[mi][ni][j] = 0.f;

    const int NC  = K / 32;
    const int ch0 = TRIM ? (row0 >> 5) : 0;   // skip exact-zero K prefix

    auto load_stage = [&](int s, int k0) {
        unsigned sb = cvta_s(smem + s * STAGE);
        #pragma unroll
        for (int i = 0; i < 2; i++) {
            int r = r_ld + 64 * i;
            long long go = (long long)r * K + k0 + 8 * c_ld;
            unsigned so = (unsigned)(r * (SA * 2) + c_ld * 16);
            cpa16(sb + so,             AtH + go);
            cpa16(sb + TILEB + so,     AtL + go);
            cpa16(sb + 2 * TILEB + so, BtH + go);
            cpa16(sb + 3 * TILEB + so, BtL + go);
        }
        asm volatile("cp.async.commit_group;");
    };

    load_stage(0, ch0 * 32);

    for (int ch = ch0; ch < NC; ch++) {
        const int s = (ch - ch0) & 1;
        if (ch + 1 < NC) {
            load_stage(s ^ 1, (ch + 1) * 32);
            asm volatile("cp.async.wait_group 1;");
        } else {
            asm volatile("cp.async.wait_group 0;");
        }
        __syncthreads();

        const __nv_bfloat16* As_hi = (const __nv_bfloat16*)(smem + s * STAGE);
        const __nv_bfloat16* As_lo = (const __nv_bfloat16*)(smem + s * STAGE + TILEB);
        const __nv_bfloat16* Bs_hi = (const __nv_bfloat16*)(smem + s * STAGE + 2 * TILEB);
        const __nv_bfloat16* Bs_lo = (const __nv_bfloat16*)(smem + s * STAGE + 3 * TILEB);

        const int g = lane >> 3;
        const int brow_base = n_off + ((g >> 1) << 3) + (lane & 7);

        #pragma unroll
        for (int ks = 0; ks < 2; ks++) {
            const int kel_b = ks * 16 + ((g & 1) << 3);
            unsigned ah[2][4], al[2][4];
            #pragma unroll
            for (int mi = 0; mi < 2; mi++) {
                int rrow = m_off + mi * 16 + (lane & 15);
                int kel  = ((lane >> 4) << 3) + ks * 16;
                ldsm4(cvta_s(As_hi + rrow * SA + kel), ah[mi]);
                ldsm4(cvta_s(As_lo + rrow * SA + kel), al[mi]);
            }
            unsigned bh[2][4], bl[4];
            ldsm4(cvta_s(Bs_hi + brow_base * SA + kel_b), bh[0]);   // np=0 hi
            #pragma unroll
            for (int np = 0; np < 4; np++) {
                const int cur = np & 1, nxt = cur ^ 1;
                ldsm4(cvta_s(Bs_lo + (brow_base + np * 16) * SA + kel_b), bl);
                if (np < 3)
                    ldsm4(cvta_s(Bs_hi + (brow_base + (np + 1) * 16) * SA + kel_b), bh[nxt]);
                #pragma unroll
                for (int half = 0; half < 2; half++) {
                    int ni = np * 2 + half;
                    // hi*hi and lo*hi first (bh[cur] ready); bl consumed last
                    #pragma unroll
                    for (int mi = 0; mi < 2; mi++)
                        mma_bf16(acc[mi][ni], ah[mi], bh[cur][half*2], bh[cur][half*2+1]);
                    #pragma unroll
                    for (int mi = 0; mi < 2; mi++)
                        mma_bf16(acc[mi][ni], al[mi], bh[cur][half*2], bh[cur][half*2+1]);
                    #pragma unroll
                    for (int mi = 0; mi < 2; mi++)
                        mma_bf16(acc[mi][ni], ah[mi], bl[half*2], bl[half*2+1]);
                }
            }
        }
        __syncthreads();
    }

    // epilogue
    const bool has_bias = (bias != nullptr);
    #pragma unroll
    for (int mi = 0; mi < 2; mi++) {
        #pragma unroll
        for (int ni = 0; ni < 8; ni++) {
            int r_base = row0 + m_off + mi * 16 + (lane >> 2);
            int c      = col0 + n_off + ni * 8 + 2 * (lane & 3);
            #pragma unroll
            for (int hh = 0; hh < 2; hh++) {
                int r = r_base + hh * 8;
                float v0 = acc[mi][ni][2 * hh];
                float v1 = acc[mi][ni][2 * hh + 1];
                if (EPI == 2) {
                    v0 *= scale; v1 *= scale;
                    if (c < r)     v0 = NEG_INF;
                    if (c + 1 < r) v1 = NEG_INF;
                } else {
                    if (has_bias) { v0 += bias[c]; v1 += bias[c + 1]; }
                    if (EPI == 1) { v0 = fmaxf(v0, 0.f); v1 = fmaxf(v1, 0.f); }
                }
                long long off = zC + (long long)r * N + c;
                if (OUTM == 0) {
                    *(float2*)(C + off) = make_float2(v0, v1);
                } else {
                    __nv_bfloat16 h2[2], l2[2];
                    h2[0] = __float2bfloat16(v0);
                    h2[1] = __float2bfloat16(v1);
                    l2[0] = __float2bfloat16(v0 - __bfloat162float(h2[0]));
                    l2[1] = __float2bfloat16(v1 - __bfloat162float(h2[1]));
                    *(unsigned*)(Chi + off) = *(unsigned*)h2;
                    *(unsigned*)(Clo + off) = *(unsigned*)l2;
                }
            }
        }
    }
}

// ---------------------------------------------------------------------------
__global__ __launch_bounds__(256) void softmax_kernel(
    const float* __restrict__ sc,
    __nv_bfloat16* __restrict__ oH, __nv_bfloat16* __restrict__ oL)
{
    const float* p = sc + (long long)blockIdx.x * SS;
    __nv_bfloat16* pH = oH + (long long)blockIdx.x * SS;
    __nv_bfloat16* pL = oL + (long long)blockIdx.x * SS;
    const int t = threadIdx.x;
    const int lane = t & 31, warp = t >> 5;
    __shared__ float red[8];

    float v[8];
    float m = NEG_INF;
    #pragma unroll
    for (int i = 0; i < 8; i++) { v[i] = p[t + 256 * i]; m = fmaxf(m, v[i]); }
    #pragma unroll
    for (int o = 16; o > 0; o >>= 1) m = fmaxf(m, __shfl_xor_sync(0xffffffffu, m, o));
    if (lane == 0) red[warp] = m;
    __syncthreads();
    float mb = red[0];
    #pragma unroll
    for (int w = 1; w < 8; w++) mb = fmaxf(mb, red[w]);

    float s = 0.f;
    #pragma unroll
    for (int i = 0; i < 8; i++) { v[i] = __expf(v[i] - mb); s += v[i]; }
    #pragma unroll
    for (int o = 16; o > 0; o >>= 1) s += __shfl_xor_sync(0xffffffffu, s, o);
    __syncthreads();
    if (lane == 0) red[warp] = s;
    __syncthreads();
    float sb = 0.f;
    #pragma unroll
    for (int w = 0; w < 8; w++) sb += red[w];

    float inv = 1.f / sb;
    #pragma unroll
    for (int i = 0; i < 8; i++) {
        float x = v[i] * inv;
        __nv_bfloat16 h = __float2bfloat16(x);
        __nv_bfloat16 l = __float2bfloat16(x - __bfloat162float(h));
        pH[t + 256 * i] = h;
        pL[t + 256 * i] = l;
    }
}

// ---------------------------------------------------------------------------
extern "C" void kernel_launch(void* const* d_in, const int* in_sizes, int n_in,
                              void* d_out, int out_size)
{
    const void*  x    = d_in[0];
    const float* emb  = (const float*)d_in[1];
    const float* pos  = (const float*)d_in[2];
    const float* wq   = (const float*)d_in[3];
    const float* bq   = (const float*)d_in[4];
    const float* wk   = (const float*)d_in[5];
    const float* bk   = (const float*)d_in[6];
    const float* wv   = (const float*)d_in[7];
    const float* bv   = (const float*)d_in[8];
    const float* w1s  = (const float*)d_in[9];
    const float* b1s  = (const float*)d_in[10];
    const float* w2s  = (const float*)d_in[11];
    const float* b2s  = (const float*)d_in[12];
    float* out = (float*)d_out;

    cudaFuncSetAttribute(hmma_gemm<0,1,0>, cudaFuncAttributeMaxDynamicSharedMemorySize, SMEM_DYN);
    cudaFuncSetAttribute(hmma_gemm<0,0,0>, cudaFuncAttributeMaxDynamicSharedMemorySize, SMEM_DYN);
    cudaFuncSetAttribute(hmma_gemm<2,0,0>, cudaFuncAttributeMaxDynamicSharedMemorySize, SMEM_DYN);
    cudaFuncSetAttribute(hmma_gemm<1,1,1>, cudaFuncAttributeMaxDynamicSharedMemorySize, SMEM_DYN);
    cudaFuncSetAttribute(hmma_gemm<1,1,0>, cudaFuncAttributeMaxDynamicSharedMemorySize, SMEM_DYN);
    cudaFuncSetAttribute(hmma_gemm<1,0,0>, cudaFuncAttributeMaxDynamicSharedMemorySize, SMEM_DYN);

    #define SYM(T, n) T* n; { void* p_; cudaGetSymbolAddress(&p_, g_##n); n = (T*)p_; }
    SYM(__nv_bfloat16, hH)  SYM(__nv_bfloat16, hL)
    SYM(__nv_bfloat16, qH)  SYM(__nv_bfloat16, qL)
    SYM(__nv_bfloat16, kH)  SYM(__nv_bfloat16, kL)
    SYM(__nv_bfloat16, vTH) SYM(__nv_bfloat16, vTL)
    SYM(__nv_bfloat16, scH) SYM(__nv_bfloat16, scL)
    SYM(__nv_bfloat16, midH) SYM(__nv_bfloat16, midL)
    SYM(__nv_bfloat16, wqH) SYM(__nv_bfloat16, wqL)
    SYM(__nv_bfloat16, wkH) SYM(__nv_bfloat16, wkL)
    SYM(__nv_bfloat16, wvH) SYM(__nv_bfloat16, wvL)
    SYM(__nv_bfloat16, w1H) SYM(__nv_bfloat16, w1L)
    SYM(__nv_bfloat16, w2H) SYM(__nv_bfloat16, w2L)
    SYM(float, v)  SYM(float, sc)
    #undef SYM

    detect_kernel<<<1, 256>>>(x);
    embed_kernel<<<ROWS, 256>>>(x, emb, pos, hH, hL);

    dim3 tb(32, 8);
    transcvt_kernel<<<dim3(32, 32, 1),  tb>>>(wq, wqH, wqL, DD, DD, 0, 0);
    transcvt_kernel<<<dim3(32, 32, 1),  tb>>>(wk, wkH, wkL, DD, DD, 0, 0);
    transcvt_kernel<<<dim3(32, 32, 1),  tb>>>(wv, wvH, wvL, DD, DD, 0, 0);
    transcvt_kernel<<<dim3(128, 32, LL), tb>>>(w1s, w1H, w1L, DD, MM,
        (long long)DD * MM, (long long)DD * MM);
    transcvt_kernel<<<dim3(32, 128, LL), tb>>>(w2s, w2H, w2L, MM, DD,
        (long long)MM * DD, (long long)MM * DD);

    // QKV projections (TN)
    hmma_gemm<0,1,0><<<dim3(8, 64, 1), 256, SMEM_DYN>>>(hH, hL, wqH, wqL, bq,
        nullptr, qH, qL, ROWS, DD, DD, 0, 0, 0, 0.f);
    hmma_gemm<0,1,0><<<dim3(8, 64, 1), 256, SMEM_DYN>>>(hH, hL, wkH, wkL, bk,
        nullptr, kH, kL, ROWS, DD, DD, 0, 0, 0, 0.f);
    hmma_gemm<0,0,0><<<dim3(8, 64, 1), 256, SMEM_DYN>>>(hH, hL, wvH, wvL, bv,
        v, nullptr, nullptr, ROWS, DD, DD, 0, 0, 0, 0.f);

    // scores = q @ k^T / 32, anti-causal mask; fully-masked tiles early-exit
    hmma_gemm<2,0,0><<<dim3(16, 16, BB), 256, SMEM_DYN>>>(qH, qL, kH, kL, nullptr,
        sc, nullptr, nullptr, SS, SS, DD,
        (long long)SS * DD, (long long)SS * DD, (long long)SS * SS, 0.03125f);

    transcvt_kernel<<<dim3(32, 64, BB), tb>>>(v, vTH, vTL, SS, DD,
        (long long)SS * DD, (long long)DD * SS);

    softmax_kernel<<<ROWS, 256>>>(sc, scH, scL);

    // h = relu(attn @ v): attn rows are exactly 0 for k < row0 -> TRIM=1
    hmma_gemm<1,1,1><<<dim3(8, 16, BB), 256, SMEM_DYN>>>(scH, scL, vTH, vTL, nullptr,
        nullptr, hH, hL, SS, DD, SS,
        (long long)SS * SS, (long long)DD * SS, (long long)SS * DD, 0.f);

    // FFN stack
    for (int l = 0; l < LL; l++) {
        hmma_gemm<1,1,0><<<dim3(32, 64, 1), 256, SMEM_DYN>>>(
            hH, hL, w1H + (long long)l * DD * MM, w1L + (long long)l * DD * MM,
            b1s + (long long)l * MM, nullptr, midH, midL,
            ROWS, MM, DD, 0, 0, 0, 0.f);
        if (l == LL - 1) {
            hmma_gemm<1,0,0><<<dim3(8, 64, 1), 256, SMEM_DYN>>>(
                midH, midL, w2H + (long long)l * MM * DD, w2L + (long long)l * MM * DD,
                b2s + (long long)l * DD, out, nullptr, nullptr,
                ROWS, DD, MM, 0, 0, 0, 0.f);
        } else {
            hmma_gemm<1,1,0><<<dim3(8, 64, 1), 256, SMEM_DYN>>>(
                midH, midL, w2H + (long long)l * MM * DD, w2L + (long long)l * MM * DD,
                b2s + (long long)l * DD, nullptr, hH, hL,
                ROWS, DD, MM, 0, 0, 0, 0.f);
        }
    }
}

// round 7
// speedup vs baseline: 2.7970x; 1.0128x over previous
#include <cuda_runtime.h>
#include <cuda_bf16.h>
#include <cstdint>

// Problem constants
#define BB 4
#define SS 2048
#define DD 1024
#define MM 4096
#define LL 4
#define ROWS (BB*SS)          // 8192
#define NEG_INF __int_as_float(0xff800000)

// GEMM tiling: 128x128 tile, BK=32, 256 threads (8 warps 4x2), 2-stage cp.async
#define SA 40                 // smem row stride (bf16 elems) = 80B, conflict-free
#define TILEB 10240           // 128*SA*2 bytes per tile
#define STAGE (4*TILEB)       // aHi,aLo,bHi,bLo = 40960
#define SMEM_DYN (2*STAGE)    // 81920

// ---------------- scratch (device globals; no allocation allowed) ----------
__device__ __nv_bfloat16 g_hH[ROWS*DD],  g_hL[ROWS*DD];
__device__ __nv_bfloat16 g_qH[ROWS*DD],  g_qL[ROWS*DD];
__device__ __nv_bfloat16 g_kH[ROWS*DD],  g_kL[ROWS*DD];
__device__ __nv_bfloat16 g_vTH[ROWS*DD], g_vTL[ROWS*DD];
__device__ __nv_bfloat16 g_scH[BB*SS*SS], g_scL[BB*SS*SS];
__device__ __nv_bfloat16 g_midH[(long long)ROWS*MM], g_midL[(long long)ROWS*MM];
__device__ __nv_bfloat16 g_wqkvH[3*DD*DD], g_wqkvL[3*DD*DD];   // concatenated [3072][1024]
__device__ __nv_bfloat16 g_w1H[LL*DD*MM], g_w1L[LL*DD*MM];
__device__ __nv_bfloat16 g_w2H[LL*DD*MM], g_w2L[LL*DD*MM];
__device__ float g_v[ROWS*DD];
__device__ float g_sc[BB*SS*SS];
__device__ int   g_is32;

// ---------------------------------------------------------------------------
__global__ void detect_kernel(const void* __restrict__ x) {
    const long long* p = (const long long*)x;
    int bad = 0;
    for (int i = threadIdx.x; i < 4096; i += 256) {
        long long v = p[i];
        if (v < 0 || v >= 32000) bad = 1;
    }
    bad = __syncthreads_or(bad);
    if (threadIdx.x == 0) g_is32 = bad;
}

__device__ __forceinline__ void split4(const float* f, __nv_bfloat16* h, __nv_bfloat16* l) {
    #pragma unroll
    for (int i = 0; i < 4; i++) {
        h[i] = __float2bfloat16(f[i]);
        l[i] = __float2bfloat16(f[i] - __bfloat162float(h[i]));
    }
}

__global__ __launch_bounds__(256) void embed_kernel(
    const void* __restrict__ x, const float* __restrict__ emb,
    const float* __restrict__ pos,
    __nv_bfloat16* __restrict__ hH, __nv_bfloat16* __restrict__ hL)
{
    int row = blockIdx.x;
    int s = row & (SS - 1);
    long long tok;
    if (g_is32) tok = ((const int*)x)[row];
    else        tok = ((const long long*)x)[row];
    int t = threadIdx.x;
    float4 a = ((const float4*)(emb + tok * (long long)DD))[t];
    float4 b = ((const float4*)(pos + (long long)s * DD))[t];
    float f[4] = {a.x + b.x, a.y + b.y, a.z + b.z, a.w + b.w};
    __nv_bfloat16 hh[4], ll[4];
    split4(f, hh, ll);
    *(uint2*)(hH + (long long)row * DD + 4 * t) = *(uint2*)hh;
    *(uint2*)(hL + (long long)row * DD + 4 * t) = *(uint2*)ll;
}

// ---------------------------------------------------------------------------
// Transpose + split: in fp32 [R,C] row-major -> out bf16 hi/lo [C,R].
__global__ __launch_bounds__(256) void transcvt_kernel(
    const float* __restrict__ in,
    __nv_bfloat16* __restrict__ oH, __nv_bfloat16* __restrict__ oL,
    int R, int C, long long si, long long so)
{
    __shared__ float t[32][33];
    in += (long long)blockIdx.z * si;
    oH += (long long)blockIdx.z * so;
    oL += (long long)blockIdx.z * so;
    int x  = blockIdx.x * 32 + threadIdx.x;
    int y0 = blockIdx.y * 32 + threadIdx.y;
    #pragma unroll
    for (int j = 0; j < 32; j += 8)
        t[threadIdx.y + j][threadIdx.x] = in[(long long)(y0 + j) * C + x];
    __syncthreads();
    int x2 = blockIdx.y * 32 + threadIdx.x;
    int y2 = blockIdx.x * 32 + threadIdx.y;
    #pragma unroll
    for (int j = 0; j < 32; j += 8) {
        float v = t[threadIdx.x][threadIdx.y + j];
        __nv_bfloat16 h = __float2bfloat16(v);
        __nv_bfloat16 l = __float2bfloat16(v - __bfloat162float(h));
        oH[(long long)(y2 + j) * R + x2] = h;
        oL[(long long)(y2 + j) * R + x2] = l;
    }
}

// ---------------------------------------------------------------------------
__device__ __forceinline__ unsigned cvta_s(const void* p) {
    return (unsigned)__cvta_generic_to_shared(p);
}
__device__ __forceinline__ void cpa16(unsigned s, const void* g) {
    asm volatile("cp.async.cg.shared.global [%0], [%1], 16;" :: "r"(s), "l"(g));
}
__device__ __forceinline__ void ldsm4(unsigned addr, unsigned* r) {
    asm volatile("ldmatrix.sync.aligned.m8n8.x4.shared.b16 {%0,%1,%2,%3},[%4];"
                 : "=r"(r[0]), "=r"(r[1]), "=r"(r[2]), "=r"(r[3]) : "r"(addr));
}
__device__ __forceinline__ void mma_bf16(float* c, const unsigned* a,
                                         unsigned b0, unsigned b1) {
    asm volatile(
        "mma.sync.aligned.m16n8k16.row.col.f32.bf16.bf16.f32 "
        "{%0,%1,%2,%3},{%4,%5,%6,%7},{%8,%9},{%0,%1,%2,%3};"
        : "+f"(c[0]), "+f"(c[1]), "+f"(c[2]), "+f"(c[3])
        : "r"(a[0]), "r"(a[1]), "r"(a[2]), "r"(a[3]), "r"(b0), "r"(b1));
}

// Shared mainloop macro-ish helpers ----------------------------------------
// Inner MMA block with dependency-reordered split mmas (distance 4).
#define MMA_BLOCK(acc, ah, al, bh_cur, bl)                                    \
    {                                                                         \
        _Pragma("unroll")                                                     \
        for (int half = 0; half < 2; half++)                                  \
            _Pragma("unroll")                                                 \
            for (int mi = 0; mi < 2; mi++)                                    \
                mma_bf16(acc[mi][np * 2 + half], ah[mi],                      \
                         bh_cur[half * 2], bh_cur[half * 2 + 1]);             \
        _Pragma("unroll")                                                     \
        for (int half = 0; half < 2; half++)                                  \
            _Pragma("unroll")                                                 \
            for (int mi = 0; mi < 2; mi++)                                    \
                mma_bf16(acc[mi][np * 2 + half], al[mi],                      \
                         bh_cur[half * 2], bh_cur[half * 2 + 1]);             \
        _Pragma("unroll")                                                     \
        for (int half = 0; half < 2; half++)                                  \
            _Pragma("unroll")                                                 \
            for (int mi = 0; mi < 2; mi++)                                    \
                mma_bf16(acc[mi][np * 2 + half], ah[mi],                      \
                         bl[half * 2], bl[half * 2 + 1]);                     \
    }

// ---------------------------------------------------------------------------
// HMMA GEMM, TN: C[M,N] = A[M,K] @ B[N,K]^T, operands pre-split bf16 hi/lo.
// EPI:  0 = +bias, 1 = +bias(+opt null)+relu, 2 = scale + anti-causal mask
// OUTM: 0 = fp32 C, 1 = bf16 hi/lo (Chi/Clo)
// TRIM: 1 = start K loop at row0 (A rows are exactly zero for k < row0)
template<int EPI, int OUTM, int TRIM>
__global__ __launch_bounds__(256, 2) void hmma_gemm(
    const __nv_bfloat16* __restrict__ Ahi, const __nv_bfloat16* __restrict__ Alo,
    const __nv_bfloat16* __restrict__ Bhi, const __nv_bfloat16* __restrict__ Blo,
    const float* __restrict__ bias, float* __restrict__ C,
    __nv_bfloat16* __restrict__ Chi, __nv_bfloat16* __restrict__ Clo,
    int M, int N, int K,
    long long sA, long long sB, long long sC, float scale)
{
    extern __shared__ __align__(128) char smem[];

    const long long zC = (long long)blockIdx.z * sC;

    const int tid  = threadIdx.x;
    const int lane = tid & 31;
    const int wid  = tid >> 5;
    const int row0 = blockIdx.y * 128;
    const int col0 = blockIdx.x * 128;
    const int m_off = (wid & 3) * 32;
    const int n_off = (wid >> 2) * 64;

    if (EPI == 2 && col0 + 128 <= row0) {
        #pragma unroll
        for (int mi = 0; mi < 2; mi++) {
            #pragma unroll
            for (int ni = 0; ni < 8; ni++) {
                int r_base = row0 + m_off + mi * 16 + (lane >> 2);
                int c      = col0 + n_off + ni * 8 + 2 * (lane & 3);
                #pragma unroll
                for (int hh = 0; hh < 2; hh++) {
                    long long off = zC + (long long)(r_base + hh * 8) * N + c;
                    *(float2*)(C + off) = make_float2(NEG_INF, NEG_INF);
                }
            }
        }
        return;
    }

    const long long zA = (long long)blockIdx.z * sA;
    const long long zB = (long long)blockIdx.z * sB;
    const __nv_bfloat16* AtH = Ahi + zA + (long long)row0 * K;
    const __nv_bfloat16* AtL = Alo + zA + (long long)row0 * K;
    const __nv_bfloat16* BtH = Bhi + zB + (long long)col0 * K;
    const __nv_bfloat16* BtL = Blo + zB + (long long)col0 * K;

    const int r_ld = tid >> 2;
    const int c_ld = tid & 3;

    float acc[2][8][4];
    #pragma unroll
    for (int mi = 0; mi < 2; mi++)
        #pragma unroll
        for (int ni = 0; ni < 8; ni++)
            #pragma unroll
            for (int j = 0; j < 4; j++) acc[mi][ni][j] = 0.f;

    const int NC  = K / 32;
    const int ch0 = TRIM ? (row0 >> 5) : 0;

    auto load_stage = [&](int s, int k0) {
        unsigned sb = cvta_s(smem + s * STAGE);
        #pragma unroll
        for (int i = 0; i < 2; i++) {
            int r = r_ld + 64 * i;
            long long go = (long long)r * K + k0 + 8 * c_ld;
            unsigned so = (unsigned)(r * (SA * 2) + c_ld * 16);
            cpa16(sb + so,             AtH + go);
            cpa16(sb + TILEB + so,     AtL + go);
            cpa16(sb + 2 * TILEB + so, BtH + go);
            cpa16(sb + 3 * TILEB + so, BtL + go);
        }
        asm volatile("cp.async.commit_group;");
    };

    load_stage(0, ch0 * 32);

    for (int ch = ch0; ch < NC; ch++) {
        const int s = (ch - ch0) & 1;
        if (ch + 1 < NC) {
            load_stage(s ^ 1, (ch + 1) * 32);
            asm volatile("cp.async.wait_group 1;");
        } else {
            asm volatile("cp.async.wait_group 0;");
        }
        __syncthreads();

        const __nv_bfloat16* As_hi = (const __nv_bfloat16*)(smem + s * STAGE);
        const __nv_bfloat16* As_lo = (const __nv_bfloat16*)(smem + s * STAGE + TILEB);
        const __nv_bfloat16* Bs_hi = (const __nv_bfloat16*)(smem + s * STAGE + 2 * TILEB);
        const __nv_bfloat16* Bs_lo = (const __nv_bfloat16*)(smem + s * STAGE + 3 * TILEB);

        const int g = lane >> 3;
        const int brow_base = n_off + ((g >> 1) << 3) + (lane & 7);

        #pragma unroll
        for (int ks = 0; ks < 2; ks++) {
            const int kel_b = ks * 16 + ((g & 1) << 3);
            unsigned ah[2][4], al[2][4];
            #pragma unroll
            for (int mi = 0; mi < 2; mi++) {
                int rrow = m_off + mi * 16 + (lane & 15);
                int kel  = ((lane >> 4) << 3) + ks * 16;
                ldsm4(cvta_s(As_hi + rrow * SA + kel), ah[mi]);
                ldsm4(cvta_s(As_lo + rrow * SA + kel), al[mi]);
            }
            unsigned bh[2][4], bl[4];
            ldsm4(cvta_s(Bs_hi + brow_base * SA + kel_b), bh[0]);
            #pragma unroll
            for (int np = 0; np < 4; np++) {
                const int cur = np & 1, nxt = cur ^ 1;
                ldsm4(cvta_s(Bs_lo + (brow_base + np * 16) * SA + kel_b), bl);
                if (np < 3)
                    ldsm4(cvta_s(Bs_hi + (brow_base + (np + 1) * 16) * SA + kel_b), bh[nxt]);
                MMA_BLOCK(acc, ah, al, bh[cur], bl)
            }
        }
        __syncthreads();
    }

    const bool has_bias = (bias != nullptr);
    #pragma unroll
    for (int mi = 0; mi < 2; mi++) {
        #pragma unroll
        for (int ni = 0; ni < 8; ni++) {
            int r_base = row0 + m_off + mi * 16 + (lane >> 2);
            int c      = col0 + n_off + ni * 8 + 2 * (lane & 3);
            #pragma unroll
            for (int hh = 0; hh < 2; hh++) {
                int r = r_base + hh * 8;
                float v0 = acc[mi][ni][2 * hh];
                float v1 = acc[mi][ni][2 * hh + 1];
                if (EPI == 2) {
                    v0 *= scale; v1 *= scale;
                    if (c < r)     v0 = NEG_INF;
                    if (c + 1 < r) v1 = NEG_INF;
                } else {
                    if (has_bias) { v0 += bias[c]; v1 += bias[c + 1]; }
                    if (EPI == 1) { v0 = fmaxf(v0, 0.f); v1 = fmaxf(v1, 0.f); }
                }
                long long off = zC + (long long)r * N + c;
                if (OUTM == 0) {
                    *(float2*)(C + off) = make_float2(v0, v1);
                } else {
                    __nv_bfloat16 h2[2], l2[2];
                    h2[0] = __float2bfloat16(v0);
                    h2[1] = __float2bfloat16(v1);
                    l2[0] = __float2bfloat16(v0 - __bfloat162float(h2[0]));
                    l2[1] = __float2bfloat16(v1 - __bfloat162float(h2[1]));
                    *(unsigned*)(Chi + off) = *(unsigned*)h2;
                    *(unsigned*)(Clo + off) = *(unsigned*)l2;
                }
            }
        }
    }
}

// ---------------------------------------------------------------------------
// Fused QKV GEMM: B = concat(wqT,wkT,wvT) [3072][1024]; output routed per
// 128-col tile: cols [0,1024) -> q hi/lo, [1024,2048) -> k hi/lo,
// [2048,3072) -> v fp32. Grid dim3(24,64) = 1536 CTAs (good wave shape).
__global__ __launch_bounds__(256, 2) void hmma_qkv(
    const __nv_bfloat16* __restrict__ Ahi, const __nv_bfloat16* __restrict__ Alo,
    const __nv_bfloat16* __restrict__ Bhi, const __nv_bfloat16* __restrict__ Blo,
    const float* __restrict__ bq, const float* __restrict__ bk,
    const float* __restrict__ bv,
    __nv_bfloat16* __restrict__ qH, __nv_bfloat16* __restrict__ qL,
    __nv_bfloat16* __restrict__ kH, __nv_bfloat16* __restrict__ kL,
    float* __restrict__ vO)
{
    extern __shared__ __align__(128) char smem[];
    const int K = DD;

    const int tid  = threadIdx.x;
    const int lane = tid & 31;
    const int wid  = tid >> 5;
    const int row0 = blockIdx.y * 128;
    const int col0 = blockIdx.x * 128;
    const int m_off = (wid & 3) * 32;
    const int n_off = (wid >> 2) * 64;

    const int sel = col0 >> 10;          // 0=q 1=k 2=v (uniform per CTA)
    const int lc0 = col0 & 1023;

    const __nv_bfloat16* AtH = Ahi + (long long)row0 * K;
    const __nv_bfloat16* AtL = Alo + (long long)row0 * K;
    const __nv_bfloat16* BtH = Bhi + (long long)col0 * K;
    const __nv_bfloat16* BtL = Blo + (long long)col0 * K;

    const int r_ld = tid >> 2;
    const int c_ld = tid & 3;

    float acc[2][8][4];
    #pragma unroll
    for (int mi = 0; mi < 2; mi++)
        #pragma unroll
        for (int ni = 0; ni < 8; ni++)
            #pragma unroll
            for (int j = 0; j < 4; j++) acc[mi][ni][j] = 0.f;

    auto load_stage = [&](int s, int k0) {
        unsigned sb = cvta_s(smem + s * STAGE);
        #pragma unroll
        for (int i = 0; i < 2; i++) {
            int r = r_ld + 64 * i;
            long long go = (long long)r * K + k0 + 8 * c_ld;
            unsigned so = (unsigned)(r * (SA * 2) + c_ld * 16);
            cpa16(sb + so,             AtH + go);
            cpa16(sb + TILEB + so,     AtL + go);
            cpa16(sb + 2 * TILEB + so, BtH + go);
            cpa16(sb + 3 * TILEB + so, BtL + go);
        }
        asm volatile("cp.async.commit_group;");
    };

    const int NC = K / 32;
    load_stage(0, 0);

    for (int ch = 0; ch < NC; ch++) {
        const int s = ch & 1;
        if (ch + 1 < NC) {
            load_stage(s ^ 1, (ch + 1) * 32);
            asm volatile("cp.async.wait_group 1;");
        } else {
            asm volatile("cp.async.wait_group 0;");
        }
        __syncthreads();

        const __nv_bfloat16* As_hi = (const __nv_bfloat16*)(smem + s * STAGE);
        const __nv_bfloat16* As_lo = (const __nv_bfloat16*)(smem + s * STAGE + TILEB);
        const __nv_bfloat16* Bs_hi = (const __nv_bfloat16*)(smem + s * STAGE + 2 * TILEB);
        const __nv_bfloat16* Bs_lo = (const __nv_bfloat16*)(smem + s * STAGE + 3 * TILEB);

        const int g = lane >> 3;
        const int brow_base = n_off + ((g >> 1) << 3) + (lane & 7);

        #pragma unroll
        for (int ks = 0; ks < 2; ks++) {
            const int kel_b = ks * 16 + ((g & 1) << 3);
            unsigned ah[2][4], al[2][4];
            #pragma unroll
            for (int mi = 0; mi < 2; mi++) {
                int rrow = m_off + mi * 16 + (lane & 15);
                int kel  = ((lane >> 4) << 3) + ks * 16;
                ldsm4(cvta_s(As_hi + rrow * SA + kel), ah[mi]);
                ldsm4(cvta_s(As_lo + rrow * SA + kel), al[mi]);
            }
            unsigned bh[2][4], bl[4];
            ldsm4(cvta_s(Bs_hi + brow_base * SA + kel_b), bh[0]);
            #pragma unroll
            for (int np = 0; np < 4; np++) {
                const int cur = np & 1, nxt = cur ^ 1;
                ldsm4(cvta_s(Bs_lo + (brow_base + np * 16) * SA + kel_b), bl);
                if (np < 3)
                    ldsm4(cvta_s(Bs_hi + (brow_base + (np + 1) * 16) * SA + kel_b), bh[nxt]);
                MMA_BLOCK(acc, ah, al, bh[cur], bl)
            }
        }
        __syncthreads();
    }

    const float* bias = (sel == 0) ? bq : (sel == 1) ? bk : bv;
    __nv_bfloat16* Chi = (sel == 0) ? qH : kH;
    __nv_bfloat16* Clo = (sel == 0) ? qL : kL;

    #pragma unroll
    for (int mi = 0; mi < 2; mi++) {
        #pragma unroll
        for (int ni = 0; ni < 8; ni++) {
            int r_base = row0 + m_off + mi * 16 + (lane >> 2);
            int lc     = lc0 + n_off + ni * 8 + 2 * (lane & 3);
            #pragma unroll
            for (int hh = 0; hh < 2; hh++) {
                int r = r_base + hh * 8;
                float v0 = acc[mi][ni][2 * hh] + bias[lc];
                float v1 = acc[mi][ni][2 * hh + 1] + bias[lc + 1];
                long long off = (long long)r * DD + lc;
                if (sel == 2) {
                    *(float2*)(vO + off) = make_float2(v0, v1);
                } else {
                    __nv_bfloat16 h2[2], l2[2];
                    h2[0] = __float2bfloat16(v0);
                    h2[1] = __float2bfloat16(v1);
                    l2[0] = __float2bfloat16(v0 - __bfloat162float(h2[0]));
                    l2[1] = __float2bfloat16(v1 - __bfloat162float(h2[1]));
                    *(unsigned*)(Chi + off) = *(unsigned*)h2;
                    *(unsigned*)(Clo + off) = *(unsigned*)l2;
                }
            }
        }
    }
}

// ---------------------------------------------------------------------------
__global__ __launch_bounds__(256) void softmax_kernel(
    const float* __restrict__ sc,
    __nv_bfloat16* __restrict__ oH, __nv_bfloat16* __restrict__ oL)
{
    const float* p = sc + (long long)blockIdx.x * SS;
    __nv_bfloat16* pH = oH + (long long)blockIdx.x * SS;
    __nv_bfloat16* pL = oL + (long long)blockIdx.x * SS;
    const int t = threadIdx.x;
    const int lane = t & 31, warp = t >> 5;
    __shared__ float red[8];

    float v[8];
    float m = NEG_INF;
    #pragma unroll
    for (int i = 0; i < 8; i++) { v[i] = p[t + 256 * i]; m = fmaxf(m, v[i]); }
    #pragma unroll
    for (int o = 16; o > 0; o >>= 1) m = fmaxf(m, __shfl_xor_sync(0xffffffffu, m, o));
    if (lane == 0) red[warp] = m;
    __syncthreads();
    float mb = red[0];
    #pragma unroll
    for (int w = 1; w < 8; w++) mb = fmaxf(mb, red[w]);

    float s = 0.f;
    #pragma unroll
    for (int i = 0; i < 8; i++) { v[i] = __expf(v[i] - mb); s += v[i]; }
    #pragma unroll
    for (int o = 16; o > 0; o >>= 1) s += __shfl_xor_sync(0xffffffffu, s, o);
    __syncthreads();
    if (lane == 0) red[warp] = s;
    __syncthreads();
    float sb = 0.f;
    #pragma unroll
    for (int w = 0; w < 8; w++) sb += red[w];

    float inv = 1.f / sb;
    #pragma unroll
    for (int i = 0; i < 8; i++) {
        float x = v[i] * inv;
        __nv_bfloat16 h = __float2bfloat16(x);
        __nv_bfloat16 l = __float2bfloat16(x - __bfloat162float(h));
        pH[t + 256 * i] = h;
        pL[t + 256 * i] = l;
    }
}

// ---------------------------------------------------------------------------
extern "C" void kernel_launch(void* const* d_in, const int* in_sizes, int n_in,
                              void* d_out, int out_size)
{
    const void*  x    = d_in[0];
    const float* emb  = (const float*)d_in[1];
    const float* pos  = (const float*)d_in[2];
    const float* wq   = (const float*)d_in[3];
    const float* bq   = (const float*)d_in[4];
    const float* wk   = (const float*)d_in[5];
    const float* bk   = (const float*)d_in[6];
    const float* wv   = (const float*)d_in[7];
    const float* bv   = (const float*)d_in[8];
    const float* w1s  = (const float*)d_in[9];
    const float* b1s  = (const float*)d_in[10];
    const float* w2s  = (const float*)d_in[11];
    const float* b2s  = (const float*)d_in[12];
    float* out = (float*)d_out;

    cudaFuncSetAttribute(hmma_qkv,         cudaFuncAttributeMaxDynamicSharedMemorySize, SMEM_DYN);
    cudaFuncSetAttribute(hmma_gemm<2,0,0>, cudaFuncAttributeMaxDynamicSharedMemorySize, SMEM_DYN);
    cudaFuncSetAttribute(hmma_gemm<1,1,1>, cudaFuncAttributeMaxDynamicSharedMemorySize, SMEM_DYN);
    cudaFuncSetAttribute(hmma_gemm<1,1,0>, cudaFuncAttributeMaxDynamicSharedMemorySize, SMEM_DYN);
    cudaFuncSetAttribute(hmma_gemm<1,0,0>, cudaFuncAttributeMaxDynamicSharedMemorySize, SMEM_DYN);

    #define SYM(T, n) T* n; { void* p_; cudaGetSymbolAddress(&p_, g_##n); n = (T*)p_; }
    SYM(__nv_bfloat16, hH)  SYM(__nv_bfloat16, hL)
    SYM(__nv_bfloat16, qH)  SYM(__nv_bfloat16, qL)
    SYM(__nv_bfloat16, kH)  SYM(__nv_bfloat16, kL)
    SYM(__nv_bfloat16, vTH) SYM(__nv_bfloat16, vTL)
    SYM(__nv_bfloat16, scH) SYM(__nv_bfloat16, scL)
    SYM(__nv_bfloat16, midH) SYM(__nv_bfloat16, midL)
    SYM(__nv_bfloat16, wqkvH) SYM(__nv_bfloat16, wqkvL)
    SYM(__nv_bfloat16, w1H) SYM(__nv_bfloat16, w1L)
    SYM(__nv_bfloat16, w2H) SYM(__nv_bfloat16, w2L)
    SYM(float, v)  SYM(float, sc)
    #undef SYM

    detect_kernel<<<1, 256>>>(x);
    embed_kernel<<<ROWS, 256>>>(x, emb, pos, hH, hL);

    dim3 tb(32, 8);
    // wq/wk/wv transposed+split into one concatenated [3072][1024] buffer
    transcvt_kernel<<<dim3(32, 32, 1),  tb>>>(wq, wqkvH,            wqkvL,            DD, DD, 0, 0);
    transcvt_kernel<<<dim3(32, 32, 1),  tb>>>(wk, wqkvH + DD*DD,    wqkvL + DD*DD,    DD, DD, 0, 0);
    transcvt_kernel<<<dim3(32, 32, 1),  tb>>>(wv, wqkvH + 2*DD*DD,  wqkvL + 2*DD*DD,  DD, DD, 0, 0);
    transcvt_kernel<<<dim3(128, 32, LL), tb>>>(w1s, w1H, w1L, DD, MM,
        (long long)DD * MM, (long long)DD * MM);
    transcvt_kernel<<<dim3(32, 128, LL), tb>>>(w2s, w2H, w2L, MM, DD,
        (long long)MM * DD, (long long)MM * DD);

    // Fused QKV: one launch, 1536 CTAs
    hmma_qkv<<<dim3(24, 64, 1), 256, SMEM_DYN>>>(hH, hL, wqkvH, wqkvL,
        bq, bk, bv, qH, qL, kH, kL, v);

    // scores = q @ k^T / 32, anti-causal mask; fully-masked tiles early-exit
    hmma_gemm<2,0,0><<<dim3(16, 16, BB), 256, SMEM_DYN>>>(qH, qL, kH, kL, nullptr,
        sc, nullptr, nullptr, SS, SS, DD,
        (long long)SS * DD, (long long)SS * DD, (long long)SS * SS, 0.03125f);

    transcvt_kernel<<<dim3(32, 64, BB), tb>>>(v, vTH, vTL, SS, DD,
        (long long)SS * DD, (long long)DD * SS);

    softmax_kernel<<<ROWS, 256>>>(sc, scH, scL);

    // h = relu(attn @ v): attn rows exactly 0 for k < row0 -> TRIM=1
    hmma_gemm<1,1,1><<<dim3(8, 16, BB), 256, SMEM_DYN>>>(scH, scL, vTH, vTL, nullptr,
        nullptr, hH, hL, SS, DD, SS,
        (long long)SS * SS, (long long)DD * SS, (long long)SS * DD, 0.f);

    // FFN stack
    for (int l = 0; l < LL; l++) {
        hmma_gemm<1,1,0><<<dim3(32, 64, 1), 256, SMEM_DYN>>>(
            hH, hL, w1H + (long long)l * DD * MM, w1L + (long long)l * DD * MM,
            b1s + (long long)l * MM, nullptr, midH, midL,
            ROWS, MM, DD, 0, 0, 0, 0.f);
        if (l == LL - 1) {
            hmma_gemm<1,0,0><<<dim3(8, 64, 1), 256, SMEM_DYN>>>(
                midH, midL, w2H + (long long)l * MM * DD, w2L + (long long)l * MM * DD,
                b2s + (long long)l * DD, out, nullptr, nullptr,
                ROWS, DD, MM, 0, 0, 0, 0.f);
        } else {
            hmma_gemm<1,1,0><<<dim3(8, 64, 1), 256, SMEM_DYN>>>(
                midH, midL, w2H + (long long)l * MM * DD, w2L + (long long)l * MM * DD,
                b2s + (long long)l * DD, nullptr, hH, hL,
                ROWS, DD, MM, 0, 0, 0, 0.f);
        }
    }
}

// round 8
// speedup vs baseline: 2.7990x; 1.0007x over previous
#include <cuda_runtime.h>
#include <cuda_bf16.h>
#include <cstdint>

// Problem constants
#define BB 4
#define SS 2048
#define DD 1024
#define MM 4096
#define LL 4
#define ROWS (BB*SS)          // 8192
#define NEG_INF __int_as_float(0xff800000)

// GEMM tiling: 128x256 tile, BK=32, 512 threads (16 warps 4x4), 3-stage cp.async
#define SA 40                 // smem row stride (bf16) = 80B, conflict-free
#define ATILE 10240           // 128*SA*2
#define BTILE 20480           // 256*SA*2
#define STAGE (2*ATILE + 2*BTILE)   // 61440
#define NSTG 3
#define SMEM_DYN (NSTG*STAGE)       // 184320

// ---------------- scratch (device globals; no allocation allowed) ----------
__device__ __nv_bfloat16 g_hH[ROWS*DD],  g_hL[ROWS*DD];
__device__ __nv_bfloat16 g_qH[ROWS*DD],  g_qL[ROWS*DD];
__device__ __nv_bfloat16 g_kH[ROWS*DD],  g_kL[ROWS*DD];
__device__ __nv_bfloat16 g_vTH[ROWS*DD], g_vTL[ROWS*DD];
__device__ __nv_bfloat16 g_scH[BB*SS*SS], g_scL[BB*SS*SS];
__device__ __nv_bfloat16 g_midH[(long long)ROWS*MM], g_midL[(long long)ROWS*MM];
__device__ __nv_bfloat16 g_wqkvH[3*DD*DD], g_wqkvL[3*DD*DD];
__device__ __nv_bfloat16 g_w1H[LL*DD*MM], g_w1L[LL*DD*MM];
__device__ __nv_bfloat16 g_w2H[LL*DD*MM], g_w2L[LL*DD*MM];
__device__ float g_v[ROWS*DD];
__device__ float g_sc[BB*SS*SS];
__device__ int   g_is32;

// ---------------------------------------------------------------------------
__global__ void detect_kernel(const void* __restrict__ x) {
    const long long* p = (const long long*)x;
    int bad = 0;
    for (int i = threadIdx.x; i < 4096; i += 256) {
        long long v = p[i];
        if (v < 0 || v >= 32000) bad = 1;
    }
    bad = __syncthreads_or(bad);
    if (threadIdx.x == 0) g_is32 = bad;
}

__device__ __forceinline__ void split4(const float* f, __nv_bfloat16* h, __nv_bfloat16* l) {
    #pragma unroll
    for (int i = 0; i < 4; i++) {
        h[i] = __float2bfloat16(f[i]);
        l[i] = __float2bfloat16(f[i] - __bfloat162float(h[i]));
    }
}

__global__ __launch_bounds__(256) void embed_kernel(
    const void* __restrict__ x, const float* __restrict__ emb,
    const float* __restrict__ pos,
    __nv_bfloat16* __restrict__ hH, __nv_bfloat16* __restrict__ hL)
{
    int row = blockIdx.x;
    int s = row & (SS - 1);
    long long tok;
    if (g_is32) tok = ((const int*)x)[row];
    else        tok = ((const long long*)x)[row];
    int t = threadIdx.x;
    float4 a = ((const float4*)(emb + tok * (long long)DD))[t];
    float4 b = ((const float4*)(pos + (long long)s * DD))[t];
    float f[4] = {a.x + b.x, a.y + b.y, a.z + b.z, a.w + b.w};
    __nv_bfloat16 hh[4], ll[4];
    split4(f, hh, ll);
    *(uint2*)(hH + (long long)row * DD + 4 * t) = *(uint2*)hh;
    *(uint2*)(hL + (long long)row * DD + 4 * t) = *(uint2*)ll;
}

// ---------------------------------------------------------------------------
// Transpose + split: in fp32 [R,C] row-major -> out bf16 hi/lo [C,R].
__global__ __launch_bounds__(256) void transcvt_kernel(
    const float* __restrict__ in,
    __nv_bfloat16* __restrict__ oH, __nv_bfloat16* __restrict__ oL,
    int R, int C, long long si, long long so)
{
    __shared__ float t[32][33];
    in += (long long)blockIdx.z * si;
    oH += (long long)blockIdx.z * so;
    oL += (long long)blockIdx.z * so;
    int x  = blockIdx.x * 32 + threadIdx.x;
    int y0 = blockIdx.y * 32 + threadIdx.y;
    #pragma unroll
    for (int j = 0; j < 32; j += 8)
        t[threadIdx.y + j][threadIdx.x] = in[(long long)(y0 + j) * C + x];
    __syncthreads();
    int x2 = blockIdx.y * 32 + threadIdx.x;
    int y2 = blockIdx.x * 32 + threadIdx.y;
    #pragma unroll
    for (int j = 0; j < 32; j += 8) {
        float v = t[threadIdx.x][threadIdx.y + j];
        __nv_bfloat16 h = __float2bfloat16(v);
        __nv_bfloat16 l = __float2bfloat16(v - __bfloat162float(h));
        oH[(long long)(y2 + j) * R + x2] = h;
        oL[(long long)(y2 + j) * R + x2] = l;
    }
}

// QKV weight transpose+split in ONE launch (z selects wq/wk/wv).
__global__ __launch_bounds__(256) void qkvw_transcvt_kernel(
    const float* __restrict__ wq, const float* __restrict__ wk,
    const float* __restrict__ wv,
    __nv_bfloat16* __restrict__ oH, __nv_bfloat16* __restrict__ oL)
{
    __shared__ float t[32][33];
    const float* in = (blockIdx.z == 0) ? wq : (blockIdx.z == 1) ? wk : wv;
    oH += (long long)blockIdx.z * DD * DD;
    oL += (long long)blockIdx.z * DD * DD;
    int x  = blockIdx.x * 32 + threadIdx.x;
    int y0 = blockIdx.y * 32 + threadIdx.y;
    #pragma unroll
    for (int j = 0; j < 32; j += 8)
        t[threadIdx.y + j][threadIdx.x] = in[(long long)(y0 + j) * DD + x];
    __syncthreads();
    int x2 = blockIdx.y * 32 + threadIdx.x;
    int y2 = blockIdx.x * 32 + threadIdx.y;
    #pragma unroll
    for (int j = 0; j < 32; j += 8) {
        float v = t[threadIdx.x][threadIdx.y + j];
        __nv_bfloat16 h = __float2bfloat16(v);
        __nv_bfloat16 l = __float2bfloat16(v - __bfloat162float(h));
        oH[(long long)(y2 + j) * DD + x2] = h;
        oL[(long long)(y2 + j) * DD + x2] = l;
    }
}

// ---------------------------------------------------------------------------
__device__ __forceinline__ unsigned cvta_s(const void* p) {
    return (unsigned)__cvta_generic_to_shared(p);
}
__device__ __forceinline__ void cpa16(unsigned s, const void* g) {
    asm volatile("cp.async.cg.shared.global [%0], [%1], 16;" :: "r"(s), "l"(g));
}
__device__ __forceinline__ void ldsm4(unsigned addr, unsigned* r) {
    asm volatile("ldmatrix.sync.aligned.m8n8.x4.shared.b16 {%0,%1,%2,%3},[%4];"
                 : "=r"(r[0]), "=r"(r[1]), "=r"(r[2]), "=r"(r[3]) : "r"(addr));
}
__device__ __forceinline__ void mma_bf16(float* c, const unsigned* a,
                                         unsigned b0, unsigned b1) {
    asm volatile(
        "mma.sync.aligned.m16n8k16.row.col.f32.bf16.bf16.f32 "
        "{%0,%1,%2,%3},{%4,%5,%6,%7},{%8,%9},{%0,%1,%2,%3};"
        : "+f"(c[0]), "+f"(c[1]), "+f"(c[2]), "+f"(c[3])
        : "r"(a[0]), "r"(a[1]), "r"(a[2]), "r"(a[3]), "r"(b0), "r"(b1));
}

// Inner MMA block with dependency-reordered split mmas.
#define MMA_BLOCK(acc, ah, al, bh_cur, bl)                                    \
    {                                                                         \
        _Pragma("unroll")                                                     \
        for (int half = 0; half < 2; half++)                                  \
            _Pragma("unroll")                                                 \
            for (int mi = 0; mi < 2; mi++)                                    \
                mma_bf16(acc[mi][np * 2 + half], ah[mi],                      \
                         bh_cur[half * 2], bh_cur[half * 2 + 1]);             \
        _Pragma("unroll")                                                     \
        for (int half = 0; half < 2; half++)                                  \
            _Pragma("unroll")                                                 \
            for (int mi = 0; mi < 2; mi++)                                    \
                mma_bf16(acc[mi][np * 2 + half], al[mi],                      \
                         bh_cur[half * 2], bh_cur[half * 2 + 1]);             \
        _Pragma("unroll")                                                     \
        for (int half = 0; half < 2; half++)                                  \
            _Pragma("unroll")                                                 \
            for (int mi = 0; mi < 2; mi++)                                    \
                mma_bf16(acc[mi][np * 2 + half], ah[mi],                      \
                         bl[half * 2], bl[half * 2 + 1]);                     \
    }

// Shared mainloop body (lambda-free macro so both kernels reuse it) ---------
#define GEMM_MAINLOOP(NCv, CH0v)                                              \
    auto load_stage = [&](int s, int k0) {                                    \
        unsigned sb = cvta_s(smem + s * STAGE);                               \
        {                                                                     \
            int r = tid >> 2, c = tid & 3;                                    \
            long long go = (long long)r * K + k0 + 8 * c;                     \
            unsigned so = (unsigned)(r * 80 + c * 16);                        \
            cpa16(sb + so, AtH + go);                                         \
            cpa16(sb + ATILE + so, AtL + go);                                 \
        }                                                                     \
        _Pragma("unroll")                                                     \
        for (int i = 0; i < 2; i++) {                                         \
            int r = (tid >> 2) + 128 * i, c = tid & 3;                        \
            long long go = (long long)r * K + k0 + 8 * c;                     \
            unsigned so = (unsigned)(r * 80 + c * 16);                        \
            cpa16(sb + 2 * ATILE + so, BtH + go);                             \
            cpa16(sb + 2 * ATILE + BTILE + so, BtL + go);                     \
        }                                                                     \
        asm volatile("cp.async.commit_group;");                               \
    };                                                                        \
    load_stage(0, (CH0v) * 32);                                               \
    if ((CH0v) + 1 < (NCv)) load_stage(1, ((CH0v) + 1) * 32);                 \
    else asm volatile("cp.async.commit_group;");                              \
    for (int ch = (CH0v); ch < (NCv); ch++) {                                 \
        const int s = (ch - (CH0v)) % NSTG;                                   \
        asm volatile("cp.async.wait_group 1;");                               \
        __syncthreads();                                                      \
        if (ch + 2 < (NCv))                                                   \
            load_stage((ch - (CH0v) + 2) % NSTG, (ch + 2) * 32);              \
        else                                                                  \
            asm volatile("cp.async.commit_group;");                           \
        const __nv_bfloat16* As_hi = (const __nv_bfloat16*)(smem + s * STAGE);            \
        const __nv_bfloat16* As_lo = (const __nv_bfloat16*)(smem + s * STAGE + ATILE);    \
        const __nv_bfloat16* Bs_hi = (const __nv_bfloat16*)(smem + s * STAGE + 2 * ATILE);\
        const __nv_bfloat16* Bs_lo = (const __nv_bfloat16*)(smem + s * STAGE + 2 * ATILE + BTILE);\
        const int g = lane >> 3;                                              \
        const int brow_base = n_off + ((g >> 1) << 3) + (lane & 7);           \
        _Pragma("unroll")                                                     \
        for (int ks = 0; ks < 2; ks++) {                                      \
            const int kel_b = ks * 16 + ((g & 1) << 3);                       \
            unsigned ah[2][4], al[2][4];                                      \
            _Pragma("unroll")                                                 \
            for (int mi = 0; mi < 2; mi++) {                                  \
                int rrow = m_off + mi * 16 + (lane & 15);                     \
                int kel  = ((lane >> 4) << 3) + ks * 16;                      \
                ldsm4(cvta_s(As_hi + rrow * SA + kel), ah[mi]);               \
                ldsm4(cvta_s(As_lo + rrow * SA + kel), al[mi]);               \
            }                                                                 \
            unsigned bh[2][4], bl[4];                                         \
            ldsm4(cvta_s(Bs_hi + brow_base * SA + kel_b), bh[0]);             \
            _Pragma("unroll")                                                 \
            for (int np = 0; np < 4; np++) {                                  \
                const int cur = np & 1, nxt = cur ^ 1;                        \
                ldsm4(cvta_s(Bs_lo + (brow_base + np * 16) * SA + kel_b), bl);\
                if (np < 3)                                                   \
                    ldsm4(cvta_s(Bs_hi + (brow_base + (np + 1) * 16) * SA + kel_b), bh[nxt]);\
                MMA_BLOCK(acc, ah, al, bh[cur], bl)                           \
            }                                                                 \
        }                                                                     \
    }

// ---------------------------------------------------------------------------
// HMMA GEMM, TN: C[M,N] = A[M,K] @ B[N,K]^T. 128x256 tile, 512 threads.
// EPI:  0 = +bias, 1 = +bias(+opt null)+relu, 2 = scale + anti-causal mask
// OUTM: 0 = fp32 C, 1 = bf16 hi/lo
// TRIM: 1 = start K loop at row0 (A cols exactly zero for k < row0)
template<int EPI, int OUTM, int TRIM>
__global__ __launch_bounds__(512, 1) void hmma_gemm(
    const __nv_bfloat16* __restrict__ Ahi, const __nv_bfloat16* __restrict__ Alo,
    const __nv_bfloat16* __restrict__ Bhi, const __nv_bfloat16* __restrict__ Blo,
    const float* __restrict__ bias, float* __restrict__ C,
    __nv_bfloat16* __restrict__ Chi, __nv_bfloat16* __restrict__ Clo,
    int M, int N, int K,
    long long sA, long long sB, long long sC, float scale)
{
    extern __shared__ __align__(128) char smem[];

    const long long zC = (long long)blockIdx.z * sC;
    const int tid  = threadIdx.x;
    const int lane = tid & 31;
    const int wid  = tid >> 5;
    const int row0 = blockIdx.y * 128;
    const int col0 = blockIdx.x * 256;
    const int m_off = (wid & 3) * 32;
    const int n_off = (wid >> 2) * 64;

    if (EPI == 2 && col0 + 256 <= row0) {
        #pragma unroll
        for (int mi = 0; mi < 2; mi++) {
            #pragma unroll
            for (int ni = 0; ni < 8; ni++) {
                int r_base = row0 + m_off + mi * 16 + (lane >> 2);
                int c      = col0 + n_off + ni * 8 + 2 * (lane & 3);
                #pragma unroll
                for (int hh = 0; hh < 2; hh++) {
                    long long off = zC + (long long)(r_base + hh * 8) * N + c;
                    *(float2*)(C + off) = make_float2(NEG_INF, NEG_INF);
                }
            }
        }
        return;
    }

    const long long zA = (long long)blockIdx.z * sA;
    const long long zB = (long long)blockIdx.z * sB;
    const __nv_bfloat16* AtH = Ahi + zA + (long long)row0 * K;
    const __nv_bfloat16* AtL = Alo + zA + (long long)row0 * K;
    const __nv_bfloat16* BtH = Bhi + zB + (long long)col0 * K;
    const __nv_bfloat16* BtL = Blo + zB + (long long)col0 * K;

    float acc[2][8][4];
    #pragma unroll
    for (int mi = 0; mi < 2; mi++)
        #pragma unroll
        for (int ni = 0; ni < 8; ni++)
            #pragma unroll
            for (int j = 0; j < 4; j++) acc[mi][ni][j] = 0.f;

    const int NC  = K / 32;
    const int ch0 = TRIM ? (row0 >> 5) : 0;

    GEMM_MAINLOOP(NC, ch0)

    const bool has_bias = (bias != nullptr);
    #pragma unroll
    for (int mi = 0; mi < 2; mi++) {
        #pragma unroll
        for (int ni = 0; ni < 8; ni++) {
            int r_base = row0 + m_off + mi * 16 + (lane >> 2);
            int c      = col0 + n_off + ni * 8 + 2 * (lane & 3);
            #pragma unroll
            for (int hh = 0; hh < 2; hh++) {
                int r = r_base + hh * 8;
                float v0 = acc[mi][ni][2 * hh];
                float v1 = acc[mi][ni][2 * hh + 1];
                if (EPI == 2) {
                    v0 *= scale; v1 *= scale;
                    if (c < r)     v0 = NEG_INF;
                    if (c + 1 < r) v1 = NEG_INF;
                } else {
                    if (has_bias) { v0 += bias[c]; v1 += bias[c + 1]; }
                    if (EPI == 1) { v0 = fmaxf(v0, 0.f); v1 = fmaxf(v1, 0.f); }
                }
                long long off = zC + (long long)r * N + c;
                if (OUTM == 0) {
                    *(float2*)(C + off) = make_float2(v0, v1);
                } else {
                    __nv_bfloat16 h2[2], l2[2];
                    h2[0] = __float2bfloat16(v0);
                    h2[1] = __float2bfloat16(v1);
                    l2[0] = __float2bfloat16(v0 - __bfloat162float(h2[0]));
                    l2[1] = __float2bfloat16(v1 - __bfloat162float(h2[1]));
                    *(unsigned*)(Chi + off) = *(unsigned*)h2;
                    *(unsigned*)(Clo + off) = *(unsigned*)l2;
                }
            }
        }
    }
}

// ---------------------------------------------------------------------------
// Fused QKV GEMM (128x256 tiles): cols [0,1024)->q, [1024,2048)->k, rest->v fp32.
__global__ __launch_bounds__(512, 1) void hmma_qkv(
    const __nv_bfloat16* __restrict__ Ahi, const __nv_bfloat16* __restrict__ Alo,
    const __nv_bfloat16* __restrict__ Bhi, const __nv_bfloat16* __restrict__ Blo,
    const float* __restrict__ bq, const float* __restrict__ bk,
    const float* __restrict__ bv,
    __nv_bfloat16* __restrict__ qH, __nv_bfloat16* __restrict__ qL,
    __nv_bfloat16* __restrict__ kH, __nv_bfloat16* __restrict__ kL,
    float* __restrict__ vO)
{
    extern __shared__ __align__(128) char smem[];
    const int K = DD;

    const int tid  = threadIdx.x;
    const int lane = tid & 31;
    const int wid  = tid >> 5;
    const int row0 = blockIdx.y * 128;
    const int col0 = blockIdx.x * 256;
    const int m_off = (wid & 3) * 32;
    const int n_off = (wid >> 2) * 64;

    const int sel = col0 >> 10;
    const int lc0 = col0 & 1023;

    const __nv_bfloat16* AtH = Ahi + (long long)row0 * K;
    const __nv_bfloat16* AtL = Alo + (long long)row0 * K;
    const __nv_bfloat16* BtH = Bhi + (long long)col0 * K;
    const __nv_bfloat16* BtL = Blo + (long long)col0 * K;

    float acc[2][8][4];
    #pragma unroll
    for (int mi = 0; mi < 2; mi++)
        #pragma unroll
        for (int ni = 0; ni < 8; ni++)
            #pragma unroll
            for (int j = 0; j < 4; j++) acc[mi][ni][j] = 0.f;

    const int NC = K / 32;
    GEMM_MAINLOOP(NC, 0)

    const float* bias = (sel == 0) ? bq : (sel == 1) ? bk : bv;
    __nv_bfloat16* Chi = (sel == 0) ? qH : kH;
    __nv_bfloat16* Clo = (sel == 0) ? qL : kL;

    #pragma unroll
    for (int mi = 0; mi < 2; mi++) {
        #pragma unroll
        for (int ni = 0; ni < 8; ni++) {
            int r_base = row0 + m_off + mi * 16 + (lane >> 2);
            int lc     = lc0 + n_off + ni * 8 + 2 * (lane & 3);
            #pragma unroll
            for (int hh = 0; hh < 2; hh++) {
                int r = r_base + hh * 8;
                float v0 = acc[mi][ni][2 * hh] + bias[lc];
                float v1 = acc[mi][ni][2 * hh + 1] + bias[lc + 1];
                long long off = (long long)r * DD + lc;
                if (sel == 2) {
                    *(float2*)(vO + off) = make_float2(v0, v1);
                } else {
                    __nv_bfloat16 h2[2], l2[2];
                    h2[0] = __float2bfloat16(v0);
                    h2[1] = __float2bfloat16(v1);
                    l2[0] = __float2bfloat16(v0 - __bfloat162float(h2[0]));
                    l2[1] = __float2bfloat16(v1 - __bfloat162float(h2[1]));
                    *(unsigned*)(Chi + off) = *(unsigned*)h2;
                    *(unsigned*)(Clo + off) = *(unsigned*)l2;
                }
            }
        }
    }
}

// ---------------------------------------------------------------------------
__global__ __launch_bounds__(256) void softmax_kernel(
    const float* __restrict__ sc,
    __nv_bfloat16* __restrict__ oH, __nv_bfloat16* __restrict__ oL)
{
    const float* p = sc + (long long)blockIdx.x * SS;
    __nv_bfloat16* pH = oH + (long long)blockIdx.x * SS;
    __nv_bfloat16* pL = oL + (long long)blockIdx.x * SS;
    const int t = threadIdx.x;
    const int lane = t & 31, warp = t >> 5;
    __shared__ float red[8];

    float v[8];
    float m = NEG_INF;
    #pragma unroll
    for (int i = 0; i < 8; i++) { v[i] = p[t + 256 * i]; m = fmaxf(m, v[i]); }
    #pragma unroll
    for (int o = 16; o > 0; o >>= 1) m = fmaxf(m, __shfl_xor_sync(0xffffffffu, m, o));
    if (lane == 0) red[warp] = m;
    __syncthreads();
    float mb = red[0];
    #pragma unroll
    for (int w = 1; w < 8; w++) mb = fmaxf(mb, red[w]);

    float s = 0.f;
    #pragma unroll
    for (int i = 0; i < 8; i++) { v[i] = __expf(v[i] - mb); s += v[i]; }
    #pragma unroll
    for (int o = 16; o > 0; o >>= 1) s += __shfl_xor_sync(0xffffffffu, s, o);
    __syncthreads();
    if (lane == 0) red[warp] = s;
    __syncthreads();
    float sb = 0.f;
    #pragma unroll
    for (int w = 0; w < 8; w++) sb += red[w];

    float inv = 1.f / sb;
    #pragma unroll
    for (int i = 0; i < 8; i++) {
        float x = v[i] * inv;
        __nv_bfloat16 h = __float2bfloat16(x);
        __nv_bfloat16 l = __float2bfloat16(x - __bfloat162float(h));
        pH[t + 256 * i] = h;
        pL[t + 256 * i] = l;
    }
}

// ---------------------------------------------------------------------------
extern "C" void kernel_launch(void* const* d_in, const int* in_sizes, int n_in,
                              void* d_out, int out_size)
{
    const void*  x    = d_in[0];
    const float* emb  = (const float*)d_in[1];
    const float* pos  = (const float*)d_in[2];
    const float* wq   = (const float*)d_in[3];
    const float* bq   = (const float*)d_in[4];
    const float* wk   = (const float*)d_in[5];
    const float* bk   = (const float*)d_in[6];
    const float* wv   = (const float*)d_in[7];
    const float* bv   = (const float*)d_in[8];
    const float* w1s  = (const float*)d_in[9];
    const float* b1s  = (const float*)d_in[10];
    const float* w2s  = (const float*)d_in[11];
    const float* b2s  = (const float*)d_in[12];
    float* out = (float*)d_out;

    cudaFuncSetAttribute(hmma_qkv,         cudaFuncAttributeMaxDynamicSharedMemorySize, SMEM_DYN);
    cudaFuncSetAttribute(hmma_gemm<2,0,0>, cudaFuncAttributeMaxDynamicSharedMemorySize, SMEM_DYN);
    cudaFuncSetAttribute(hmma_gemm<1,1,1>, cudaFuncAttributeMaxDynamicSharedMemorySize, SMEM_DYN);
    cudaFuncSetAttribute(hmma_gemm<1,1,0>, cudaFuncAttributeMaxDynamicSharedMemorySize, SMEM_DYN);
    cudaFuncSetAttribute(hmma_gemm<1,0,0>, cudaFuncAttributeMaxDynamicSharedMemorySize, SMEM_DYN);

    #define SYM(T, n) T* n; { void* p_; cudaGetSymbolAddress(&p_, g_##n); n = (T*)p_; }
    SYM(__nv_bfloat16, hH)  SYM(__nv_bfloat16, hL)
    SYM(__nv_bfloat16, qH)  SYM(__nv_bfloat16, qL)
    SYM(__nv_bfloat16, kH)  SYM(__nv_bfloat16, kL)
    SYM(__nv_bfloat16, vTH) SYM(__nv_bfloat16, vTL)
    SYM(__nv_bfloat16, scH) SYM(__nv_bfloat16, scL)
    SYM(__nv_bfloat16, midH) SYM(__nv_bfloat16, midL)
    SYM(__nv_bfloat16, wqkvH) SYM(__nv_bfloat16, wqkvL)
    SYM(__nv_bfloat16, w1H) SYM(__nv_bfloat16, w1L)
    SYM(__nv_bfloat16, w2H) SYM(__nv_bfloat16, w2L)
    SYM(float, v)  SYM(float, sc)
    #undef SYM

    dim3 tb(32, 8);
    // Launch order puts hmma_qkv at position 6 so ncu (-s 5 -c 1) captures it.
    detect_kernel<<<1, 256>>>(x);                                           // 1
    embed_kernel<<<ROWS, 256>>>(x, emb, pos, hH, hL);                       // 2
    qkvw_transcvt_kernel<<<dim3(32, 32, 3), tb>>>(wq, wk, wv, wqkvH, wqkvL);// 3
    transcvt_kernel<<<dim3(128, 32, LL), tb>>>(w1s, w1H, w1L, DD, MM,       // 4
        (long long)DD * MM, (long long)DD * MM);
    transcvt_kernel<<<dim3(32, 128, LL), tb>>>(w2s, w2H, w2L, MM, DD,       // 5
        (long long)MM * DD, (long long)MM * DD);

    // Fused QKV: grid (12,64) = 768 CTAs                                   // 6
    hmma_qkv<<<dim3(12, 64, 1), 512, SMEM_DYN>>>(hH, hL, wqkvH, wqkvL,
        bq, bk, bv, qH, qL, kH, kL, v);

    // scores = q @ k^T / 32, anti-causal mask; fully-masked tiles early-exit
    hmma_gemm<2,0,0><<<dim3(8, 16, BB), 512, SMEM_DYN>>>(qH, qL, kH, kL, nullptr,
        sc, nullptr, nullptr, SS, SS, DD,
        (long long)SS * DD, (long long)SS * DD, (long long)SS * SS, 0.03125f);

    transcvt_kernel<<<dim3(32, 64, BB), tb>>>(v, vTH, vTL, SS, DD,
        (long long)SS * DD, (long long)DD * SS);

    softmax_kernel<<<ROWS, 256>>>(sc, scH, scL);

    // h = relu(attn @ v): attn rows exactly 0 for k < row0 -> TRIM=1
    hmma_gemm<1,1,1><<<dim3(4, 16, BB), 512, SMEM_DYN>>>(scH, scL, vTH, vTL, nullptr,
        nullptr, hH, hL, SS, DD, SS,
        (long long)SS * SS, (long long)DD * SS, (long long)SS * DD, 0.f);

    // FFN stack
    for (int l = 0; l < LL; l++) {
        hmma_gemm<1,1,0><<<dim3(16, 64, 1), 512, SMEM_DYN>>>(
            hH, hL, w1H + (long long)l * DD * MM, w1L + (long long)l * DD * MM,
            b1s + (long long)l * MM, nullptr, midH, midL,
            ROWS, MM, DD, 0, 0, 0, 0.f);
        if (l == LL - 1) {
            hmma_gemm<1,0,0><<<dim3(4, 64, 1), 512, SMEM_DYN>>>(
                midH, midL, w2H + (long long)l * MM * DD, w2L + (long long)l * MM * DD,
                b2s + (long long)l * DD, out, nullptr, nullptr,
                ROWS, DD, MM, 0, 0, 0, 0.f);
        } else {
            hmma_gemm<1,1,0><<<dim3(4, 64, 1), 512, SMEM_DYN>>>(
                midH, midL, w2H + (long long)l * MM * DD, w2L + (long long)l * MM * DD,
                b2s + (long long)l * DD, nullptr, hH, hL,
                ROWS, DD, MM, 0, 0, 0, 0.f);
        }
    }
}

// round 9
// speedup vs baseline: 2.8498x; 1.0182x over previous
#include <cuda_runtime.h>
#include <cuda_bf16.h>
#include <cstdint>

// Problem constants
#define BB 4
#define SS 2048
#define DD 1024
#define MM 4096
#define LL 4
#define ROWS (BB*SS)          // 8192
#define NEG_INF __int_as_float(0xff800000)

// GEMM tiling: 128x256 block tile, BK=32, 256 threads (8 warps 2x4, warp 64x64)
#define SA 40                 // smem row stride (bf16) = 80B, conflict-free
#define ATILE 10240           // 128*SA*2
#define BTILE 20480           // 256*SA*2
#define STAGE (2*ATILE + 2*BTILE)   // 61440
#define NSTG 3
#define SMEM_DYN (NSTG*STAGE)       // 184320

// ---------------- scratch (device globals; no allocation allowed) ----------
__device__ __nv_bfloat16 g_hH[ROWS*DD],  g_hL[ROWS*DD];
__device__ __nv_bfloat16 g_qH[ROWS*DD],  g_qL[ROWS*DD];
__device__ __nv_bfloat16 g_kH[ROWS*DD],  g_kL[ROWS*DD];
__device__ __nv_bfloat16 g_vTH[ROWS*DD], g_vTL[ROWS*DD];
__device__ __nv_bfloat16 g_scH[BB*SS*SS], g_scL[BB*SS*SS];
__device__ __nv_bfloat16 g_midH[(long long)ROWS*MM], g_midL[(long long)ROWS*MM];
__device__ __nv_bfloat16 g_wqkvH[3*DD*DD], g_wqkvL[3*DD*DD];
__device__ __nv_bfloat16 g_w1H[LL*DD*MM], g_w1L[LL*DD*MM];
__device__ __nv_bfloat16 g_w2H[LL*DD*MM], g_w2L[LL*DD*MM];
__device__ float g_v[ROWS*DD];
__device__ float g_sc[BB*SS*SS];
__device__ int   g_is32;

// ---------------------------------------------------------------------------
__global__ void detect_kernel(const void* __restrict__ x) {
    const long long* p = (const long long*)x;
    int bad = 0;
    for (int i = threadIdx.x; i < 4096; i += 256) {
        long long v = p[i];
        if (v < 0 || v >= 32000) bad = 1;
    }
    bad = __syncthreads_or(bad);
    if (threadIdx.x == 0) g_is32 = bad;
}

__device__ __forceinline__ void split4(const float* f, __nv_bfloat16* h, __nv_bfloat16* l) {
    #pragma unroll
    for (int i = 0; i < 4; i++) {
        h[i] = __float2bfloat16(f[i]);
        l[i] = __float2bfloat16(f[i] - __bfloat162float(h[i]));
    }
}

__global__ __launch_bounds__(256) void embed_kernel(
    const void* __restrict__ x, const float* __restrict__ emb,
    const float* __restrict__ pos,
    __nv_bfloat16* __restrict__ hH, __nv_bfloat16* __restrict__ hL)
{
    int row = blockIdx.x;
    int s = row & (SS - 1);
    long long tok;
    if (g_is32) tok = ((const int*)x)[row];
    else        tok = ((const long long*)x)[row];
    int t = threadIdx.x;
    float4 a = ((const float4*)(emb + tok * (long long)DD))[t];
    float4 b = ((const float4*)(pos + (long long)s * DD))[t];
    float f[4] = {a.x + b.x, a.y + b.y, a.z + b.z, a.w + b.w};
    __nv_bfloat16 hh[4], ll[4];
    split4(f, hh, ll);
    *(uint2*)(hH + (long long)row * DD + 4 * t) = *(uint2*)hh;
    *(uint2*)(hL + (long long)row * DD + 4 * t) = *(uint2*)ll;
}

// ---------------------------------------------------------------------------
// Transpose + split: in fp32 [R,C] row-major -> out bf16 hi/lo [C,R].
__global__ __launch_bounds__(256) void transcvt_kernel(
    const float* __restrict__ in,
    __nv_bfloat16* __restrict__ oH, __nv_bfloat16* __restrict__ oL,
    int R, int C, long long si, long long so)
{
    __shared__ float t[32][33];
    in += (long long)blockIdx.z * si;
    oH += (long long)blockIdx.z * so;
    oL += (long long)blockIdx.z * so;
    int x  = blockIdx.x * 32 + threadIdx.x;
    int y0 = blockIdx.y * 32 + threadIdx.y;
    #pragma unroll
    for (int j = 0; j < 32; j += 8)
        t[threadIdx.y + j][threadIdx.x] = in[(long long)(y0 + j) * C + x];
    __syncthreads();
    int x2 = blockIdx.y * 32 + threadIdx.x;
    int y2 = blockIdx.x * 32 + threadIdx.y;
    #pragma unroll
    for (int j = 0; j < 32; j += 8) {
        float v = t[threadIdx.x][threadIdx.y + j];
        __nv_bfloat16 h = __float2bfloat16(v);
        __nv_bfloat16 l = __float2bfloat16(v - __bfloat162float(h));
        oH[(long long)(y2 + j) * R + x2] = h;
        oL[(long long)(y2 + j) * R + x2] = l;
    }
}

// QKV weight transpose+split in ONE launch (z selects wq/wk/wv).
__global__ __launch_bounds__(256) void qkvw_transcvt_kernel(
    const float* __restrict__ wq, const float* __restrict__ wk,
    const float* __restrict__ wv,
    __nv_bfloat16* __restrict__ oH, __nv_bfloat16* __restrict__ oL)
{
    __shared__ float t[32][33];
    const float* in = (blockIdx.z == 0) ? wq : (blockIdx.z == 1) ? wk : wv;
    oH += (long long)blockIdx.z * DD * DD;
    oL += (long long)blockIdx.z * DD * DD;
    int x  = blockIdx.x * 32 + threadIdx.x;
    int y0 = blockIdx.y * 32 + threadIdx.y;
    #pragma unroll
    for (int j = 0; j < 32; j += 8)
        t[threadIdx.y + j][threadIdx.x] = in[(long long)(y0 + j) * DD + x];
    __syncthreads();
    int x2 = blockIdx.y * 32 + threadIdx.x;
    int y2 = blockIdx.x * 32 + threadIdx.y;
    #pragma unroll
    for (int j = 0; j < 32; j += 8) {
        float v = t[threadIdx.x][threadIdx.y + j];
        __nv_bfloat16 h = __float2bfloat16(v);
        __nv_bfloat16 l = __float2bfloat16(v - __bfloat162float(h));
        oH[(long long)(y2 + j) * DD + x2] = h;
        oL[(long long)(y2 + j) * DD + x2] = l;
    }
}

// ---------------------------------------------------------------------------
__device__ __forceinline__ unsigned cvta_s(const void* p) {
    return (unsigned)__cvta_generic_to_shared(p);
}
__device__ __forceinline__ void cpa16(unsigned s, const void* g) {
    asm volatile("cp.async.cg.shared.global [%0], [%1], 16;" :: "r"(s), "l"(g));
}
__device__ __forceinline__ void ldsm4(unsigned addr, unsigned* r) {
    asm volatile("ldmatrix.sync.aligned.m8n8.x4.shared.b16 {%0,%1,%2,%3},[%4];"
                 : "=r"(r[0]), "=r"(r[1]), "=r"(r[2]), "=r"(r[3]) : "r"(addr));
}
__device__ __forceinline__ void mma_bf16(float* c, const unsigned* a,
                                         unsigned b0, unsigned b1) {
    asm volatile(
        "mma.sync.aligned.m16n8k16.row.col.f32.bf16.bf16.f32 "
        "{%0,%1,%2,%3},{%4,%5,%6,%7},{%8,%9},{%0,%1,%2,%3};"
        : "+f"(c[0]), "+f"(c[1]), "+f"(c[2]), "+f"(c[3])
        : "r"(a[0]), "r"(a[1]), "r"(a[2]), "r"(a[3]), "r"(b0), "r"(b1));
}

// Inner MMA block, warp tile 64x64: 4 m16 frags x 2 n8 halves x 3 split = 24
// MMAs per np. Same-acc distance = 8 issues.
#define MMA_BLOCK(acc, ah, al, bh_cur, bl_cur)                                \
    {                                                                         \
        _Pragma("unroll")                                                     \
        for (int half = 0; half < 2; half++)                                  \
            _Pragma("unroll")                                                 \
            for (int mi = 0; mi < 4; mi++)                                    \
                mma_bf16(acc[mi][np * 2 + half], ah[mi],                      \
                         bh_cur[half * 2], bh_cur[half * 2 + 1]);             \
        _Pragma("unroll")                                                     \
        for (int half = 0; half < 2; half++)                                  \
            _Pragma("unroll")                                                 \
            for (int mi = 0; mi < 4; mi++)                                    \
                mma_bf16(acc[mi][np * 2 + half], al[mi],                      \
                         bh_cur[half * 2], bh_cur[half * 2 + 1]);             \
        _Pragma("unroll")                                                     \
        for (int half = 0; half < 2; half++)                                  \
            _Pragma("unroll")                                                 \
            for (int mi = 0; mi < 4; mi++)                                    \
                mma_bf16(acc[mi][np * 2 + half], ah[mi],                      \
                         bl_cur[half * 2], bl_cur[half * 2 + 1]);             \
    }

// Shared mainloop (256 threads load 128xBK A hi/lo + 256xBK B hi/lo) --------
#define GEMM_MAINLOOP(NCv, CH0v)                                              \
    auto load_stage = [&](int s, int k0) {                                    \
        unsigned sb = cvta_s(smem + s * STAGE);                               \
        int rr = tid >> 2, cc = tid & 3;                                      \
        _Pragma("unroll")                                                     \
        for (int i = 0; i < 2; i++) {                                         \
            int r = rr + 64 * i;                                              \
            long long go = (long long)r * K + k0 + 8 * cc;                    \
            unsigned so = (unsigned)(r * 80 + cc * 16);                       \
            cpa16(sb + so, AtH + go);                                         \
            cpa16(sb + ATILE + so, AtL + go);                                 \
        }                                                                     \
        _Pragma("unroll")                                                     \
        for (int i = 0; i < 4; i++) {                                         \
            int r = rr + 64 * i;                                              \
            long long go = (long long)r * K + k0 + 8 * cc;                    \
            unsigned so = (unsigned)(r * 80 + cc * 16);                       \
            cpa16(sb + 2 * ATILE + so, BtH + go);                             \
            cpa16(sb + 2 * ATILE + BTILE + so, BtL + go);                     \
        }                                                                     \
        asm volatile("cp.async.commit_group;");                               \
    };                                                                        \
    load_stage(0, (CH0v) * 32);                                               \
    if ((CH0v) + 1 < (NCv)) load_stage(1, ((CH0v) + 1) * 32);                 \
    else asm volatile("cp.async.commit_group;");                              \
    for (int ch = (CH0v); ch < (NCv); ch++) {                                 \
        const int s = (ch - (CH0v)) % NSTG;                                   \
        asm volatile("cp.async.wait_group 1;");                               \
        __syncthreads();                                                      \
        if (ch + 2 < (NCv))                                                   \
            load_stage((ch - (CH0v) + 2) % NSTG, (ch + 2) * 32);              \
        else                                                                  \
            asm volatile("cp.async.commit_group;");                           \
        const __nv_bfloat16* As_hi = (const __nv_bfloat16*)(smem + s * STAGE);            \
        const __nv_bfloat16* As_lo = (const __nv_bfloat16*)(smem + s * STAGE + ATILE);    \
        const __nv_bfloat16* Bs_hi = (const __nv_bfloat16*)(smem + s * STAGE + 2 * ATILE);\
        const __nv_bfloat16* Bs_lo = (const __nv_bfloat16*)(smem + s * STAGE + 2 * ATILE + BTILE);\
        const int g = lane >> 3;                                              \
        const int brow_base = n_off + ((g >> 1) << 3) + (lane & 7);           \
        _Pragma("unroll")                                                     \
        for (int ks = 0; ks < 2; ks++) {                                      \
            const int kel_b = ks * 16 + ((g & 1) << 3);                       \
            unsigned ah[4][4], al[4][4];                                      \
            _Pragma("unroll")                                                 \
            for (int mi = 0; mi < 4; mi++) {                                  \
                int rrow = m_off + mi * 16 + (lane & 15);                     \
                int kel  = ((lane >> 4) << 3) + ks * 16;                      \
                ldsm4(cvta_s(As_hi + rrow * SA + kel), ah[mi]);               \
                ldsm4(cvta_s(As_lo + rrow * SA + kel), al[mi]);               \
            }                                                                 \
            unsigned bh[2][4], bl[2][4];                                      \
            ldsm4(cvta_s(Bs_hi + brow_base * SA + kel_b), bh[0]);             \
            ldsm4(cvta_s(Bs_lo + brow_base * SA + kel_b), bl[0]);             \
            _Pragma("unroll")                                                 \
            for (int np = 0; np < 4; np++) {                                  \
                const int cur = np & 1, nxt = cur ^ 1;                        \
                if (np < 3) {                                                 \
                    ldsm4(cvta_s(Bs_hi + (brow_base + (np + 1) * 16) * SA + kel_b), bh[nxt]);\
                    ldsm4(cvta_s(Bs_lo + (brow_base + (np + 1) * 16) * SA + kel_b), bl[nxt]);\
                }                                                             \
                MMA_BLOCK(acc, ah, al, bh[cur], bl[cur])                      \
            }                                                                 \
        }                                                                     \
    }

// ---------------------------------------------------------------------------
// HMMA GEMM, TN: C[M,N] = A[M,K] @ B[N,K]^T. 128x256 tile, 256 threads,
// warp tile 64x64 (warps 2x4).
// EPI:  0 = +bias, 1 = +bias(+opt null)+relu, 2 = scale + anti-causal mask
// OUTM: 0 = fp32 C, 1 = bf16 hi/lo
// TRIM: 1 = start K loop at row0 (A cols exactly zero for k < row0)
template<int EPI, int OUTM, int TRIM>
__global__ __launch_bounds__(256, 1) void hmma_gemm(
    const __nv_bfloat16* __restrict__ Ahi, const __nv_bfloat16* __restrict__ Alo,
    const __nv_bfloat16* __restrict__ Bhi, const __nv_bfloat16* __restrict__ Blo,
    const float* __restrict__ bias, float* __restrict__ C,
    __nv_bfloat16* __restrict__ Chi, __nv_bfloat16* __restrict__ Clo,
    int M, int N, int K,
    long long sA, long long sB, long long sC, float scale)
{
    extern __shared__ __align__(128) char smem[];

    const long long zC = (long long)blockIdx.z * sC;
    const int tid  = threadIdx.x;
    const int lane = tid & 31;
    const int wid  = tid >> 5;
    const int row0 = blockIdx.y * 128;
    const int col0 = blockIdx.x * 256;
    const int m_off = (wid & 1) * 64;
    const int n_off = (wid >> 1) * 64;

    if (EPI == 2 && col0 + 256 <= row0) {
        #pragma unroll
        for (int mi = 0; mi < 4; mi++) {
            #pragma unroll
            for (int ni = 0; ni < 8; ni++) {
                int r_base = row0 + m_off + mi * 16 + (lane >> 2);
                int c      = col0 + n_off + ni * 8 + 2 * (lane & 3);
                #pragma unroll
                for (int hh = 0; hh < 2; hh++) {
                    long long off = zC + (long long)(r_base + hh * 8) * N + c;
                    *(float2*)(C + off) = make_float2(NEG_INF, NEG_INF);
                }
            }
        }
        return;
    }

    const long long zA = (long long)blockIdx.z * sA;
    const long long zB = (long long)blockIdx.z * sB;
    const __nv_bfloat16* AtH = Ahi + zA + (long long)row0 * K;
    const __nv_bfloat16* AtL = Alo + zA + (long long)row0 * K;
    const __nv_bfloat16* BtH = Bhi + zB + (long long)col0 * K;
    const __nv_bfloat16* BtL = Blo + zB + (long long)col0 * K;

    float acc[4][8][4];
    #pragma unroll
    for (int mi = 0; mi < 4; mi++)
        #pragma unroll
        for (int ni = 0; ni < 8; ni++)
            #pragma unroll
            for (int j = 0; j < 4; j++) acc[mi][ni][j] = 0.f;

    const int NC  = K / 32;
    const int ch0 = TRIM ? (row0 >> 5) : 0;

    GEMM_MAINLOOP(NC, ch0)

    const bool has_bias = (bias != nullptr);
    #pragma unroll
    for (int mi = 0; mi < 4; mi++) {
        #pragma unroll
        for (int ni = 0; ni < 8; ni++) {
            int r_base = row0 + m_off + mi * 16 + (lane >> 2);
            int c      = col0 + n_off + ni * 8 + 2 * (lane & 3);
            #pragma unroll
            for (int hh = 0; hh < 2; hh++) {
                int r = r_base + hh * 8;
                float v0 = acc[mi][ni][2 * hh];
                float v1 = acc[mi][ni][2 * hh + 1];
                if (EPI == 2) {
                    v0 *= scale; v1 *= scale;
                    if (c < r)     v0 = NEG_INF;
                    if (c + 1 < r) v1 = NEG_INF;
                } else {
                    if (has_bias) { v0 += bias[c]; v1 += bias[c + 1]; }
                    if (EPI == 1) { v0 = fmaxf(v0, 0.f); v1 = fmaxf(v1, 0.f); }
                }
                long long off = zC + (long long)r * N + c;
                if (OUTM == 0) {
                    *(float2*)(C + off) = make_float2(v0, v1);
                } else {
                    __nv_bfloat16 h2[2], l2[2];
                    h2[0] = __float2bfloat16(v0);
                    h2[1] = __float2bfloat16(v1);
                    l2[0] = __float2bfloat16(v0 - __bfloat162float(h2[0]));
                    l2[1] = __float2bfloat16(v1 - __bfloat162float(h2[1]));
                    *(unsigned*)(Chi + off) = *(unsigned*)h2;
                    *(unsigned*)(Clo + off) = *(unsigned*)l2;
                }
            }
        }
    }
}

// ---------------------------------------------------------------------------
// Fused QKV GEMM (128x256 tiles): cols [0,1024)->q, [1024,2048)->k, rest->v fp32.
__global__ __launch_bounds__(256, 1) void hmma_qkv(
    const __nv_bfloat16* __restrict__ Ahi, const __nv_bfloat16* __restrict__ Alo,
    const __nv_bfloat16* __restrict__ Bhi, const __nv_bfloat16* __restrict__ Blo,
    const float* __restrict__ bq, const float* __restrict__ bk,
    const float* __restrict__ bv,
    __nv_bfloat16* __restrict__ qH, __nv_bfloat16* __restrict__ qL,
    __nv_bfloat16* __restrict__ kH, __nv_bfloat16* __restrict__ kL,
    float* __restrict__ vO)
{
    extern __shared__ __align__(128) char smem[];
    const int K = DD;

    const int tid  = threadIdx.x;
    const int lane = tid & 31;
    const int wid  = tid >> 5;
    const int row0 = blockIdx.y * 128;
    const int col0 = blockIdx.x * 256;
    const int m_off = (wid & 1) * 64;
    const int n_off = (wid >> 1) * 64;

    const int sel = col0 >> 10;
    const int lc0 = col0 & 1023;

    const __nv_bfloat16* AtH = Ahi + (long long)row0 * K;
    const __nv_bfloat16* AtL = Alo + (long long)row0 * K;
    const __nv_bfloat16* BtH = Bhi + (long long)col0 * K;
    const __nv_bfloat16* BtL = Blo + (long long)col0 * K;

    float acc[4][8][4];
    #pragma unroll
    for (int mi = 0; mi < 4; mi++)
        #pragma unroll
        for (int ni = 0; ni < 8; ni++)
            #pragma unroll
            for (int j = 0; j < 4; j++) acc[mi][ni][j] = 0.f;

    const int NC = K / 32;
    GEMM_MAINLOOP(NC, 0)

    const float* bias = (sel == 0) ? bq : (sel == 1) ? bk : bv;
    __nv_bfloat16* Chi = (sel == 0) ? qH : kH;
    __nv_bfloat16* Clo = (sel == 0) ? qL : kL;

    #pragma unroll
    for (int mi = 0; mi < 4; mi++) {
        #pragma unroll
        for (int ni = 0; ni < 8; ni++) {
            int r_base = row0 + m_off + mi * 16 + (lane >> 2);
            int lc     = lc0 + n_off + ni * 8 + 2 * (lane & 3);
            #pragma unroll
            for (int hh = 0; hh < 2; hh++) {
                int r = r_base + hh * 8;
                float v0 = acc[mi][ni][2 * hh] + bias[lc];
                float v1 = acc[mi][ni][2 * hh + 1] + bias[lc + 1];
                long long off = (long long)r * DD + lc;
                if (sel == 2) {
                    *(float2*)(vO + off) = make_float2(v0, v1);
                } else {
                    __nv_bfloat16 h2[2], l2[2];
                    h2[0] = __float2bfloat16(v0);
                    h2[1] = __float2bfloat16(v1);
                    l2[0] = __float2bfloat16(v0 - __bfloat162float(h2[0]));
                    l2[1] = __float2bfloat16(v1 - __bfloat162float(h2[1]));
                    *(unsigned*)(Chi + off) = *(unsigned*)h2;
                    *(unsigned*)(Clo + off) = *(unsigned*)l2;
                }
            }
        }
    }
}

// ---------------------------------------------------------------------------
__global__ __launch_bounds__(256) void softmax_kernel(
    const float* __restrict__ sc,
    __nv_bfloat16* __restrict__ oH, __nv_bfloat16* __restrict__ oL)
{
    const float* p = sc + (long long)blockIdx.x * SS;
    __nv_bfloat16* pH = oH + (long long)blockIdx.x * SS;
    __nv_bfloat16* pL = oL + (long long)blockIdx.x * SS;
    const int t = threadIdx.x;
    const int lane = t & 31, warp = t >> 5;
    __shared__ float red[8];

    float v[8];
    float m = NEG_INF;
    #pragma unroll
    for (int i = 0; i < 8; i++) { v[i] = p[t + 256 * i]; m = fmaxf(m, v[i]); }
    #pragma unroll
    for (int o = 16; o > 0; o >>= 1) m = fmaxf(m, __shfl_xor_sync(0xffffffffu, m, o));
    if (lane == 0) red[warp] = m;
    __syncthreads();
    float mb = red[0];
    #pragma unroll
    for (int w = 1; w < 8; w++) mb = fmaxf(mb, red[w]);

    float s = 0.f;
    #pragma unroll
    for (int i = 0; i < 8; i++) { v[i] = __expf(v[i] - mb); s += v[i]; }
    #pragma unroll
    for (int o = 16; o > 0; o >>= 1) s += __shfl_xor_sync(0xffffffffu, s, o);
    __syncthreads();
    if (lane == 0) red[warp] = s;
    __syncthreads();
    float sb = 0.f;
    #pragma unroll
    for (int w = 0; w < 8; w++) sb += red[w];

    float inv = 1.f / sb;
    #pragma unroll
    for (int i = 0; i < 8; i++) {
        float x = v[i] * inv;
        __nv_bfloat16 h = __float2bfloat16(x);
        __nv_bfloat16 l = __float2bfloat16(x - __bfloat162float(h));
        pH[t + 256 * i] = h;
        pL[t + 256 * i] = l;
    }
}

// ---------------------------------------------------------------------------
extern "C" void kernel_launch(void* const* d_in, const int* in_sizes, int n_in,
                              void* d_out, int out_size)
{
    const void*  x    = d_in[0];
    const float* emb  = (const float*)d_in[1];
    const float* pos  = (const float*)d_in[2];
    const float* wq   = (const float*)d_in[3];
    const float* bq   = (const float*)d_in[4];
    const float* wk   = (const float*)d_in[5];
    const float* bk   = (const float*)d_in[6];
    const float* wv   = (const float*)d_in[7];
    const float* bv   = (const float*)d_in[8];
    const float* w1s  = (const float*)d_in[9];
    const float* b1s  = (const float*)d_in[10];
    const float* w2s  = (const float*)d_in[11];
    const float* b2s  = (const float*)d_in[12];
    float* out = (float*)d_out;

    cudaFuncSetAttribute(hmma_qkv,         cudaFuncAttributeMaxDynamicSharedMemorySize, SMEM_DYN);
    cudaFuncSetAttribute(hmma_gemm<2,0,0>, cudaFuncAttributeMaxDynamicSharedMemorySize, SMEM_DYN);
    cudaFuncSetAttribute(hmma_gemm<1,1,1>, cudaFuncAttributeMaxDynamicSharedMemorySize, SMEM_DYN);
    cudaFuncSetAttribute(hmma_gemm<1,1,0>, cudaFuncAttributeMaxDynamicSharedMemorySize, SMEM_DYN);
    cudaFuncSetAttribute(hmma_gemm<1,0,0>, cudaFuncAttributeMaxDynamicSharedMemorySize, SMEM_DYN);

    #define SYM(T, n) T* n; { void* p_; cudaGetSymbolAddress(&p_, g_##n); n = (T*)p_; }
    SYM(__nv_bfloat16, hH)  SYM(__nv_bfloat16, hL)
    SYM(__nv_bfloat16, qH)  SYM(__nv_bfloat16, qL)
    SYM(__nv_bfloat16, kH)  SYM(__nv_bfloat16, kL)
    SYM(__nv_bfloat16, vTH) SYM(__nv_bfloat16, vTL)
    SYM(__nv_bfloat16, scH) SYM(__nv_bfloat16, scL)
    SYM(__nv_bfloat16, midH) SYM(__nv_bfloat16, midL)
    SYM(__nv_bfloat16, wqkvH) SYM(__nv_bfloat16, wqkvL)
    SYM(__nv_bfloat16, w1H) SYM(__nv_bfloat16, w1L)
    SYM(__nv_bfloat16, w2H) SYM(__nv_bfloat16, w2L)
    SYM(float, v)  SYM(float, sc)
    #undef SYM

    dim3 tb(32, 8);
    detect_kernel<<<1, 256>>>(x);
    embed_kernel<<<ROWS, 256>>>(x, emb, pos, hH, hL);
    qkvw_transcvt_kernel<<<dim3(32, 32, 3), tb>>>(wq, wk, wv, wqkvH, wqkvL);
    transcvt_kernel<<<dim3(128, 32, LL), tb>>>(w1s, w1H, w1L, DD, MM,
        (long long)DD * MM, (long long)DD * MM);
    transcvt_kernel<<<dim3(32, 128, LL), tb>>>(w2s, w2H, w2L, MM, DD,
        (long long)MM * DD, (long long)MM * DD);

    // Fused QKV: grid (12,64) = 768 CTAs
    hmma_qkv<<<dim3(12, 64, 1), 256, SMEM_DYN>>>(hH, hL, wqkvH, wqkvL,
        bq, bk, bv, qH, qL, kH, kL, v);

    // scores = q @ k^T / 32, anti-causal mask; fully-masked tiles early-exit
    hmma_gemm<2,0,0><<<dim3(8, 16, BB), 256, SMEM_DYN>>>(qH, qL, kH, kL, nullptr,
        sc, nullptr, nullptr, SS, SS, DD,
        (long long)SS * DD, (long long)SS * DD, (long long)SS * SS, 0.03125f);

    transcvt_kernel<<<dim3(32, 64, BB), tb>>>(v, vTH, vTL, SS, DD,
        (long long)SS * DD, (long long)DD * SS);

    softmax_kernel<<<ROWS, 256>>>(sc, scH, scL);

    // h = relu(attn @ v): attn rows exactly 0 for k < row0 -> TRIM=1
    hmma_gemm<1,1,1><<<dim3(4, 16, BB), 256, SMEM_DYN>>>(scH, scL, vTH, vTL, nullptr,
        nullptr, hH, hL, SS, DD, SS,
        (long long)SS * SS, (long long)DD * SS, (long long)SS * DD, 0.f);

    // FFN stack
    for (int l = 0; l < LL; l++) {
        hmma_gemm<1,1,0><<<dim3(16, 64, 1), 256, SMEM_DYN>>>(
            hH, hL, w1H + (long long)l * DD * MM, w1L + (long long)l * DD * MM,
            b1s + (long long)l * MM, nullptr, midH, midL,
            ROWS, MM, DD, 0, 0, 0, 0.f);
        if (l == LL - 1) {
            hmma_gemm<1,0,0><<<dim3(4, 64, 1), 256, SMEM_DYN>>>(
                midH, midL, w2H + (long long)l * MM * DD, w2L + (long long)l * MM * DD,
                b2s + (long long)l * DD, out, nullptr, nullptr,
                ROWS, DD, MM, 0, 0, 0, 0.f);
        } else {
            hmma_gemm<1,1,0><<<dim3(4, 64, 1), 256, SMEM_DYN>>>(
                midH, midL, w2H + (long long)l * MM * DD, w2L + (long long)l * MM * DD,
                b2s + (long long)l * DD, nullptr, hH, hL,
                ROWS, DD, MM, 0, 0, 0, 0.f);
        }
    }
}

// round 10
// speedup vs baseline: 3.8467x; 1.3498x over previous
#include <cuda_runtime.h>
#include <cuda_fp16.h>
#include <cstdint>

// Problem constants
#define BB 4
#define SS 2048
#define DD 1024
#define MM 4096
#define LL 4
#define ROWS (BB*SS)          // 8192
#define NEG_INF __int_as_float(0xff800000)

// GEMM tiling: 128x256 block tile, BK=32, 256 threads (8 warps 2x4, warp 64x64)
// fp16 2-MMA split: A hi-only, B hi+lo.
#define SA 40                 // smem row stride (fp16) = 80B, conflict-free
#define ATILE 10240           // 128*SA*2
#define BTILE 20480           // 256*SA*2
#define STAGE (ATILE + 2*BTILE)     // 51200
#define NSTG 3
#define SMEM_DYN (NSTG*STAGE)       // 153600

// ---------------- scratch (device globals; no allocation allowed) ----------
__device__ __half g_hH[ROWS*DD];
__device__ __half g_qH[ROWS*DD];
__device__ __half g_kH[ROWS*DD],  g_kL[ROWS*DD];
__device__ __half g_vTH[ROWS*DD], g_vTL[ROWS*DD];
__device__ __half g_scH[BB*SS*SS];
__device__ __half g_midH[(long long)ROWS*MM];
__device__ __half g_wqkvH[3*DD*DD], g_wqkvL[3*DD*DD];
__device__ __half g_w1H[LL*DD*MM], g_w1L[LL*DD*MM];
__device__ __half g_w2H[LL*DD*MM], g_w2L[LL*DD*MM];
__device__ float g_v[ROWS*DD];
__device__ float g_sc[BB*SS*SS];
__device__ int   g_is32;

// ---------------------------------------------------------------------------
__global__ void detect_kernel(const void* __restrict__ x) {
    const long long* p = (const long long*)x;
    int bad = 0;
    for (int i = threadIdx.x; i < 4096; i += 256) {
        long long v = p[i];
        if (v < 0 || v >= 32000) bad = 1;
    }
    bad = __syncthreads_or(bad);
    if (threadIdx.x == 0) g_is32 = bad;
}

// h = emb[x] + pos -> fp16 (hi only; h is always an A operand)
__global__ __launch_bounds__(256) void embed_kernel(
    const void* __restrict__ x, const float* __restrict__ emb,
    const float* __restrict__ pos, __half* __restrict__ hH)
{
    int row = blockIdx.x;
    int s = row & (SS - 1);
    long long tok;
    if (g_is32) tok = ((const int*)x)[row];
    else        tok = ((const long long*)x)[row];
    int t = threadIdx.x;
    float4 a = ((const float4*)(emb + tok * (long long)DD))[t];
    float4 b = ((const float4*)(pos + (long long)s * DD))[t];
    __half h4[4];
    h4[0] = __float2half_rn(a.x + b.x);
    h4[1] = __float2half_rn(a.y + b.y);
    h4[2] = __float2half_rn(a.z + b.z);
    h4[3] = __float2half_rn(a.w + b.w);
    *(uint2*)(hH + (long long)row * DD + 4 * t) = *(uint2*)h4;
}

// ---------------------------------------------------------------------------
// Transpose + split: fp32 [R,C] row-major -> fp16 hi/lo [C,R].
__global__ __launch_bounds__(256) void transcvt_kernel(
    const float* __restrict__ in,
    __half* __restrict__ oH, __half* __restrict__ oL,
    int R, int C, long long si, long long so)
{
    __shared__ float t[32][33];
    in += (long long)blockIdx.z * si;
    oH += (long long)blockIdx.z * so;
    oL += (long long)blockIdx.z * so;
    int x  = blockIdx.x * 32 + threadIdx.x;
    int y0 = blockIdx.y * 32 + threadIdx.y;
    #pragma unroll
    for (int j = 0; j < 32; j += 8)
        t[threadIdx.y + j][threadIdx.x] = in[(long long)(y0 + j) * C + x];
    __syncthreads();
    int x2 = blockIdx.y * 32 + threadIdx.x;
    int y2 = blockIdx.x * 32 + threadIdx.y;
    #pragma unroll
    for (int j = 0; j < 32; j += 8) {
        float v = t[threadIdx.x][threadIdx.y + j];
        __half h = __float2half_rn(v);
        __half l = __float2half_rn(v - __half2float(h));
        oH[(long long)(y2 + j) * R + x2] = h;
        oL[(long long)(y2 + j) * R + x2] = l;
    }
}

// QKV weight transpose+split in ONE launch (z selects wq/wk/wv).
__global__ __launch_bounds__(256) void qkvw_transcvt_kernel(
    const float* __restrict__ wq, const float* __restrict__ wk,
    const float* __restrict__ wv,
    __half* __restrict__ oH, __half* __restrict__ oL)
{
    __shared__ float t[32][33];
    const float* in = (blockIdx.z == 0) ? wq : (blockIdx.z == 1) ? wk : wv;
    oH += (long long)blockIdx.z * DD * DD;
    oL += (long long)blockIdx.z * DD * DD;
    int x  = blockIdx.x * 32 + threadIdx.x;
    int y0 = blockIdx.y * 32 + threadIdx.y;
    #pragma unroll
    for (int j = 0; j < 32; j += 8)
        t[threadIdx.y + j][threadIdx.x] = in[(long long)(y0 + j) * DD + x];
    __syncthreads();
    int x2 = blockIdx.y * 32 + threadIdx.x;
    int y2 = blockIdx.x * 32 + threadIdx.y;
    #pragma unroll
    for (int j = 0; j < 32; j += 8) {
        float v = t[threadIdx.x][threadIdx.y + j];
        __half h = __float2half_rn(v);
        __half l = __float2half_rn(v - __half2float(h));
        oH[(long long)(y2 + j) * DD + x2] = h;
        oL[(long long)(y2 + j) * DD + x2] = l;
    }
}

// ---------------------------------------------------------------------------
__device__ __forceinline__ unsigned cvta_s(const void* p) {
    return (unsigned)__cvta_generic_to_shared(p);
}
__device__ __forceinline__ void cpa16(unsigned s, const void* g) {
    asm volatile("cp.async.cg.shared.global [%0], [%1], 16;" :: "r"(s), "l"(g));
}
__device__ __forceinline__ void ldsm4(unsigned addr, unsigned* r) {
    asm volatile("ldmatrix.sync.aligned.m8n8.x4.shared.b16 {%0,%1,%2,%3},[%4];"
                 : "=r"(r[0]), "=r"(r[1]), "=r"(r[2]), "=r"(r[3]) : "r"(addr));
}
__device__ __forceinline__ void mma_f16(float* c, const unsigned* a,
                                        unsigned b0, unsigned b1) {
    asm volatile(
        "mma.sync.aligned.m16n8k16.row.col.f32.f16.f16.f32 "
        "{%0,%1,%2,%3},{%4,%5,%6,%7},{%8,%9},{%0,%1,%2,%3};"
        : "+f"(c[0]), "+f"(c[1]), "+f"(c[2]), "+f"(c[3])
        : "r"(a[0]), "r"(a[1]), "r"(a[2]), "r"(a[3]), "r"(b0), "r"(b1));
}

// Inner MMA block: 2-term split (ah*bh + ah*bl). Same-acc distance = 8.
#define MMA_BLOCK(acc, ah, bh_cur, bl_cur)                                    \
    {                                                                         \
        _Pragma("unroll")                                                     \
        for (int half = 0; half < 2; half++)                                  \
            _Pragma("unroll")                                                 \
            for (int mi = 0; mi < 4; mi++)                                    \
                mma_f16(acc[mi][np * 2 + half], ah[mi],                       \
                        bh_cur[half * 2], bh_cur[half * 2 + 1]);              \
        _Pragma("unroll")                                                     \
        for (int half = 0; half < 2; half++)                                  \
            _Pragma("unroll")                                                 \
            for (int mi = 0; mi < 4; mi++)                                    \
                mma_f16(acc[mi][np * 2 + half], ah[mi],                       \
                        bl_cur[half * 2], bl_cur[half * 2 + 1]);              \
    }

// Shared mainloop (256 threads load 128xBK A-hi + 256xBK B hi/lo) -----------
#define GEMM_MAINLOOP(NCv, CH0v)                                              \
    auto load_stage = [&](int s, int k0) {                                    \
        unsigned sb = cvta_s(smem + s * STAGE);                               \
        int rr = tid >> 2, cc = tid & 3;                                      \
        _Pragma("unroll")                                                     \
        for (int i = 0; i < 2; i++) {                                         \
            int r = rr + 64 * i;                                              \
            long long go = (long long)r * K + k0 + 8 * cc;                    \
            unsigned so = (unsigned)(r * 80 + cc * 16);                       \
            cpa16(sb + so, AtH + go);                                         \
        }                                                                     \
        _Pragma("unroll")                                                     \
        for (int i = 0; i < 4; i++) {                                         \
            int r = rr + 64 * i;                                              \
            long long go = (long long)r * K + k0 + 8 * cc;                    \
            unsigned so = (unsigned)(r * 80 + cc * 16);                       \
            cpa16(sb + ATILE + so, BtH + go);                                 \
            cpa16(sb + ATILE + BTILE + so, BtL + go);                         \
        }                                                                     \
        asm volatile("cp.async.commit_group;");                               \
    };                                                                        \
    load_stage(0, (CH0v) * 32);                                               \
    if ((CH0v) + 1 < (NCv)) load_stage(1, ((CH0v) + 1) * 32);                 \
    else asm volatile("cp.async.commit_group;");                              \
    for (int ch = (CH0v); ch < (NCv); ch++) {                                 \
        const int s = (ch - (CH0v)) % NSTG;                                   \
        asm volatile("cp.async.wait_group 1;");                               \
        __syncthreads();                                                      \
        if (ch + 2 < (NCv))                                                   \
            load_stage((ch - (CH0v) + 2) % NSTG, (ch + 2) * 32);              \
        else                                                                  \
            asm volatile("cp.async.commit_group;");                           \
        const __half* As_hi = (const __half*)(smem + s * STAGE);              \
        const __half* Bs_hi = (const __half*)(smem + s * STAGE + ATILE);      \
        const __half* Bs_lo = (const __half*)(smem + s * STAGE + ATILE + BTILE);\
        const int g = lane >> 3;                                              \
        const int brow_base = n_off + ((g >> 1) << 3) + (lane & 7);           \
        _Pragma("unroll")                                                     \
        for (int ks = 0; ks < 2; ks++) {                                      \
            const int kel_b = ks * 16 + ((g & 1) << 3);                       \
            unsigned ah[4][4];                                                \
            _Pragma("unroll")                                                 \
            for (int mi = 0; mi < 4; mi++) {                                  \
                int rrow = m_off + mi * 16 + (lane & 15);                     \
                int kel  = ((lane >> 4) << 3) + ks * 16;                      \
                ldsm4(cvta_s(As_hi + rrow * SA + kel), ah[mi]);               \
            }                                                                 \
            unsigned bh[2][4], bl[2][4];                                      \
            ldsm4(cvta_s(Bs_hi + brow_base * SA + kel_b), bh[0]);             \
            ldsm4(cvta_s(Bs_lo + brow_base * SA + kel_b), bl[0]);             \
            _Pragma("unroll")                                                 \
            for (int np = 0; np < 4; np++) {                                  \
                const int cur = np & 1, nxt = cur ^ 1;                        \
                if (np < 3) {                                                 \
                    ldsm4(cvta_s(Bs_hi + (brow_base + (np + 1) * 16) * SA + kel_b), bh[nxt]);\
                    ldsm4(cvta_s(Bs_lo + (brow_base + (np + 1) * 16) * SA + kel_b), bl[nxt]);\
                }                                                             \
                MMA_BLOCK(acc, ah, bh[cur], bl[cur])                          \
            }                                                                 \
        }                                                                     \
    }

// ---------------------------------------------------------------------------
// HMMA GEMM, TN: C[M,N] = A[M,K] @ B[N,K]^T. 128x256 tile, 256 threads,
// warp tile 64x64. A fp16 (hi only), B fp16 hi+lo.
// EPI:  0 = +bias, 1 = +bias(+opt null)+relu, 2 = scale + anti-causal mask
// OUTM: 0 = fp32 C, 1 = fp16 hi-only (Chi)
// TRIM: 1 = start K loop at row0 (A cols exactly zero for k < row0)
template<int EPI, int OUTM, int TRIM>
__global__ __launch_bounds__(256, 1) void hmma_gemm(
    const __half* __restrict__ Ahi,
    const __half* __restrict__ Bhi, const __half* __restrict__ Blo,
    const float* __restrict__ bias, float* __restrict__ C,
    __half* __restrict__ Chi,
    int M, int N, int K,
    long long sA, long long sB, long long sC, float scale)
{
    extern __shared__ __align__(128) char smem[];

    const long long zC = (long long)blockIdx.z * sC;
    const int tid  = threadIdx.x;
    const int lane = tid & 31;
    const int wid  = tid >> 5;
    const int row0 = blockIdx.y * 128;
    const int col0 = blockIdx.x * 256;
    const int m_off = (wid & 1) * 64;
    const int n_off = (wid >> 1) * 64;

    if (EPI == 2 && col0 + 256 <= row0) {
        #pragma unroll
        for (int mi = 0; mi < 4; mi++) {
            #pragma unroll
            for (int ni = 0; ni < 8; ni++) {
                int r_base = row0 + m_off + mi * 16 + (lane >> 2);
                int c      = col0 + n_off + ni * 8 + 2 * (lane & 3);
                #pragma unroll
                for (int hh = 0; hh < 2; hh++) {
                    long long off = zC + (long long)(r_base + hh * 8) * N + c;
                    *(float2*)(C + off) = make_float2(NEG_INF, NEG_INF);
                }
            }
        }
        return;
    }

    const long long zA = (long long)blockIdx.z * sA;
    const long long zB = (long long)blockIdx.z * sB;
    const __half* AtH = Ahi + zA + (long long)row0 * K;
    const __half* BtH = Bhi + zB + (long long)col0 * K;
    const __half* BtL = Blo + zB + (long long)col0 * K;

    float acc[4][8][4];
    #pragma unroll
    for (int mi = 0; mi < 4; mi++)
        #pragma unroll
        for (int ni = 0; ni < 8; ni++)
            #pragma unroll
            for (int j = 0; j < 4; j++) acc[mi][ni][j] = 0.f;

    const int NC  = K / 32;
    const int ch0 = TRIM ? (row0 >> 5) : 0;

    GEMM_MAINLOOP(NC, ch0)

    const bool has_bias = (bias != nullptr);
    #pragma unroll
    for (int mi = 0; mi < 4; mi++) {
        #pragma unroll
        for (int ni = 0; ni < 8; ni++) {
            int r_base = row0 + m_off + mi * 16 + (lane >> 2);
            int c      = col0 + n_off + ni * 8 + 2 * (lane & 3);
            #pragma unroll
            for (int hh = 0; hh < 2; hh++) {
                int r = r_base + hh * 8;
                float v0 = acc[mi][ni][2 * hh];
                float v1 = acc[mi][ni][2 * hh + 1];
                if (EPI == 2) {
                    v0 *= scale; v1 *= scale;
                    if (c < r)     v0 = NEG_INF;
                    if (c + 1 < r) v1 = NEG_INF;
                } else {
                    if (has_bias) { v0 += bias[c]; v1 += bias[c + 1]; }
                    if (EPI == 1) { v0 = fmaxf(v0, 0.f); v1 = fmaxf(v1, 0.f); }
                }
                long long off = zC + (long long)r * N + c;
                if (OUTM == 0) {
                    *(float2*)(C + off) = make_float2(v0, v1);
                } else {
                    __half h2[2];
                    h2[0] = __float2half_rn(v0);
                    h2[1] = __float2half_rn(v1);
                    *(unsigned*)(Chi + off) = *(unsigned*)h2;
                }
            }
        }
    }
}

// ---------------------------------------------------------------------------
// Fused QKV GEMM: cols [0,1024)->q fp16-hi, [1024,2048)->k fp16 hi+lo,
// [2048,3072)->v fp32.
__global__ __launch_bounds__(256, 1) void hmma_qkv(
    const __half* __restrict__ Ahi,
    const __half* __restrict__ Bhi, const __half* __restrict__ Blo,
    const float* __restrict__ bq, const float* __restrict__ bk,
    const float* __restrict__ bv,
    __half* __restrict__ qH,
    __half* __restrict__ kH, __half* __restrict__ kL,
    float* __restrict__ vO)
{
    extern __shared__ __align__(128) char smem[];
    const int K = DD;

    const int tid  = threadIdx.x;
    const int lane = tid & 31;
    const int wid  = tid >> 5;
    const int row0 = blockIdx.y * 128;
    const int col0 = blockIdx.x * 256;
    const int m_off = (wid & 1) * 64;
    const int n_off = (wid >> 1) * 64;

    const int sel = col0 >> 10;
    const int lc0 = col0 & 1023;

    const __half* AtH = Ahi + (long long)row0 * K;
    const __half* BtH = Bhi + (long long)col0 * K;
    const __half* BtL = Blo + (long long)col0 * K;

    float acc[4][8][4];
    #pragma unroll
    for (int mi = 0; mi < 4; mi++)
        #pragma unroll
        for (int ni = 0; ni < 8; ni++)
            #pragma unroll
            for (int j = 0; j < 4; j++) acc[mi][ni][j] = 0.f;

    const int NC = K / 32;
    GEMM_MAINLOOP(NC, 0)

    const float* bias = (sel == 0) ? bq : (sel == 1) ? bk : bv;

    #pragma unroll
    for (int mi = 0; mi < 4; mi++) {
        #pragma unroll
        for (int ni = 0; ni < 8; ni++) {
            int r_base = row0 + m_off + mi * 16 + (lane >> 2);
            int lc     = lc0 + n_off + ni * 8 + 2 * (lane & 3);
            #pragma unroll
            for (int hh = 0; hh < 2; hh++) {
                int r = r_base + hh * 8;
                float v0 = acc[mi][ni][2 * hh] + bias[lc];
                float v1 = acc[mi][ni][2 * hh + 1] + bias[lc + 1];
                long long off = (long long)r * DD + lc;
                if (sel == 2) {
                    *(float2*)(vO + off) = make_float2(v0, v1);
                } else if (sel == 0) {
                    __half h2[2];
                    h2[0] = __float2half_rn(v0);
                    h2[1] = __float2half_rn(v1);
                    *(unsigned*)(qH + off) = *(unsigned*)h2;
                } else {
                    __half h2[2], l2[2];
                    h2[0] = __float2half_rn(v0);
                    h2[1] = __float2half_rn(v1);
                    l2[0] = __float2half_rn(v0 - __half2float(h2[0]));
                    l2[1] = __float2half_rn(v1 - __half2float(h2[1]));
                    *(unsigned*)(kH + off) = *(unsigned*)h2;
                    *(unsigned*)(kL + off) = *(unsigned*)l2;
                }
            }
        }
    }
}

// ---------------------------------------------------------------------------
__global__ __launch_bounds__(256) void softmax_kernel(
    const float* __restrict__ sc, __half* __restrict__ oH)
{
    const float* p = sc + (long long)blockIdx.x * SS;
    __half* pH = oH + (long long)blockIdx.x * SS;
    const int t = threadIdx.x;
    const int lane = t & 31, warp = t >> 5;
    __shared__ float red[8];

    float v[8];
    float m = NEG_INF;
    #pragma unroll
    for (int i = 0; i < 8; i++) { v[i] = p[t + 256 * i]; m = fmaxf(m, v[i]); }
    #pragma unroll
    for (int o = 16; o > 0; o >>= 1) m = fmaxf(m, __shfl_xor_sync(0xffffffffu, m, o));
    if (lane == 0) red[warp] = m;
    __syncthreads();
    float mb = red[0];
    #pragma unroll
    for (int w = 1; w < 8; w++) mb = fmaxf(mb, red[w]);

    float s = 0.f;
    #pragma unroll
    for (int i = 0; i < 8; i++) { v[i] = __expf(v[i] - mb); s += v[i]; }
    #pragma unroll
    for (int o = 16; o > 0; o >>= 1) s += __shfl_xor_sync(0xffffffffu, s, o);
    __syncthreads();
    if (lane == 0) red[warp] = s;
    __syncthreads();
    float sb = 0.f;
    #pragma unroll
    for (int w = 0; w < 8; w++) sb += red[w];

    float inv = 1.f / sb;
    #pragma unroll
    for (int i = 0; i < 8; i++)
        pH[t + 256 * i] = __float2half_rn(v[i] * inv);
}

// ---------------------------------------------------------------------------
extern "C" void kernel_launch(void* const* d_in, const int* in_sizes, int n_in,
                              void* d_out, int out_size)
{
    const void*  x    = d_in[0];
    const float* emb  = (const float*)d_in[1];
    const float* pos  = (const float*)d_in[2];
    const float* wq   = (const float*)d_in[3];
    const float* bq   = (const float*)d_in[4];
    const float* wk   = (const float*)d_in[5];
    const float* bk   = (const float*)d_in[6];
    const float* wv   = (const float*)d_in[7];
    const float* bv   = (const float*)d_in[8];
    const float* w1s  = (const float*)d_in[9];
    const float* b1s  = (const float*)d_in[10];
    const float* w2s  = (const float*)d_in[11];
    const float* b2s  = (const float*)d_in[12];
    float* out = (float*)d_out;

    cudaFuncSetAttribute(hmma_qkv,         cudaFuncAttributeMaxDynamicSharedMemorySize, SMEM_DYN);
    cudaFuncSetAttribute(hmma_gemm<2,0,0>, cudaFuncAttributeMaxDynamicSharedMemorySize, SMEM_DYN);
    cudaFuncSetAttribute(hmma_gemm<1,1,1>, cudaFuncAttributeMaxDynamicSharedMemorySize, SMEM_DYN);
    cudaFuncSetAttribute(hmma_gemm<1,1,0>, cudaFuncAttributeMaxDynamicSharedMemorySize, SMEM_DYN);
    cudaFuncSetAttribute(hmma_gemm<1,0,0>, cudaFuncAttributeMaxDynamicSharedMemorySize, SMEM_DYN);

    #define SYM(T, n) T* n; { void* p_; cudaGetSymbolAddress(&p_, g_##n); n = (T*)p_; }
    SYM(__half, hH)
    SYM(__half, qH)
    SYM(__half, kH)   SYM(__half, kL)
    SYM(__half, vTH)  SYM(__half, vTL)
    SYM(__half, scH)
    SYM(__half, midH)
    SYM(__half, wqkvH) SYM(__half, wqkvL)
    SYM(__half, w1H)  SYM(__half, w1L)
    SYM(__half, w2H)  SYM(__half, w2L)
    SYM(float, v)  SYM(float, sc)
    #undef SYM

    dim3 tb(32, 8);
    detect_kernel<<<1, 256>>>(x);
    embed_kernel<<<ROWS, 256>>>(x, emb, pos, hH);
    qkvw_transcvt_kernel<<<dim3(32, 32, 3), tb>>>(wq, wk, wv, wqkvH, wqkvL);
    transcvt_kernel<<<dim3(128, 32, LL), tb>>>(w1s, w1H, w1L, DD, MM,
        (long long)DD * MM, (long long)DD * MM);
    transcvt_kernel<<<dim3(32, 128, LL), tb>>>(w2s, w2H, w2L, MM, DD,
        (long long)MM * DD, (long long)MM * DD);

    // Fused QKV: grid (12,64) = 768 CTAs
    hmma_qkv<<<dim3(12, 64, 1), 256, SMEM_DYN>>>(hH, wqkvH, wqkvL,
        bq, bk, bv, qH, kH, kL, v);

    // scores = q @ k^T / 32, anti-causal mask; fully-masked tiles early-exit
    hmma_gemm<2,0,0><<<dim3(8, 16, BB), 256, SMEM_DYN>>>(qH, kH, kL, nullptr,
        sc, nullptr, SS, SS, DD,
        (long long)SS * DD, (long long)SS * DD, (long long)SS * SS, 0.03125f);

    transcvt_kernel<<<dim3(32, 64, BB), tb>>>(v, vTH, vTL, SS, DD,
        (long long)SS * DD, (long long)DD * SS);

    softmax_kernel<<<ROWS, 256>>>(sc, scH);

    // h = relu(attn @ v): attn rows exactly 0 for k < row0 -> TRIM=1
    hmma_gemm<1,1,1><<<dim3(4, 16, BB), 256, SMEM_DYN>>>(scH, vTH, vTL, nullptr,
        nullptr, hH, SS, DD, SS,
        (long long)SS * SS, (long long)DD * SS, (long long)SS * DD, 0.f);

    // FFN stack
    for (int l = 0; l < LL; l++) {
        hmma_gemm<1,1,0><<<dim3(16, 64, 1), 256, SMEM_DYN>>>(
            hH, w1H + (long long)l * DD * MM, w1L + (long long)l * DD * MM,
            b1s + (long long)l * MM, nullptr, midH,
            ROWS, MM, DD, 0, 0, 0, 0.f);
        if (l == LL - 1) {
            hmma_gemm<1,0,0><<<dim3(4, 64, 1), 256, SMEM_DYN>>>(
                midH, w2H + (long long)l * MM * DD, w2L + (long long)l * MM * DD,
                b2s + (long long)l * DD, out, nullptr,
                ROWS, DD, MM, 0, 0, 0, 0.f);
        } else {
            hmma_gemm<1,1,0><<<dim3(4, 64, 1), 256, SMEM_DYN>>>(
                midH, w2H + (long long)l * MM * DD, w2L + (long long)l * MM * DD,
                b2s + (long long)l * DD, nullptr, hH,
                ROWS, DD, MM, 0, 0, 0, 0.f);
        }
    }
}

// round 11
// speedup vs baseline: 4.5935x; 1.1941x over previous
#include <cuda_runtime.h>
#include <cuda_fp16.h>
#include <cstdint>

// Problem constants
#define BB 4
#define SS 2048
#define DD 1024
#define MM 4096
#define LL 4
#define ROWS (BB*SS)          // 8192
#define NEG_INF __int_as_float(0xff800000)

// GEMM tiling: 128x256 block tile, BK=32, 256 threads (8 warps 2x4, warp 64x64)
// fp16 split: A hi-only, B hi(+optional lo, template BLO).
#define SA 40                 // smem row stride (fp16) = 80B, conflict-free
#define ATILE 10240           // 128*SA*2
#define BTILE 20480           // 256*SA*2
#define STAGE (ATILE + 2*BTILE)     // 51200
#define NSTG 3
#define SMEM_DYN (NSTG*STAGE)       // 153600

// ---------------- scratch (device globals; no allocation allowed) ----------
__device__ __half g_hH[ROWS*DD];
__device__ __half g_qH[ROWS*DD];
__device__ __half g_kH[ROWS*DD],  g_kL[ROWS*DD];
__device__ __half g_vTH[ROWS*DD], g_vTL[ROWS*DD];
__device__ __half g_scH[BB*SS*SS];
__device__ __half g_midH[(long long)ROWS*MM];
__device__ __half g_wqkvH[3*DD*DD], g_wqkvL[3*DD*DD];
__device__ __half g_w1H[LL*DD*MM];                 // FFN1 weights: hi only (1-MMA)
__device__ __half g_w2H[LL*DD*MM], g_w2L[LL*DD*MM];
__device__ float g_v[ROWS*DD];
__device__ float g_sc[BB*SS*SS];
__device__ int   g_is32;

// ---------------------------------------------------------------------------
__global__ void detect_kernel(const void* __restrict__ x) {
    const long long* p = (const long long*)x;
    int bad = 0;
    for (int i = threadIdx.x; i < 4096; i += 256) {
        long long v = p[i];
        if (v < 0 || v >= 32000) bad = 1;
    }
    bad = __syncthreads_or(bad);
    if (threadIdx.x == 0) g_is32 = bad;
}

// h = emb[x] + pos -> fp16 (hi only; h is always an A operand)
__global__ __launch_bounds__(256) void embed_kernel(
    const void* __restrict__ x, const float* __restrict__ emb,
    const float* __restrict__ pos, __half* __restrict__ hH)
{
    int row = blockIdx.x;
    int s = row & (SS - 1);
    long long tok;
    if (g_is32) tok = ((const int*)x)[row];
    else        tok = ((const long long*)x)[row];
    int t = threadIdx.x;
    float4 a = ((const float4*)(emb + tok * (long long)DD))[t];
    float4 b = ((const float4*)(pos + (long long)s * DD))[t];
    __half h4[4];
    h4[0] = __float2half_rn(a.x + b.x);
    h4[1] = __float2half_rn(a.y + b.y);
    h4[2] = __float2half_rn(a.z + b.z);
    h4[3] = __float2half_rn(a.w + b.w);
    *(uint2*)(hH + (long long)row * DD + 4 * t) = *(uint2*)h4;
}

// ---------------------------------------------------------------------------
// Transpose + split: fp32 [R,C] row-major -> fp16 hi (+lo if wlo) [C,R].
__global__ __launch_bounds__(256) void transcvt_kernel(
    const float* __restrict__ in,
    __half* __restrict__ oH, __half* __restrict__ oL,
    int R, int C, long long si, long long so, int wlo)
{
    __shared__ float t[32][33];
    in += (long long)blockIdx.z * si;
    oH += (long long)blockIdx.z * so;
    oL += (long long)blockIdx.z * so;
    int x  = blockIdx.x * 32 + threadIdx.x;
    int y0 = blockIdx.y * 32 + threadIdx.y;
    #pragma unroll
    for (int j = 0; j < 32; j += 8)
        t[threadIdx.y + j][threadIdx.x] = in[(long long)(y0 + j) * C + x];
    __syncthreads();
    int x2 = blockIdx.y * 32 + threadIdx.x;
    int y2 = blockIdx.x * 32 + threadIdx.y;
    #pragma unroll
    for (int j = 0; j < 32; j += 8) {
        float v = t[threadIdx.x][threadIdx.y + j];
        __half h = __float2half_rn(v);
        oH[(long long)(y2 + j) * R + x2] = h;
        if (wlo) {
            __half l = __float2half_rn(v - __half2float(h));
            oL[(long long)(y2 + j) * R + x2] = l;
        }
    }
}

// QKV weight transpose+split in ONE launch (z selects wq/wk/wv).
__global__ __launch_bounds__(256) void qkvw_transcvt_kernel(
    const float* __restrict__ wq, const float* __restrict__ wk,
    const float* __restrict__ wv,
    __half* __restrict__ oH, __half* __restrict__ oL)
{
    __shared__ float t[32][33];
    const float* in = (blockIdx.z == 0) ? wq : (blockIdx.z == 1) ? wk : wv;
    oH += (long long)blockIdx.z * DD * DD;
    oL += (long long)blockIdx.z * DD * DD;
    int x  = blockIdx.x * 32 + threadIdx.x;
    int y0 = blockIdx.y * 32 + threadIdx.y;
    #pragma unroll
    for (int j = 0; j < 32; j += 8)
        t[threadIdx.y + j][threadIdx.x] = in[(long long)(y0 + j) * DD + x];
    __syncthreads();
    int x2 = blockIdx.y * 32 + threadIdx.x;
    int y2 = blockIdx.x * 32 + threadIdx.y;
    #pragma unroll
    for (int j = 0; j < 32; j += 8) {
        float v = t[threadIdx.x][threadIdx.y + j];
        __half h = __float2half_rn(v);
        __half l = __float2half_rn(v - __half2float(h));
        oH[(long long)(y2 + j) * DD + x2] = h;
        oL[(long long)(y2 + j) * DD + x2] = l;
    }
}

// ---------------------------------------------------------------------------
__device__ __forceinline__ unsigned cvta_s(const void* p) {
    return (unsigned)__cvta_generic_to_shared(p);
}
__device__ __forceinline__ void cpa16(unsigned s, const void* g) {
    asm volatile("cp.async.cg.shared.global [%0], [%1], 16;" :: "r"(s), "l"(g));
}
__device__ __forceinline__ void ldsm4(unsigned addr, unsigned* r) {
    asm volatile("ldmatrix.sync.aligned.m8n8.x4.shared.b16 {%0,%1,%2,%3},[%4];"
                 : "=r"(r[0]), "=r"(r[1]), "=r"(r[2]), "=r"(r[3]) : "r"(addr));
}
__device__ __forceinline__ void mma_f16(float* c, const unsigned* a,
                                        unsigned b0, unsigned b1) {
    asm volatile(
        "mma.sync.aligned.m16n8k16.row.col.f32.f16.f16.f32 "
        "{%0,%1,%2,%3},{%4,%5,%6,%7},{%8,%9},{%0,%1,%2,%3};"
        : "+f"(c[0]), "+f"(c[1]), "+f"(c[2]), "+f"(c[3])
        : "r"(a[0]), "r"(a[1]), "r"(a[2]), "r"(a[3]), "r"(b0), "r"(b1));
}

// Inner MMA block: ah*bh (+ ah*bl when BLO). BLO is a constexpr in scope.
#define MMA_BLOCK(acc, ah, bh_cur, bl_cur)                                    \
    {                                                                         \
        _Pragma("unroll")                                                     \
        for (int half = 0; half < 2; half++)                                  \
            _Pragma("unroll")                                                 \
            for (int mi = 0; mi < 4; mi++)                                    \
                mma_f16(acc[mi][np * 2 + half], ah[mi],                       \
                        bh_cur[half * 2], bh_cur[half * 2 + 1]);              \
        if (BLO) {                                                            \
            _Pragma("unroll")                                                 \
            for (int half = 0; half < 2; half++)                              \
                _Pragma("unroll")                                             \
                for (int mi = 0; mi < 4; mi++)                                \
                    mma_f16(acc[mi][np * 2 + half], ah[mi],                   \
                            bl_cur[half * 2], bl_cur[half * 2 + 1]);          \
        }                                                                     \
    }

// Shared mainloop (256 threads load 128xBK A-hi + 256xBK B hi(+lo)) ---------
#define GEMM_MAINLOOP(NCv, CH0v)                                              \
    auto load_stage = [&](int s, int k0) {                                    \
        unsigned sb = cvta_s(smem + s * STAGE);                               \
        int rr = tid >> 2, cc = tid & 3;                                      \
        _Pragma("unroll")                                                     \
        for (int i = 0; i < 2; i++) {                                         \
            int r = rr + 64 * i;                                              \
            long long go = (long long)r * K + k0 + 8 * cc;                    \
            unsigned so = (unsigned)(r * 80 + cc * 16);                       \
            cpa16(sb + so, AtH + go);                                         \
        }                                                                     \
        _Pragma("unroll")                                                     \
        for (int i = 0; i < 4; i++) {                                         \
            int r = rr + 64 * i;                                              \
            long long go = (long long)r * K + k0 + 8 * cc;                    \
            unsigned so = (unsigned)(r * 80 + cc * 16);                       \
            cpa16(sb + ATILE + so, BtH + go);                                 \
            if (BLO) cpa16(sb + ATILE + BTILE + so, BtL + go);                \
        }                                                                     \
        asm volatile("cp.async.commit_group;");                               \
    };                                                                        \
    load_stage(0, (CH0v) * 32);                                               \
    if ((CH0v) + 1 < (NCv)) load_stage(1, ((CH0v) + 1) * 32);                 \
    else asm volatile("cp.async.commit_group;");                              \
    for (int ch = (CH0v); ch < (NCv); ch++) {                                 \
        const int s = (ch - (CH0v)) % NSTG;                                   \
        asm volatile("cp.async.wait_group 1;");                               \
        __syncthreads();                                                      \
        if (ch + 2 < (NCv))                                                   \
            load_stage((ch - (CH0v) + 2) % NSTG, (ch + 2) * 32);              \
        else                                                                  \
            asm volatile("cp.async.commit_group;");                           \
        const __half* As_hi = (const __half*)(smem + s * STAGE);              \
        const __half* Bs_hi = (const __half*)(smem + s * STAGE + ATILE);      \
        const __half* Bs_lo = (const __half*)(smem + s * STAGE + ATILE + BTILE);\
        const int g = lane >> 3;                                              \
        const int brow_base = n_off + ((g >> 1) << 3) + (lane & 7);           \
        _Pragma("unroll")                                                     \
        for (int ks = 0; ks < 2; ks++) {                                      \
            const int kel_b = ks * 16 + ((g & 1) << 3);                       \
            unsigned ah[4][4];                                                \
            _Pragma("unroll")                                                 \
            for (int mi = 0; mi < 4; mi++) {                                  \
                int rrow = m_off + mi * 16 + (lane & 15);                     \
                int kel  = ((lane >> 4) << 3) + ks * 16;                      \
                ldsm4(cvta_s(As_hi + rrow * SA + kel), ah[mi]);               \
            }                                                                 \
            unsigned bh[2][4], bl[2][4];                                      \
            ldsm4(cvta_s(Bs_hi + brow_base * SA + kel_b), bh[0]);             \
            if (BLO) ldsm4(cvta_s(Bs_lo + brow_base * SA + kel_b), bl[0]);    \
            _Pragma("unroll")                                                 \
            for (int np = 0; np < 4; np++) {                                  \
                const int cur = np & 1, nxt = cur ^ 1;                        \
                if (np < 3) {                                                 \
                    ldsm4(cvta_s(Bs_hi + (brow_base + (np + 1) * 16) * SA + kel_b), bh[nxt]);\
                    if (BLO) ldsm4(cvta_s(Bs_lo + (brow_base + (np + 1) * 16) * SA + kel_b), bl[nxt]);\
                }                                                             \
                MMA_BLOCK(acc, ah, bh[cur], bl[cur])                          \
            }                                                                 \
        }                                                                     \
    }

// ---------------------------------------------------------------------------
// HMMA GEMM, TN: C[M,N] = A[M,K] @ B[N,K]^T. 128x256 tile, 256 threads,
// warp tile 64x64. A fp16 (hi only), B fp16 hi (+lo when BLO=1).
// EPI:  0 = +bias, 1 = +bias(+opt null)+relu, 2 = scale + anti-causal mask
// OUTM: 0 = fp32 C, 1 = fp16 hi-only (Chi)
// TRIM: 1 = start K loop at row0 (A cols exactly zero for k < row0)
// BLO:  1 = 2-MMA split (B hi+lo), 0 = 1-MMA plain fp16 B
template<int EPI, int OUTM, int TRIM, int BLO>
__global__ __launch_bounds__(256, 1) void hmma_gemm(
    const __half* __restrict__ Ahi,
    const __half* __restrict__ Bhi, const __half* __restrict__ Blo,
    const float* __restrict__ bias, float* __restrict__ C,
    __half* __restrict__ Chi,
    int M, int N, int K,
    long long sA, long long sB, long long sC, float scale)
{
    extern __shared__ __align__(128) char smem[];

    const long long zC = (long long)blockIdx.z * sC;
    const int tid  = threadIdx.x;
    const int lane = tid & 31;
    const int wid  = tid >> 5;
    const int row0 = blockIdx.y * 128;
    const int col0 = blockIdx.x * 256;
    const int m_off = (wid & 1) * 64;
    const int n_off = (wid >> 1) * 64;

    if (EPI == 2 && col0 + 256 <= row0) {
        #pragma unroll
        for (int mi = 0; mi < 4; mi++) {
            #pragma unroll
            for (int ni = 0; ni < 8; ni++) {
                int r_base = row0 + m_off + mi * 16 + (lane >> 2);
                int c      = col0 + n_off + ni * 8 + 2 * (lane & 3);
                #pragma unroll
                for (int hh = 0; hh < 2; hh++) {
                    long long off = zC + (long long)(r_base + hh * 8) * N + c;
                    *(float2*)(C + off) = make_float2(NEG_INF, NEG_INF);
                }
            }
        }
        return;
    }

    const long long zA = (long long)blockIdx.z * sA;
    const long long zB = (long long)blockIdx.z * sB;
    const __half* AtH = Ahi + zA + (long long)row0 * K;
    const __half* BtH = Bhi + zB + (long long)col0 * K;
    const __half* BtL = Blo + zB + (long long)col0 * K;

    float acc[4][8][4];
    #pragma unroll
    for (int mi = 0; mi < 4; mi++)
        #pragma unroll
        for (int ni = 0; ni < 8; ni++)
            #pragma unroll
            for (int j = 0; j < 4; j++) acc[mi][ni][j] = 0.f;

    const int NC  = K / 32;
    const int ch0 = TRIM ? (row0 >> 5) : 0;

    GEMM_MAINLOOP(NC, ch0)

    const bool has_bias = (bias != nullptr);
    #pragma unroll
    for (int mi = 0; mi < 4; mi++) {
        #pragma unroll
        for (int ni = 0; ni < 8; ni++) {
            int r_base = row0 + m_off + mi * 16 + (lane >> 2);
            int c      = col0 + n_off + ni * 8 + 2 * (lane & 3);
            #pragma unroll
            for (int hh = 0; hh < 2; hh++) {
                int r = r_base + hh * 8;
                float v0 = acc[mi][ni][2 * hh];
                float v1 = acc[mi][ni][2 * hh + 1];
                if (EPI == 2) {
                    v0 *= scale; v1 *= scale;
                    if (c < r)     v0 = NEG_INF;
                    if (c + 1 < r) v1 = NEG_INF;
                } else {
                    if (has_bias) { v0 += bias[c]; v1 += bias[c + 1]; }
                    if (EPI == 1) { v0 = fmaxf(v0, 0.f); v1 = fmaxf(v1, 0.f); }
                }
                long long off = zC + (long long)r * N + c;
                if (OUTM == 0) {
                    *(float2*)(C + off) = make_float2(v0, v1);
                } else {
                    __half h2[2];
                    h2[0] = __float2half_rn(v0);
                    h2[1] = __float2half_rn(v1);
                    *(unsigned*)(Chi + off) = *(unsigned*)h2;
                }
            }
        }
    }
}

// ---------------------------------------------------------------------------
// Fused QKV GEMM: cols [0,1024)->q fp16-hi, [1024,2048)->k fp16 hi+lo,
// [2048,3072)->v fp32.
__global__ __launch_bounds__(256, 1) void hmma_qkv(
    const __half* __restrict__ Ahi,
    const __half* __restrict__ Bhi, const __half* __restrict__ Blo,
    const float* __restrict__ bq, const float* __restrict__ bk,
    const float* __restrict__ bv,
    __half* __restrict__ qH,
    __half* __restrict__ kH, __half* __restrict__ kL,
    float* __restrict__ vO)
{
    extern __shared__ __align__(128) char smem[];
    const int K = DD;
    constexpr int BLO = 1;

    const int tid  = threadIdx.x;
    const int lane = tid & 31;
    const int wid  = tid >> 5;
    const int row0 = blockIdx.y * 128;
    const int col0 = blockIdx.x * 256;
    const int m_off = (wid & 1) * 64;
    const int n_off = (wid >> 1) * 64;

    const int sel = col0 >> 10;
    const int lc0 = col0 & 1023;

    const __half* AtH = Ahi + (long long)row0 * K;
    const __half* BtH = Bhi + (long long)col0 * K;
    const __half* BtL = Blo + (long long)col0 * K;

    float acc[4][8][4];
    #pragma unroll
    for (int mi = 0; mi < 4; mi++)
        #pragma unroll
        for (int ni = 0; ni < 8; ni++)
            #pragma unroll
            for (int j = 0; j < 4; j++) acc[mi][ni][j] = 0.f;

    const int NC = K / 32;
    GEMM_MAINLOOP(NC, 0)

    const float* bias = (sel == 0) ? bq : (sel == 1) ? bk : bv;

    #pragma unroll
    for (int mi = 0; mi < 4; mi++) {
        #pragma unroll
        for (int ni = 0; ni < 8; ni++) {
            int r_base = row0 + m_off + mi * 16 + (lane >> 2);
            int lc     = lc0 + n_off + ni * 8 + 2 * (lane & 3);
            #pragma unroll
            for (int hh = 0; hh < 2; hh++) {
                int r = r_base + hh * 8;
                float v0 = acc[mi][ni][2 * hh] + bias[lc];
                float v1 = acc[mi][ni][2 * hh + 1] + bias[lc + 1];
                long long off = (long long)r * DD + lc;
                if (sel == 2) {
                    *(float2*)(vO + off) = make_float2(v0, v1);
                } else if (sel == 0) {
                    __half h2[2];
                    h2[0] = __float2half_rn(v0);
                    h2[1] = __float2half_rn(v1);
                    *(unsigned*)(qH + off) = *(unsigned*)h2;
                } else {
                    __half h2[2], l2[2];
                    h2[0] = __float2half_rn(v0);
                    h2[1] = __float2half_rn(v1);
                    l2[0] = __float2half_rn(v0 - __half2float(h2[0]));
                    l2[1] = __float2half_rn(v1 - __half2float(h2[1]));
                    *(unsigned*)(kH + off) = *(unsigned*)h2;
                    *(unsigned*)(kL + off) = *(unsigned*)l2;
                }
            }
        }
    }
}

// ---------------------------------------------------------------------------
__global__ __launch_bounds__(256) void softmax_kernel(
    const float* __restrict__ sc, __half* __restrict__ oH)
{
    const float* p = sc + (long long)blockIdx.x * SS;
    __half* pH = oH + (long long)blockIdx.x * SS;
    const int t = threadIdx.x;
    const int lane = t & 31, warp = t >> 5;
    __shared__ float red[8];

    float v[8];
    float m = NEG_INF;
    #pragma unroll
    for (int i = 0; i < 8; i++) { v[i] = p[t + 256 * i]; m = fmaxf(m, v[i]); }
    #pragma unroll
    for (int o = 16; o > 0; o >>= 1) m = fmaxf(m, __shfl_xor_sync(0xffffffffu, m, o));
    if (lane == 0) red[warp] = m;
    __syncthreads();
    float mb = red[0];
    #pragma unroll
    for (int w = 1; w < 8; w++) mb = fmaxf(mb, red[w]);

    float s = 0.f;
    #pragma unroll
    for (int i = 0; i < 8; i++) { v[i] = __expf(v[i] - mb); s += v[i]; }
    #pragma unroll
    for (int o = 16; o > 0; o >>= 1) s += __shfl_xor_sync(0xffffffffu, s, o);
    __syncthreads();
    if (lane == 0) red[warp] = s;
    __syncthreads();
    float sb = 0.f;
    #pragma unroll
    for (int w = 0; w < 8; w++) sb += red[w];

    float inv = 1.f / sb;
    #pragma unroll
    for (int i = 0; i < 8; i++)
        pH[t + 256 * i] = __float2half_rn(v[i] * inv);
}

// ---------------------------------------------------------------------------
extern "C" void kernel_launch(void* const* d_in, const int* in_sizes, int n_in,
                              void* d_out, int out_size)
{
    const void*  x    = d_in[0];
    const float* emb  = (const float*)d_in[1];
    const float* pos  = (const float*)d_in[2];
    const float* wq   = (const float*)d_in[3];
    const float* bq   = (const float*)d_in[4];
    const float* wk   = (const float*)d_in[5];
    const float* bk   = (const float*)d_in[6];
    const float* wv   = (const float*)d_in[7];
    const float* bv   = (const float*)d_in[8];
    const float* w1s  = (const float*)d_in[9];
    const float* b1s  = (const float*)d_in[10];
    const float* w2s  = (const float*)d_in[11];
    const float* b2s  = (const float*)d_in[12];
    float* out = (float*)d_out;

    cudaFuncSetAttribute(hmma_qkv,           cudaFuncAttributeMaxDynamicSharedMemorySize, SMEM_DYN);
    cudaFuncSetAttribute(hmma_gemm<2,0,0,1>, cudaFuncAttributeMaxDynamicSharedMemorySize, SMEM_DYN);
    cudaFuncSetAttribute(hmma_gemm<1,1,1,1>, cudaFuncAttributeMaxDynamicSharedMemorySize, SMEM_DYN);
    cudaFuncSetAttribute(hmma_gemm<1,1,0,0>, cudaFuncAttributeMaxDynamicSharedMemorySize, SMEM_DYN);
    cudaFuncSetAttribute(hmma_gemm<1,1,0,1>, cudaFuncAttributeMaxDynamicSharedMemorySize, SMEM_DYN);
    cudaFuncSetAttribute(hmma_gemm<1,0,0,1>, cudaFuncAttributeMaxDynamicSharedMemorySize, SMEM_DYN);

    #define SYM(T, n) T* n; { void* p_; cudaGetSymbolAddress(&p_, g_##n); n = (T*)p_; }
    SYM(__half, hH)
    SYM(__half, qH)
    SYM(__half, kH)   SYM(__half, kL)
    SYM(__half, vTH)  SYM(__half, vTL)
    SYM(__half, scH)
    SYM(__half, midH)
    SYM(__half, wqkvH) SYM(__half, wqkvL)
    SYM(__half, w1H)
    SYM(__half, w2H)  SYM(__half, w2L)
    SYM(float, v)  SYM(float, sc)
    #undef SYM

    dim3 tb(32, 8);
    detect_kernel<<<1, 256>>>(x);
    embed_kernel<<<ROWS, 256>>>(x, emb, pos, hH);
    qkvw_transcvt_kernel<<<dim3(32, 32, 3), tb>>>(wq, wk, wv, wqkvH, wqkvL);
    // w1: hi only (FFN1 runs 1-MMA)
    transcvt_kernel<<<dim3(128, 32, LL), tb>>>(w1s, w1H, w1H, DD, MM,
        (long long)DD * MM, (long long)DD * MM, 0);
    transcvt_kernel<<<dim3(32, 128, LL), tb>>>(w2s, w2H, w2L, MM, DD,
        (long long)MM * DD, (long long)MM * DD, 1);

    // Fused QKV: grid (12,64) = 768 CTAs
    hmma_qkv<<<dim3(12, 64, 1), 256, SMEM_DYN>>>(hH, wqkvH, wqkvL,
        bq, bk, bv, qH, kH, kL, v);

    // scores = q @ k^T / 32, anti-causal mask; fully-masked tiles early-exit
    hmma_gemm<2,0,0,1><<<dim3(8, 16, BB), 256, SMEM_DYN>>>(qH, kH, kL, nullptr,
        sc, nullptr, SS, SS, DD,
        (long long)SS * DD, (long long)SS * DD, (long long)SS * SS, 0.03125f);

    transcvt_kernel<<<dim3(32, 64, BB), tb>>>(v, vTH, vTL, SS, DD,
        (long long)SS * DD, (long long)DD * SS, 1);

    softmax_kernel<<<ROWS, 256>>>(sc, scH);

    // h = relu(attn @ v): attn rows exactly 0 for k < row0 -> TRIM=1
    hmma_gemm<1,1,1,1><<<dim3(4, 16, BB), 256, SMEM_DYN>>>(scH, vTH, vTL, nullptr,
        nullptr, hH, SS, DD, SS,
        (long long)SS * SS, (long long)DD * SS, (long long)SS * DD, 0.f);

    // FFN stack: FFN1 = 1-MMA (BLO=0), FFN2 = 2-MMA (BLO=1)
    for (int l = 0; l < LL; l++) {
        hmma_gemm<1,1,0,0><<<dim3(16, 64, 1), 256, SMEM_DYN>>>(
            hH, w1H + (long long)l * DD * MM, w1H + (long long)l * DD * MM,
            b1s + (long long)l * MM, nullptr, midH,
            ROWS, MM, DD, 0, 0, 0, 0.f);
        if (l == LL - 1) {
            hmma_gemm<1,0,0,1><<<dim3(4, 64, 1), 256, SMEM_DYN>>>(
                midH, w2H + (long long)l * MM * DD, w2L + (long long)l * MM * DD,
                b2s + (long long)l * DD, out, nullptr,
                ROWS, DD, MM, 0, 0, 0, 0.f);
        } else {
            hmma_gemm<1,1,0,1><<<dim3(4, 64, 1), 256, SMEM_DYN>>>(
                midH, w2H + (long long)l * MM * DD, w2L + (long long)l * MM * DD,
                b2s + (long long)l * DD, nullptr, hH,
                ROWS, DD, MM, 0, 0, 0, 0.f);
        }
    }
}

// round 12
// speedup vs baseline: 5.2685x; 1.1469x over previous
#include <cuda_runtime.h>
#include <cuda_fp16.h>
#include <cstdint>

// Problem constants
#define BB 4
#define SS 2048
#define DD 1024
#define MM 4096
#define LL 4
#define ROWS (BB*SS)          // 8192
#define NEG_INF __int_as_float(0xff800000)

// GEMM tiling: 128x256 block tile, BK=64, 256 threads (8 warps 2x4, warp 64x64)
// fp16 split: A hi-only, B hi(+optional lo, template BLO).
#define SA 72                 // smem row stride (fp16) = 144B, conflict-free
#define ATILE 18432           // 128*SA*2
#define BTILE 36864           // 256*SA*2
#define STAGE (ATILE + 2*BTILE)     // 92160
#define NSTG 2
#define SMEM_DYN (NSTG*STAGE)       // 184320

// ---------------- scratch (device globals; no allocation allowed) ----------
__device__ __half g_hH[ROWS*DD];
__device__ __half g_qH[ROWS*DD];
__device__ __half g_kH[ROWS*DD],  g_kL[ROWS*DD];
__device__ __half g_vTH[ROWS*DD], g_vTL[ROWS*DD];
__device__ __half g_scH[BB*SS*SS];
__device__ __half g_midH[(long long)ROWS*MM];
__device__ __half g_wqkvH[3*DD*DD], g_wqkvL[3*DD*DD];
__device__ __half g_w1H[LL*DD*MM];                 // FFN1 weights: hi only (1-MMA)
__device__ __half g_w2H[LL*DD*MM], g_w2L[LL*DD*MM];
__device__ float g_v[ROWS*DD];
__device__ float g_sc[BB*SS*SS];
__device__ int   g_is32;

// ---------------------------------------------------------------------------
__global__ void detect_kernel(const void* __restrict__ x) {
    const long long* p = (const long long*)x;
    int bad = 0;
    for (int i = threadIdx.x; i < 4096; i += 256) {
        long long v = p[i];
        if (v < 0 || v >= 32000) bad = 1;
    }
    bad = __syncthreads_or(bad);
    if (threadIdx.x == 0) g_is32 = bad;
}

// h = emb[x] + pos -> fp16 (hi only; h is always an A operand)
__global__ __launch_bounds__(256) void embed_kernel(
    const void* __restrict__ x, const float* __restrict__ emb,
    const float* __restrict__ pos, __half* __restrict__ hH)
{
    int row = blockIdx.x;
    int s = row & (SS - 1);
    long long tok;
    if (g_is32) tok = ((const int*)x)[row];
    else        tok = ((const long long*)x)[row];
    int t = threadIdx.x;
    float4 a = ((const float4*)(emb + tok * (long long)DD))[t];
    float4 b = ((const float4*)(pos + (long long)s * DD))[t];
    __half h4[4];
    h4[0] = __float2half_rn(a.x + b.x);
    h4[1] = __float2half_rn(a.y + b.y);
    h4[2] = __float2half_rn(a.z + b.z);
    h4[3] = __float2half_rn(a.w + b.w);
    *(uint2*)(hH + (long long)row * DD + 4 * t) = *(uint2*)h4;
}

// ---------------------------------------------------------------------------
// Transpose + split: fp32 [R,C] row-major -> fp16 hi (+lo if wlo) [C,R].
__global__ __launch_bounds__(256) void transcvt_kernel(
    const float* __restrict__ in,
    __half* __restrict__ oH, __half* __restrict__ oL,
    int R, int C, long long si, long long so, int wlo)
{
    __shared__ float t[32][33];
    in += (long long)blockIdx.z * si;
    oH += (long long)blockIdx.z * so;
    oL += (long long)blockIdx.z * so;
    int x  = blockIdx.x * 32 + threadIdx.x;
    int y0 = blockIdx.y * 32 + threadIdx.y;
    #pragma unroll
    for (int j = 0; j < 32; j += 8)
        t[threadIdx.y + j][threadIdx.x] = in[(long long)(y0 + j) * C + x];
    __syncthreads();
    int x2 = blockIdx.y * 32 + threadIdx.x;
    int y2 = blockIdx.x * 32 + threadIdx.y;
    #pragma unroll
    for (int j = 0; j < 32; j += 8) {
        float v = t[threadIdx.x][threadIdx.y + j];
        __half h = __float2half_rn(v);
        oH[(long long)(y2 + j) * R + x2] = h;
        if (wlo) {
            __half l = __float2half_rn(v - __half2float(h));
            oL[(long long)(y2 + j) * R + x2] = l;
        }
    }
}

// QKV weight transpose+split in ONE launch (z selects wq/wk/wv).
__global__ __launch_bounds__(256) void qkvw_transcvt_kernel(
    const float* __restrict__ wq, const float* __restrict__ wk,
    const float* __restrict__ wv,
    __half* __restrict__ oH, __half* __restrict__ oL)
{
    __shared__ float t[32][33];
    const float* in = (blockIdx.z == 0) ? wq : (blockIdx.z == 1) ? wk : wv;
    oH += (long long)blockIdx.z * DD * DD;
    oL += (long long)blockIdx.z * DD * DD;
    int x  = blockIdx.x * 32 + threadIdx.x;
    int y0 = blockIdx.y * 32 + threadIdx.y;
    #pragma unroll
    for (int j = 0; j < 32; j += 8)
        t[threadIdx.y + j][threadIdx.x] = in[(long long)(y0 + j) * DD + x];
    __syncthreads();
    int x2 = blockIdx.y * 32 + threadIdx.x;
    int y2 = blockIdx.x * 32 + threadIdx.y;
    #pragma unroll
    for (int j = 0; j < 32; j += 8) {
        float v = t[threadIdx.x][threadIdx.y + j];
        __half h = __float2half_rn(v);
        __half l = __float2half_rn(v - __half2float(h));
        oH[(long long)(y2 + j) * DD + x2] = h;
        oL[(long long)(y2 + j) * DD + x2] = l;
    }
}

// ---------------------------------------------------------------------------
__device__ __forceinline__ unsigned cvta_s(const void* p) {
    return (unsigned)__cvta_generic_to_shared(p);
}
__device__ __forceinline__ void cpa16(unsigned s, const void* g) {
    asm volatile("cp.async.cg.shared.global [%0], [%1], 16;" :: "r"(s), "l"(g));
}
__device__ __forceinline__ void ldsm4(unsigned addr, unsigned* r) {
    asm volatile("ldmatrix.sync.aligned.m8n8.x4.shared.b16 {%0,%1,%2,%3},[%4];"
                 : "=r"(r[0]), "=r"(r[1]), "=r"(r[2]), "=r"(r[3]) : "r"(addr));
}
__device__ __forceinline__ void mma_f16(float* c, const unsigned* a,
                                        unsigned b0, unsigned b1) {
    asm volatile(
        "mma.sync.aligned.m16n8k16.row.col.f32.f16.f16.f32 "
        "{%0,%1,%2,%3},{%4,%5,%6,%7},{%8,%9},{%0,%1,%2,%3};"
        : "+f"(c[0]), "+f"(c[1]), "+f"(c[2]), "+f"(c[3])
        : "r"(a[0]), "r"(a[1]), "r"(a[2]), "r"(a[3]), "r"(b0), "r"(b1));
}

// Inner MMA block: ah*bh (+ ah*bl when BLO). BLO is a constexpr in scope.
#define MMA_BLOCK(acc, ah, bh_cur, bl_cur)                                    \
    {                                                                         \
        _Pragma("unroll")                                                     \
        for (int half = 0; half < 2; half++)                                  \
            _Pragma("unroll")                                                 \
            for (int mi = 0; mi < 4; mi++)                                    \
                mma_f16(acc[mi][np * 2 + half], ah[mi],                       \
                        bh_cur[half * 2], bh_cur[half * 2 + 1]);              \
        if (BLO) {                                                            \
            _Pragma("unroll")                                                 \
            for (int half = 0; half < 2; half++)                              \
                _Pragma("unroll")                                             \
                for (int mi = 0; mi < 4; mi++)                                \
                    mma_f16(acc[mi][np * 2 + half], ah[mi],                   \
                            bl_cur[half * 2], bl_cur[half * 2 + 1]);          \
        }                                                                     \
    }

// Shared mainloop, BK=64, 2-stage single-sync pipeline:
//   wait(ch) -> sync -> issue load(ch+1) -> compute(ch)
#define GEMM_MAINLOOP(NCv, CH0v)                                              \
    auto load_stage = [&](int s, int k0) {                                    \
        unsigned sb = cvta_s(smem + s * STAGE);                               \
        int rr = tid >> 3, cc = tid & 7;                                      \
        _Pragma("unroll")                                                     \
        for (int i = 0; i < 4; i++) {                                         \
            int r = rr + 32 * i;                                              \
            long long go = (long long)r * K + k0 + 8 * cc;                    \
            unsigned so = (unsigned)(r * 144 + cc * 16);                      \
            cpa16(sb + so, AtH + go);                                         \
        }                                                                     \
        _Pragma("unroll")                                                     \
        for (int i = 0; i < 8; i++) {                                         \
            int r = rr + 32 * i;                                              \
            long long go = (long long)r * K + k0 + 8 * cc;                    \
            unsigned so = (unsigned)(r * 144 + cc * 16);                      \
            cpa16(sb + ATILE + so, BtH + go);                                 \
            if (BLO) cpa16(sb + ATILE + BTILE + so, BtL + go);                \
        }                                                                     \
        asm volatile("cp.async.commit_group;");                               \
    };                                                                        \
    load_stage(0, (CH0v) * 64);                                               \
    for (int ch = (CH0v); ch < (NCv); ch++) {                                 \
        const int s = (ch - (CH0v)) & 1;                                      \
        asm volatile("cp.async.wait_group 0;");                               \
        __syncthreads();                                                      \
        if (ch + 1 < (NCv)) load_stage(s ^ 1, (ch + 1) * 64);                 \
        const __half* As_hi = (const __half*)(smem + s * STAGE);              \
        const __half* Bs_hi = (const __half*)(smem + s * STAGE + ATILE);      \
        const __half* Bs_lo = (const __half*)(smem + s * STAGE + ATILE + BTILE);\
        const int g = lane >> 3;                                              \
        const int brow_base = n_off + ((g >> 1) << 3) + (lane & 7);           \
        _Pragma("unroll")                                                     \
        for (int ks = 0; ks < 4; ks++) {                                      \
            const int kel_b = ks * 16 + ((g & 1) << 3);                       \
            unsigned ah[4][4];                                                \
            _Pragma("unroll")                                                 \
            for (int mi = 0; mi < 4; mi++) {                                  \
                int rrow = m_off + mi * 16 + (lane & 15);                     \
                int kel  = ((lane >> 4) << 3) + ks * 16;                      \
                ldsm4(cvta_s(As_hi + rrow * SA + kel), ah[mi]);               \
            }                                                                 \
            unsigned bh[2][4], bl[2][4];                                      \
            ldsm4(cvta_s(Bs_hi + brow_base * SA + kel_b), bh[0]);             \
            if (BLO) ldsm4(cvta_s(Bs_lo + brow_base * SA + kel_b), bl[0]);    \
            _Pragma("unroll")                                                 \
            for (int np = 0; np < 4; np++) {                                  \
                const int cur = np & 1, nxt = cur ^ 1;                        \
                if (np < 3) {                                                 \
                    ldsm4(cvta_s(Bs_hi + (brow_base + (np + 1) * 16) * SA + kel_b), bh[nxt]);\
                    if (BLO) ldsm4(cvta_s(Bs_lo + (brow_base + (np + 1) * 16) * SA + kel_b), bl[nxt]);\
                }                                                             \
                MMA_BLOCK(acc, ah, bh[cur], bl[cur])                          \
            }                                                                 \
        }                                                                     \
    }

// ---------------------------------------------------------------------------
// HMMA GEMM, TN: C[M,N] = A[M,K] @ B[N,K]^T. 128x256 tile, 256 threads,
// warp tile 64x64. A fp16 (hi only), B fp16 hi (+lo when BLO=1).
// EPI:  0 = +bias, 1 = +bias(+opt null)+relu, 2 = scale + anti-causal mask
// OUTM: 0 = fp32 C, 1 = fp16 hi-only (Chi)
// TRIM: 1 = start K loop at row0 (A cols exactly zero for k < row0)
// BLO:  1 = 2-MMA split (B hi+lo), 0 = 1-MMA plain fp16 B
template<int EPI, int OUTM, int TRIM, int BLO>
__global__ __launch_bounds__(256, 1) void hmma_gemm(
    const __half* __restrict__ Ahi,
    const __half* __restrict__ Bhi, const __half* __restrict__ Blo,
    const float* __restrict__ bias, float* __restrict__ C,
    __half* __restrict__ Chi,
    int M, int N, int K,
    long long sA, long long sB, long long sC, float scale)
{
    extern __shared__ __align__(128) char smem[];

    const long long zC = (long long)blockIdx.z * sC;
    const int tid  = threadIdx.x;
    const int lane = tid & 31;
    const int wid  = tid >> 5;
    const int row0 = blockIdx.y * 128;
    const int col0 = blockIdx.x * 256;
    const int m_off = (wid & 1) * 64;
    const int n_off = (wid >> 1) * 64;

    if (EPI == 2 && col0 + 256 <= row0) {
        #pragma unroll
        for (int mi = 0; mi < 4; mi++) {
            #pragma unroll
            for (int ni = 0; ni < 8; ni++) {
                int r_base = row0 + m_off + mi * 16 + (lane >> 2);
                int c      = col0 + n_off + ni * 8 + 2 * (lane & 3);
                #pragma unroll
                for (int hh = 0; hh < 2; hh++) {
                    long long off = zC + (long long)(r_base + hh * 8) * N + c;
                    *(float2*)(C + off) = make_float2(NEG_INF, NEG_INF);
                }
            }
        }
        return;
    }

    const long long zA = (long long)blockIdx.z * sA;
    const long long zB = (long long)blockIdx.z * sB;
    const __half* AtH = Ahi + zA + (long long)row0 * K;
    const __half* BtH = Bhi + zB + (long long)col0 * K;
    const __half* BtL = Blo + zB + (long long)col0 * K;

    float acc[4][8][4];
    #pragma unroll
    for (int mi = 0; mi < 4; mi++)
        #pragma unroll
        for (int ni = 0; ni < 8; ni++)
            #pragma unroll
            for (int j = 0; j < 4; j++) acc[mi][ni][j] = 0.f;

    const int NC  = K / 64;
    const int ch0 = TRIM ? (row0 >> 6) : 0;

    GEMM_MAINLOOP(NC, ch0)

    const bool has_bias = (bias != nullptr);
    #pragma unroll
    for (int mi = 0; mi < 4; mi++) {
        #pragma unroll
        for (int ni = 0; ni < 8; ni++) {
            int r_base = row0 + m_off + mi * 16 + (lane >> 2);
            int c      = col0 + n_off + ni * 8 + 2 * (lane & 3);
            #pragma unroll
            for (int hh = 0; hh < 2; hh++) {
                int r = r_base + hh * 8;
                float v0 = acc[mi][ni][2 * hh];
                float v1 = acc[mi][ni][2 * hh + 1];
                if (EPI == 2) {
                    v0 *= scale; v1 *= scale;
                    if (c < r)     v0 = NEG_INF;
                    if (c + 1 < r) v1 = NEG_INF;
                } else {
                    if (has_bias) { v0 += bias[c]; v1 += bias[c + 1]; }
                    if (EPI == 1) { v0 = fmaxf(v0, 0.f); v1 = fmaxf(v1, 0.f); }
                }
                long long off = zC + (long long)r * N + c;
                if (OUTM == 0) {
                    *(float2*)(C + off) = make_float2(v0, v1);
                } else {
                    __half h2[2];
                    h2[0] = __float2half_rn(v0);
                    h2[1] = __float2half_rn(v1);
                    *(unsigned*)(Chi + off) = *(unsigned*)h2;
                }
            }
        }
    }
}

// ---------------------------------------------------------------------------
// Fused QKV GEMM: cols [0,1024)->q fp16-hi, [1024,2048)->k fp16 hi+lo,
// [2048,3072)->v fp32.
__global__ __launch_bounds__(256, 1) void hmma_qkv(
    const __half* __restrict__ Ahi,
    const __half* __restrict__ Bhi, const __half* __restrict__ Blo,
    const float* __restrict__ bq, const float* __restrict__ bk,
    const float* __restrict__ bv,
    __half* __restrict__ qH,
    __half* __restrict__ kH, __half* __restrict__ kL,
    float* __restrict__ vO)
{
    extern __shared__ __align__(128) char smem[];
    const int K = DD;
    constexpr int BLO = 1;

    const int tid  = threadIdx.x;
    const int lane = tid & 31;
    const int wid  = tid >> 5;
    const int row0 = blockIdx.y * 128;
    const int col0 = blockIdx.x * 256;
    const int m_off = (wid & 1) * 64;
    const int n_off = (wid >> 1) * 64;

    const int sel = col0 >> 10;
    const int lc0 = col0 & 1023;

    const __half* AtH = Ahi + (long long)row0 * K;
    const __half* BtH = Bhi + (long long)col0 * K;
    const __half* BtL = Blo + (long long)col0 * K;

    float acc[4][8][4];
    #pragma unroll
    for (int mi = 0; mi < 4; mi++)
        #pragma unroll
        for (int ni = 0; ni < 8; ni++)
            #pragma unroll
            for (int j = 0; j < 4; j++) acc[mi][ni][j] = 0.f;

    const int NC = K / 64;
    GEMM_MAINLOOP(NC, 0)

    const float* bias = (sel == 0) ? bq : (sel == 1) ? bk : bv;

    #pragma unroll
    for (int mi = 0; mi < 4; mi++) {
        #pragma unroll
        for (int ni = 0; ni < 8; ni++) {
            int r_base = row0 + m_off + mi * 16 + (lane >> 2);
            int lc     = lc0 + n_off + ni * 8 + 2 * (lane & 3);
            #pragma unroll
            for (int hh = 0; hh < 2; hh++) {
                int r = r_base + hh * 8;
                float v0 = acc[mi][ni][2 * hh] + bias[lc];
                float v1 = acc[mi][ni][2 * hh + 1] + bias[lc + 1];
                long long off = (long long)r * DD + lc;
                if (sel == 2) {
                    *(float2*)(vO + off) = make_float2(v0, v1);
                } else if (sel == 0) {
                    __half h2[2];
                    h2[0] = __float2half_rn(v0);
                    h2[1] = __float2half_rn(v1);
                    *(unsigned*)(qH + off) = *(unsigned*)h2;
                } else {
                    __half h2[2], l2[2];
                    h2[0] = __float2half_rn(v0);
                    h2[1] = __float2half_rn(v1);
                    l2[0] = __float2half_rn(v0 - __half2float(h2[0]));
                    l2[1] = __float2half_rn(v1 - __half2float(h2[1]));
                    *(unsigned*)(kH + off) = *(unsigned*)h2;
                    *(unsigned*)(kL + off) = *(unsigned*)l2;
                }
            }
        }
    }
}

// ---------------------------------------------------------------------------
__global__ __launch_bounds__(256) void softmax_kernel(
    const float* __restrict__ sc, __half* __restrict__ oH)
{
    const float* p = sc + (long long)blockIdx.x * SS;
    __half* pH = oH + (long long)blockIdx.x * SS;
    const int t = threadIdx.x;
    const int lane = t & 31, warp = t >> 5;
    __shared__ float red[8];

    float v[8];
    float m = NEG_INF;
    #pragma unroll
    for (int i = 0; i < 8; i++) { v[i] = p[t + 256 * i]; m = fmaxf(m, v[i]); }
    #pragma unroll
    for (int o = 16; o > 0; o >>= 1) m = fmaxf(m, __shfl_xor_sync(0xffffffffu, m, o));
    if (lane == 0) red[warp] = m;
    __syncthreads();
    float mb = red[0];
    #pragma unroll
    for (int w = 1; w < 8; w++) mb = fmaxf(mb, red[w]);

    float s = 0.f;
    #pragma unroll
    for (int i = 0; i < 8; i++) { v[i] = __expf(v[i] - mb); s += v[i]; }
    #pragma unroll
    for (int o = 16; o > 0; o >>= 1) s += __shfl_xor_sync(0xffffffffu, s, o);
    __syncthreads();
    if (lane == 0) red[warp] = s;
    __syncthreads();
    float sb = 0.f;
    #pragma unroll
    for (int w = 0; w < 8; w++) sb += red[w];

    float inv = 1.f / sb;
    #pragma unroll
    for (int i = 0; i < 8; i++)
        pH[t + 256 * i] = __float2half_rn(v[i] * inv);
}

// ---------------------------------------------------------------------------
extern "C" void kernel_launch(void* const* d_in, const int* in_sizes, int n_in,
                              void* d_out, int out_size)
{
    const void*  x    = d_in[0];
    const float* emb  = (const float*)d_in[1];
    const float* pos  = (const float*)d_in[2];
    const float* wq   = (const float*)d_in[3];
    const float* bq   = (const float*)d_in[4];
    const float* wk   = (const float*)d_in[5];
    const float* bk   = (const float*)d_in[6];
    const float* wv   = (const float*)d_in[7];
    const float* bv   = (const float*)d_in[8];
    const float* w1s  = (const float*)d_in[9];
    const float* b1s  = (const float*)d_in[10];
    const float* w2s  = (const float*)d_in[11];
    const float* b2s  = (const float*)d_in[12];
    float* out = (float*)d_out;

    cudaFuncSetAttribute(hmma_qkv,           cudaFuncAttributeMaxDynamicSharedMemorySize, SMEM_DYN);
    cudaFuncSetAttribute(hmma_gemm<2,0,0,1>, cudaFuncAttributeMaxDynamicSharedMemorySize, SMEM_DYN);
    cudaFuncSetAttribute(hmma_gemm<1,1,1,1>, cudaFuncAttributeMaxDynamicSharedMemorySize, SMEM_DYN);
    cudaFuncSetAttribute(hmma_gemm<1,1,0,0>, cudaFuncAttributeMaxDynamicSharedMemorySize, SMEM_DYN);
    cudaFuncSetAttribute(hmma_gemm<1,1,0,1>, cudaFuncAttributeMaxDynamicSharedMemorySize, SMEM_DYN);
    cudaFuncSetAttribute(hmma_gemm<1,0,0,1>, cudaFuncAttributeMaxDynamicSharedMemorySize, SMEM_DYN);

    #define SYM(T, n) T* n; { void* p_; cudaGetSymbolAddress(&p_, g_##n); n = (T*)p_; }
    SYM(__half, hH)
    SYM(__half, qH)
    SYM(__half, kH)   SYM(__half, kL)
    SYM(__half, vTH)  SYM(__half, vTL)
    SYM(__half, scH)
    SYM(__half, midH)
    SYM(__half, wqkvH) SYM(__half, wqkvL)
    SYM(__half, w1H)
    SYM(__half, w2H)  SYM(__half, w2L)
    SYM(float, v)  SYM(float, sc)
    #undef SYM

    dim3 tb(32, 8);
    detect_kernel<<<1, 256>>>(x);
    embed_kernel<<<ROWS, 256>>>(x, emb, pos, hH);
    qkvw_transcvt_kernel<<<dim3(32, 32, 3), tb>>>(wq, wk, wv, wqkvH, wqkvL);
    // w1: hi only (FFN1 runs 1-MMA)
    transcvt_kernel<<<dim3(128, 32, LL), tb>>>(w1s, w1H, w1H, DD, MM,
        (long long)DD * MM, (long long)DD * MM, 0);
    transcvt_kernel<<<dim3(32, 128, LL), tb>>>(w2s, w2H, w2L, MM, DD,
        (long long)MM * DD, (long long)MM * DD, 1);

    // Fused QKV: grid (12,64) = 768 CTAs
    hmma_qkv<<<dim3(12, 64, 1), 256, SMEM_DYN>>>(hH, wqkvH, wqkvL,
        bq, bk, bv, qH, kH, kL, v);

    // scores = q @ k^T / 32, anti-causal mask; fully-masked tiles early-exit
    hmma_gemm<2,0,0,1><<<dim3(8, 16, BB), 256, SMEM_DYN>>>(qH, kH, kL, nullptr,
        sc, nullptr, SS, SS, DD,
        (long long)SS * DD, (long long)SS * DD, (long long)SS * SS, 0.03125f);

    transcvt_kernel<<<dim3(32, 64, BB), tb>>>(v, vTH, vTL, SS, DD,
        (long long)SS * DD, (long long)DD * SS, 1);

    softmax_kernel<<<ROWS, 256>>>(sc, scH);

    // h = relu(attn @ v): attn rows exactly 0 for k < row0 -> TRIM=1
    hmma_gemm<1,1,1,1><<<dim3(4, 16, BB), 256, SMEM_DYN>>>(scH, vTH, vTL, nullptr,
        nullptr, hH, SS, DD, SS,
        (long long)SS * SS, (long long)DD * SS, (long long)SS * DD, 0.f);

    // FFN stack: FFN1 = 1-MMA (BLO=0), FFN2 = 2-MMA (BLO=1)
    for (int l = 0; l < LL; l++) {
        hmma_gemm<1,1,0,0><<<dim3(16, 64, 1), 256, SMEM_DYN>>>(
            hH, w1H + (long long)l * DD * MM, w1H + (long long)l * DD * MM,
            b1s + (long long)l * MM, nullptr, midH,
            ROWS, MM, DD, 0, 0, 0, 0.f);
        if (l == LL - 1) {
            hmma_gemm<1,0,0,1><<<dim3(4, 64, 1), 256, SMEM_DYN>>>(
                midH, w2H + (long long)l * MM * DD, w2L + (long long)l * MM * DD,
                b2s + (long long)l * DD, out, nullptr,
                ROWS, DD, MM, 0, 0, 0, 0.f);
        } else {
            hmma_gemm<1,1,0,1><<<dim3(4, 64, 1), 256, SMEM_DYN>>>(
                midH, w2H + (long long)l * MM * DD, w2L + (long long)l * MM * DD,
                b2s + (long long)l * DD, nullptr, hH,
                ROWS, DD, MM, 0, 0, 0, 0.f);
        }
    }
}